// round 1
// baseline (speedup 1.0000x reference)
#include <cuda_runtime.h>
#include <cuda_bf16.h>
#include <math.h>

// ---------------------------------------------------------------------------
// Problem constants
// ---------------------------------------------------------------------------
#define B_   2
#define S_   2048
#define CTX_ 256
#define D_   1024
#define H_   16
#define DH_  64
#define INNER_ 1024
#define DFF_ 4096

// ---------------------------------------------------------------------------
// Scratch (static device globals: no allocation allowed)
// ---------------------------------------------------------------------------
__device__ float g_x   [B_*S_*D_];        // residual stream
__device__ float g_h   [B_*S_*D_];        // normed activations
__device__ float g_q   [B_*S_*INNER_];
__device__ float g_k   [B_*S_*INNER_];
__device__ float g_v   [B_*S_*INNER_];
__device__ float g_attn[B_*S_*INNER_];
__device__ float g_ff1 [B_*S_*2*DFF_];    // 128 MB
__device__ float g_glu [B_*S_*DFF_];      // 64 MB
__device__ float g_emb [B_*2*D_];

// ---------------------------------------------------------------------------
// emb = t @ W + b  (tiny: B x 2D outputs, K = 1024)
// one thread per output element
// ---------------------------------------------------------------------------
__global__ void emb_kernel(const float* __restrict__ t,
                           const float* __restrict__ W,
                           const float* __restrict__ bias,
                           float* __restrict__ emb) {
    int j = blockIdx.x * blockDim.x + threadIdx.x;   // 0 .. B*2D-1
    int b  = j / (2*D_);
    int jj = j - b * (2*D_);
    const float* tr = t + b * D_;
    float acc = bias[jj];
    #pragma unroll 8
    for (int k = 0; k < D_; k++)
        acc += tr[k] * W[k * (2*D_) + jj];
    emb[j] = acc;
}

// ---------------------------------------------------------------------------
// AdaLN: out = layernorm(x) * (1 + scale) + shift    (one block per row)
// ---------------------------------------------------------------------------
__global__ void __launch_bounds__(256) adaln_kernel(const float* __restrict__ x,
                                                    const float* __restrict__ emb,
                                                    float* __restrict__ out) {
    int row = blockIdx.x;                // 0 .. B*S-1
    int b   = row >> 11;                 // row / 2048
    const float* xr = x + (size_t)row * D_;
    int tid = threadIdx.x;

    float v[4];
    float s = 0.f, ss = 0.f;
    #pragma unroll
    for (int i = 0; i < 4; i++) {
        v[i] = xr[tid + i*256];
        s  += v[i];
        ss += v[i]*v[i];
    }
    // warp reduce
    #pragma unroll
    for (int off = 16; off; off >>= 1) {
        s  += __shfl_xor_sync(0xffffffffu, s,  off);
        ss += __shfl_xor_sync(0xffffffffu, ss, off);
    }
    __shared__ float rs[8], rss[8];
    __shared__ float s_mean, s_rstd;
    int w = tid >> 5, lane = tid & 31;
    if (lane == 0) { rs[w] = s; rss[w] = ss; }
    __syncthreads();
    if (tid == 0) {
        float S1 = 0.f, S2 = 0.f;
        #pragma unroll
        for (int i = 0; i < 8; i++) { S1 += rs[i]; S2 += rss[i]; }
        float mean = S1 * (1.f/D_);
        float var  = S2 * (1.f/D_) - mean*mean;
        s_mean = mean;
        s_rstd = rsqrtf(var + 1e-5f);
    }
    __syncthreads();
    float mean = s_mean, rstd = s_rstd;
    const float* eb = emb + b * (2*D_);
    float* orow = out + (size_t)row * D_;
    #pragma unroll
    for (int i = 0; i < 4; i++) {
        int j = tid + i*256;
        orow[j] = (v[i] - mean) * rstd * (1.f + eb[j]) + eb[D_ + j];
    }
}

// ---------------------------------------------------------------------------
// Tiled SGEMM: C[M,N] = A[M,K] @ W[K,N]  (+bias)  (+resid)
// BM=BN=128, BK=16, 256 threads, 8x8 per thread
// All dims must be multiples of 128 (true for every call here).
// ---------------------------------------------------------------------------
#define BM 128
#define BN 128
#define BK 16

template<bool BIAS, bool RESID>
__global__ void __launch_bounds__(256) sgemm_kernel(
        const float* __restrict__ A, const float* __restrict__ W,
        const float* __restrict__ bias, const float* __restrict__ Rs,
        float* __restrict__ C, int M, int N, int K) {
    __shared__ float As[BK * BM];   // [k][m]
    __shared__ float Bs[BK * BN];   // [k][n]

    int tid = threadIdx.x;
    int tx = tid & 15, ty = tid >> 4;
    const int m0 = blockIdx.y * BM, n0 = blockIdx.x * BN;

    float acc[8][8];
    #pragma unroll
    for (int i = 0; i < 8; i++)
        #pragma unroll
        for (int j = 0; j < 8; j++) acc[i][j] = 0.f;

    for (int k0 = 0; k0 < K; k0 += BK) {
        // load A tile 128x16 (512 float4)
        #pragma unroll
        for (int it = 0; it < 2; it++) {
            int i = tid + it*256;
            int r = i >> 2, c4 = (i & 3) << 2;
            float4 a = *(const float4*)(A + (size_t)(m0 + r)*K + k0 + c4);
            As[(c4+0)*BM + r] = a.x;
            As[(c4+1)*BM + r] = a.y;
            As[(c4+2)*BM + r] = a.z;
            As[(c4+3)*BM + r] = a.w;
        }
        // load W tile 16x128 (512 float4, fully coalesced)
        #pragma unroll
        for (int it = 0; it < 2; it++) {
            int i = tid + it*256;
            int r = i >> 5, c4 = (i & 31) << 2;
            *(float4*)(Bs + r*BN + c4) =
                *(const float4*)(W + (size_t)(k0 + r)*N + n0 + c4);
        }
        __syncthreads();

        #pragma unroll
        for (int k = 0; k < BK; k++) {
            float ra[8], rb[8];
            *(float4*)(ra  ) = *(const float4*)(As + k*BM + ty*8);
            *(float4*)(ra+4) = *(const float4*)(As + k*BM + ty*8 + 4);
            *(float4*)(rb  ) = *(const float4*)(Bs + k*BN + tx*8);
            *(float4*)(rb+4) = *(const float4*)(Bs + k*BN + tx*8 + 4);
            #pragma unroll
            for (int i = 0; i < 8; i++)
                #pragma unroll
                for (int j = 0; j < 8; j++)
                    acc[i][j] += ra[i] * rb[j];
        }
        __syncthreads();
    }

    #pragma unroll
    for (int i = 0; i < 8; i++) {
        int row = m0 + ty*8 + i;
        #pragma unroll
        for (int j = 0; j < 8; j++) {
            int col = n0 + tx*8 + j;
            float v = acc[i][j];
            if (BIAS)  v += bias[col];
            if (RESID) v += Rs[(size_t)row*N + col];
            C[(size_t)row*N + col] = v;
        }
    }
}

// ---------------------------------------------------------------------------
// Flash attention (fp32). One warp per query row, 8 rows per block.
// Q/K/V/O layout: [b, s, h*64+d] with row stride 1024.
// scale = 1/sqrt(64) = 0.125
// ---------------------------------------------------------------------------
#define LDK 68     // padded key-tile row stride (floats); 68*4 bytes is 16B-aligned
#define KTILE 128
#define FLASH_SMEM ((512 + 2*KTILE*LDK) * 4)

__global__ void __launch_bounds__(256) flash_kernel(
        const float* __restrict__ Q, const float* __restrict__ Kg,
        const float* __restrict__ Vg, float* __restrict__ O,
        int Sq, int Sk) {
    extern __shared__ float sm[];
    float* q_s = sm;                  // 8 x 64
    float* K_s = sm + 512;            // KTILE x LDK
    float* V_s = K_s + KTILE*LDK;     // KTILE x LDK

    const int tid = threadIdx.x;
    const int w = tid >> 5, lane = tid & 31;
    const int h = blockIdx.y, b = blockIdx.z;
    const int qrow = blockIdx.x * 8 + w;

    // load 8 q rows (128 float4)
    for (int i = tid; i < 8*16; i += 256) {
        int r = i >> 4, c4 = (i & 15) << 2;
        *(float4*)(q_s + r*64 + c4) =
            *(const float4*)(Q + ((size_t)(b*Sq + blockIdx.x*8 + r))*INNER_ + h*DH_ + c4);
    }

    float m = -1e30f, l = 0.f;
    float acc[64];
    #pragma unroll
    for (int d = 0; d < 64; d++) acc[d] = 0.f;

    const int ntiles = Sk / KTILE;
    for (int kt = 0; kt < ntiles; kt++) {
        __syncthreads();
        // load K and V tiles: 128 rows x 64 cols each (2048 float4 per matrix)
        const int kbase = kt * KTILE;
        for (int i = tid; i < KTILE*16; i += 256) {
            int r = i >> 4, c4 = (i & 15) << 2;
            size_t gofs = ((size_t)(b*Sk + kbase + r))*INNER_ + h*DH_ + c4;
            float4 kv = *(const float4*)(Kg + gofs);
            float4 vv = *(const float4*)(Vg + gofs);
            K_s[r*LDK + c4+0] = kv.x; K_s[r*LDK + c4+1] = kv.y;
            K_s[r*LDK + c4+2] = kv.z; K_s[r*LDK + c4+3] = kv.w;
            V_s[r*LDK + c4+0] = vv.x; V_s[r*LDK + c4+1] = vv.y;
            V_s[r*LDK + c4+2] = vv.z; V_s[r*LDK + c4+3] = vv.w;
        }
        __syncthreads();

        // 4 keys per lane: j = c*32 + lane
        float s0 = 0.f, s1 = 0.f, s2 = 0.f, s3 = 0.f;
        const float4* q4 = (const float4*)(q_s + w*64);
        const float4* k0p = (const float4*)(K_s + (      lane)*LDK);
        const float4* k1p = (const float4*)(K_s + ( 32 + lane)*LDK);
        const float4* k2p = (const float4*)(K_s + ( 64 + lane)*LDK);
        const float4* k3p = (const float4*)(K_s + ( 96 + lane)*LDK);
        #pragma unroll
        for (int d4 = 0; d4 < 16; d4++) {
            float4 qv = q4[d4];
            float4 a = k0p[d4], c = k1p[d4], e = k2p[d4], g = k3p[d4];
            s0 += qv.x*a.x + qv.y*a.y + qv.z*a.z + qv.w*a.w;
            s1 += qv.x*c.x + qv.y*c.y + qv.z*c.z + qv.w*c.w;
            s2 += qv.x*e.x + qv.y*e.y + qv.z*e.z + qv.w*e.w;
            s3 += qv.x*g.x + qv.y*g.y + qv.z*g.z + qv.w*g.w;
        }
        s0 *= 0.125f; s1 *= 0.125f; s2 *= 0.125f; s3 *= 0.125f;

        float mt = fmaxf(fmaxf(s0, s1), fmaxf(s2, s3));
        float mnew = fmaxf(m, mt);
        float corr = expf(m - mnew);
        float p0 = expf(s0 - mnew), p1 = expf(s1 - mnew);
        float p2 = expf(s2 - mnew), p3 = expf(s3 - mnew);
        l = l * corr + (p0 + p1 + p2 + p3);
        m = mnew;

        const float4* v0p = (const float4*)(V_s + (      lane)*LDK);
        const float4* v1p = (const float4*)(V_s + ( 32 + lane)*LDK);
        const float4* v2p = (const float4*)(V_s + ( 64 + lane)*LDK);
        const float4* v3p = (const float4*)(V_s + ( 96 + lane)*LDK);
        #pragma unroll
        for (int d4 = 0; d4 < 16; d4++) {
            float4 a = v0p[d4], c = v1p[d4], e = v2p[d4], g = v3p[d4];
            int d = d4 * 4;
            acc[d+0] = acc[d+0]*corr + p0*a.x + p1*c.x + p2*e.x + p3*g.x;
            acc[d+1] = acc[d+1]*corr + p0*a.y + p1*c.y + p2*e.y + p3*g.y;
            acc[d+2] = acc[d+2]*corr + p0*a.z + p1*c.z + p2*e.z + p3*g.z;
            acc[d+3] = acc[d+3]*corr + p0*a.w + p1*c.w + p2*e.w + p3*g.w;
        }
    }

    // merge 32 per-lane partial softmax states (butterfly)
    #pragma unroll
    for (int off = 16; off; off >>= 1) {
        float m2 = __shfl_xor_sync(0xffffffffu, m, off);
        float l2 = __shfl_xor_sync(0xffffffffu, l, off);
        float M  = fmaxf(m, m2);
        float c1 = expf(m - M), c2 = expf(m2 - M);
        l = l*c1 + l2*c2;
        #pragma unroll
        for (int d = 0; d < 64; d++) {
            float o2 = __shfl_xor_sync(0xffffffffu, acc[d], off);
            acc[d] = acc[d]*c1 + o2*c2;
        }
        m = M;
    }

    float inv = 1.f / l;
    float* op = O + ((size_t)(b*Sq + qrow))*INNER_ + h*DH_;
    #pragma unroll
    for (int d = 0; d < 64; d++)
        if ((d & 31) == lane) op[d] = acc[d] * inv;
}

// ---------------------------------------------------------------------------
// GEGLU: out[row, j] = u[row, j] * gelu(u[row, DFF + j])   (exact gelu)
// ---------------------------------------------------------------------------
__global__ void glu_kernel(const float* __restrict__ u, float* __restrict__ out) {
    int idx = blockIdx.x * blockDim.x + threadIdx.x;   // < B*S*DFF
    int row = idx >> 12;
    int j   = idx & (DFF_ - 1);
    float a = u[(size_t)row * (2*DFF_) + j];
    float g = u[(size_t)row * (2*DFF_) + DFF_ + j];
    float ge = 0.5f * g * (1.f + erff(g * 0.70710678118654752f));
    out[idx] = a * ge;
}

// ---------------------------------------------------------------------------
// Launch
// ---------------------------------------------------------------------------
static float* sym_addr(const void* s) {
    void* p = nullptr;
    cudaGetSymbolAddress(&p, s);
    return (float*)p;
}

extern "C" void kernel_launch(void* const* d_in, const int* in_sizes, int n_in,
                              void* d_out, int out_size) {
    const float* x_in   = (const float*)d_in[0];
    const float* t_in   = (const float*)d_in[1];
    const float* ctx_in = (const float*)d_in[2];
    const float* a1_wq = (const float*)d_in[3];
    const float* a1_wk = (const float*)d_in[4];
    const float* a1_wv = (const float*)d_in[5];
    const float* a1_wo = (const float*)d_in[6];
    const float* a1_bo = (const float*)d_in[7];
    const float* a2_wq = (const float*)d_in[8];
    const float* a2_wk = (const float*)d_in[9];
    const float* a2_wv = (const float*)d_in[10];
    const float* a2_wo = (const float*)d_in[11];
    const float* a2_bo = (const float*)d_in[12];
    const float* ff_w1 = (const float*)d_in[13];
    const float* ff_b1 = (const float*)d_in[14];
    const float* ff_w2 = (const float*)d_in[15];
    const float* ff_b2 = (const float*)d_in[16];
    const float* n1_w  = (const float*)d_in[17];
    const float* n1_b  = (const float*)d_in[18];
    const float* n2_w  = (const float*)d_in[19];
    const float* n2_b  = (const float*)d_in[20];
    const float* n3_w  = (const float*)d_in[21];
    const float* n3_b  = (const float*)d_in[22];
    float* out = (float*)d_out;

    float* px    = sym_addr(g_x);
    float* ph    = sym_addr(g_h);
    float* pq    = sym_addr(g_q);
    float* pk    = sym_addr(g_k);
    float* pv    = sym_addr(g_v);
    float* pattn = sym_addr(g_attn);
    float* pff1  = sym_addr(g_ff1);
    float* pglu  = sym_addr(g_glu);
    float* pemb  = sym_addr(g_emb);

    cudaFuncSetAttribute(flash_kernel,
                         cudaFuncAttributeMaxDynamicSharedMemorySize, FLASH_SMEM);

    const int M  = B_ * S_;      // 4096
    const int Mc = B_ * CTX_;    // 512
    dim3 blk256(256);

    // ---------------- phase 1: AdaLN + self-attention ----------------
    emb_kernel<<<(B_*2*D_)/256, blk256>>>(t_in, n1_w, n1_b, pemb);
    adaln_kernel<<<M, blk256>>>(x_in, pemb, ph);

    dim3 g1(INNER_/BN, M/BM);
    sgemm_kernel<false,false><<<g1, blk256>>>(ph, a1_wq, nullptr, nullptr, pq, M, INNER_, D_);
    sgemm_kernel<false,false><<<g1, blk256>>>(ph, a1_wk, nullptr, nullptr, pk, M, INNER_, D_);
    sgemm_kernel<false,false><<<g1, blk256>>>(ph, a1_wv, nullptr, nullptr, pv, M, INNER_, D_);

    dim3 gf1(S_/8, H_, B_);
    flash_kernel<<<gf1, blk256, FLASH_SMEM>>>(pq, pk, pv, pattn, S_, S_);

    dim3 g2(D_/BN, M/BM);
    sgemm_kernel<true,true><<<g2, blk256>>>(pattn, a1_wo, a1_bo, x_in, px, M, D_, INNER_);

    // ---------------- phase 2: AdaLN + cross-attention ----------------
    emb_kernel<<<(B_*2*D_)/256, blk256>>>(t_in, n2_w, n2_b, pemb);
    adaln_kernel<<<M, blk256>>>(px, pemb, ph);

    sgemm_kernel<false,false><<<g1, blk256>>>(ph, a2_wq, nullptr, nullptr, pq, M, INNER_, D_);
    dim3 g1c(INNER_/BN, Mc/BM);
    sgemm_kernel<false,false><<<g1c, blk256>>>(ctx_in, a2_wk, nullptr, nullptr, pk, Mc, INNER_, D_);
    sgemm_kernel<false,false><<<g1c, blk256>>>(ctx_in, a2_wv, nullptr, nullptr, pv, Mc, INNER_, D_);

    flash_kernel<<<gf1, blk256, FLASH_SMEM>>>(pq, pk, pv, pattn, S_, CTX_);

    sgemm_kernel<true,true><<<g2, blk256>>>(pattn, a2_wo, a2_bo, px, px, M, D_, INNER_);

    // ---------------- phase 3: AdaLN + GEGLU FFN ----------------
    emb_kernel<<<(B_*2*D_)/256, blk256>>>(t_in, n3_w, n3_b, pemb);
    adaln_kernel<<<M, blk256>>>(px, pemb, ph);

    dim3 g3((2*DFF_)/BN, M/BM);
    sgemm_kernel<true,false><<<g3, blk256>>>(ph, ff_w1, ff_b1, nullptr, pff1, M, 2*DFF_, D_);

    glu_kernel<<<(B_*S_*DFF_)/256, blk256>>>(pff1, pglu);

    dim3 g4(D_/BN, M/BM);
    sgemm_kernel<true,true><<<g4, blk256>>>(pglu, ff_w2, ff_b2, px, out, M, D_, DFF_);
}

// round 3
// speedup vs baseline: 1.5015x; 1.5015x over previous
#include <cuda_runtime.h>
#include <cuda_bf16.h>
#include <math.h>
#include <cstdint>

// ---------------------------------------------------------------------------
// Problem constants
// ---------------------------------------------------------------------------
#define B_   2
#define S_   2048
#define CTX_ 256
#define D_   1024
#define H_   16
#define DH_  64
#define INNER_ 1024
#define DFF_ 4096

__device__ __forceinline__ float to_tf32(float x) {
    float y;
    asm("cvt.rna.tf32.f32 %0, %1;" : "=f"(y) : "f"(x));
    return y;
}

// ---------------------------------------------------------------------------
// Scratch (static device globals: no allocation allowed)
// ---------------------------------------------------------------------------
__device__ float g_x   [B_*S_*D_];
__device__ float g_h   [B_*S_*D_];
__device__ float g_q   [B_*S_*INNER_];
__device__ float g_k   [B_*S_*INNER_];
__device__ float g_v   [B_*S_*INNER_];
__device__ float g_attn[B_*S_*INNER_];
__device__ float g_ff1 [B_*S_*2*DFF_];
__device__ float g_glu [B_*S_*DFF_];
__device__ float g_emb [B_*2*D_];
// transposed weights: [N,K] K-major
__device__ float g_a1wqT[INNER_*D_];
__device__ float g_a1wkT[INNER_*D_];
__device__ float g_a1wvT[INNER_*D_];
__device__ float g_a1woT[D_*INNER_];
__device__ float g_a2wqT[INNER_*D_];
__device__ float g_a2wkT[INNER_*D_];
__device__ float g_a2wvT[INNER_*D_];
__device__ float g_a2woT[D_*INNER_];
__device__ float g_ffw1T[2*DFF_*D_];
__device__ float g_ffw2T[D_*DFF_];

// ---------------------------------------------------------------------------
// Transpose: src[R, C] -> dst[C, R]
// ---------------------------------------------------------------------------
__global__ void __launch_bounds__(256) transpose_kernel(const float* __restrict__ src,
                                                        float* __restrict__ dst,
                                                        int R, int C) {
    __shared__ float t[32][33];
    int bx = blockIdx.x * 32, by = blockIdx.y * 32;
    int x = bx + threadIdx.x;
    #pragma unroll
    for (int i = 0; i < 4; i++) {
        int y = by + threadIdx.y + i * 8;
        t[threadIdx.y + i*8][threadIdx.x] = src[(size_t)y * C + x];
    }
    __syncthreads();
    int x2 = by + threadIdx.x;
    #pragma unroll
    for (int i = 0; i < 4; i++) {
        int y2 = bx + threadIdx.y + i * 8;
        dst[(size_t)y2 * R + x2] = t[threadIdx.x][threadIdx.y + i*8];
    }
}

// ---------------------------------------------------------------------------
// emb = t @ W + b
// ---------------------------------------------------------------------------
__global__ void emb_kernel(const float* __restrict__ t,
                           const float* __restrict__ W,
                           const float* __restrict__ bias,
                           float* __restrict__ emb) {
    int j = blockIdx.x * blockDim.x + threadIdx.x;
    int b  = j / (2*D_);
    int jj = j - b * (2*D_);
    const float* tr = t + b * D_;
    float acc = bias[jj];
    #pragma unroll 8
    for (int k = 0; k < D_; k++)
        acc += tr[k] * W[k * (2*D_) + jj];
    emb[j] = acc;
}

// ---------------------------------------------------------------------------
// AdaLN
// ---------------------------------------------------------------------------
__global__ void __launch_bounds__(256) adaln_kernel(const float* __restrict__ x,
                                                    const float* __restrict__ emb,
                                                    float* __restrict__ out) {
    int row = blockIdx.x;
    int b   = row >> 11;
    const float* xr = x + (size_t)row * D_;
    int tid = threadIdx.x;

    float v[4];
    float s = 0.f, ss = 0.f;
    #pragma unroll
    for (int i = 0; i < 4; i++) {
        v[i] = xr[tid + i*256];
        s  += v[i];
        ss += v[i]*v[i];
    }
    #pragma unroll
    for (int off = 16; off; off >>= 1) {
        s  += __shfl_xor_sync(0xffffffffu, s,  off);
        ss += __shfl_xor_sync(0xffffffffu, ss, off);
    }
    __shared__ float rs[8], rss[8];
    __shared__ float s_mean, s_rstd;
    int w = tid >> 5, lane = tid & 31;
    if (lane == 0) { rs[w] = s; rss[w] = ss; }
    __syncthreads();
    if (tid == 0) {
        float S1 = 0.f, S2 = 0.f;
        #pragma unroll
        for (int i = 0; i < 8; i++) { S1 += rs[i]; S2 += rss[i]; }
        float mean = S1 * (1.f/D_);
        float var  = S2 * (1.f/D_) - mean*mean;
        s_mean = mean;
        s_rstd = rsqrtf(var + 1e-5f);
    }
    __syncthreads();
    float mean = s_mean, rstd = s_rstd;
    const float* eb = emb + b * (2*D_);
    float* orow = out + (size_t)row * D_;
    #pragma unroll
    for (int i = 0; i < 4; i++) {
        int j = tid + i*256;
        orow[j] = (v[i] - mean) * rstd * (1.f + eb[j]) + eb[D_ + j];
    }
}

// ---------------------------------------------------------------------------
// mma.sync tf32 GEMM: C[M,N] = A[M,K] @ Bt[N,K]^T   (+bias) (+resid)
// Block tile 128x128x16; 8 warps as 4(M) x 2(N); warp tile 32x64.
// mma.m16n8k8: per warp per k-step: 2 m-frag x 8 n-frag.
// SMEM: As/Bs [128][20] (pad 20 -> conflict-free quad LDS), double buffered.
// ---------------------------------------------------------------------------
#define LDT 20

__device__ __forceinline__ void mma_tf32(float* c, const uint32_t* a, const uint32_t* b) {
    asm volatile(
        "mma.sync.aligned.m16n8k8.row.col.f32.tf32.tf32.f32 "
        "{%0,%1,%2,%3}, {%4,%5,%6,%7}, {%8,%9}, {%0,%1,%2,%3};"
        : "+f"(c[0]), "+f"(c[1]), "+f"(c[2]), "+f"(c[3])
        : "r"(a[0]), "r"(a[1]), "r"(a[2]), "r"(a[3]), "r"(b[0]), "r"(b[1]));
}

template<bool BIAS, bool RESID>
__global__ void __launch_bounds__(256) gemm_mma_kernel(
        const float* __restrict__ A, const float* __restrict__ Bt,
        const float* __restrict__ bias, const float* __restrict__ Rs,
        float* __restrict__ C, int M, int N, int K) {
    __shared__ float As[2][128*LDT];
    __shared__ float Bs[2][128*LDT];

    const int tid  = threadIdx.x;
    const int wid  = tid >> 5, lane = tid & 31;
    const int grp  = lane >> 2, tig = lane & 3;
    const int wm   = (wid & 3) * 32;      // warp M offset in tile
    const int wn   = (wid >> 2) * 64;     // warp N offset in tile
    const int m0   = blockIdx.y * 128, n0 = blockIdx.x * 128;

    float acc[2][8][4];
    #pragma unroll
    for (int i = 0; i < 2; i++)
        #pragma unroll
        for (int j = 0; j < 8; j++)
            #pragma unroll
            for (int q = 0; q < 4; q++) acc[i][j][q] = 0.f;

    const int niter = K >> 4;

    // preload tile 0
    {
        #pragma unroll
        for (int j = 0; j < 2; j++) {
            int idx = tid + j * 256;
            int r = idx >> 2, c4 = (idx & 3) << 2;
            float4 av = *(const float4*)(A  + (size_t)(m0 + r) * K + c4);
            float4 bv = *(const float4*)(Bt + (size_t)(n0 + r) * K + c4);
            float* ap = &As[0][r*LDT + c4];
            float* bp = &Bs[0][r*LDT + c4];
            ap[0]=to_tf32(av.x); ap[1]=to_tf32(av.y); ap[2]=to_tf32(av.z); ap[3]=to_tf32(av.w);
            bp[0]=to_tf32(bv.x); bp[1]=to_tf32(bv.y); bp[2]=to_tf32(bv.z); bp[3]=to_tf32(bv.w);
        }
    }
    __syncthreads();

    for (int it = 0; it < niter; ++it) {
        const int s = it & 1;
        float4 pav[2], pbv[2];
        if (it + 1 < niter) {
            const int k0 = (it + 1) << 4;
            #pragma unroll
            for (int j = 0; j < 2; j++) {
                int idx = tid + j * 256;
                int r = idx >> 2, c4 = (idx & 3) << 2;
                pav[j] = *(const float4*)(A  + (size_t)(m0 + r) * K + k0 + c4);
                pbv[j] = *(const float4*)(Bt + (size_t)(n0 + r) * K + k0 + c4);
            }
        }

        const float* as = As[s];
        const float* bs = Bs[s];
        #pragma unroll
        for (int kk = 0; kk < 16; kk += 8) {
            uint32_t af[2][4], bf[8][2];
            #pragma unroll
            for (int mt = 0; mt < 2; mt++) {
                int r = wm + mt*16 + grp;
                af[mt][0] = __float_as_uint(as[(r    )*LDT + kk + tig    ]);
                af[mt][1] = __float_as_uint(as[(r + 8)*LDT + kk + tig    ]);
                af[mt][2] = __float_as_uint(as[(r    )*LDT + kk + tig + 4]);
                af[mt][3] = __float_as_uint(as[(r + 8)*LDT + kk + tig + 4]);
            }
            #pragma unroll
            for (int nt = 0; nt < 8; nt++) {
                int r = wn + nt*8 + grp;
                bf[nt][0] = __float_as_uint(bs[r*LDT + kk + tig    ]);
                bf[nt][1] = __float_as_uint(bs[r*LDT + kk + tig + 4]);
            }
            #pragma unroll
            for (int mt = 0; mt < 2; mt++)
                #pragma unroll
                for (int nt = 0; nt < 8; nt++)
                    mma_tf32(acc[mt][nt], af[mt], bf[nt]);
        }

        if (it + 1 < niter) {
            const int s2 = s ^ 1;
            #pragma unroll
            for (int j = 0; j < 2; j++) {
                int idx = tid + j * 256;
                int r = idx >> 2, c4 = (idx & 3) << 2;
                float* ap = &As[s2][r*LDT + c4];
                float* bp = &Bs[s2][r*LDT + c4];
                ap[0]=to_tf32(pav[j].x); ap[1]=to_tf32(pav[j].y);
                ap[2]=to_tf32(pav[j].z); ap[3]=to_tf32(pav[j].w);
                bp[0]=to_tf32(pbv[j].x); bp[1]=to_tf32(pbv[j].y);
                bp[2]=to_tf32(pbv[j].z); bp[3]=to_tf32(pbv[j].w);
            }
        }
        __syncthreads();
    }

    // Epilogue
    #pragma unroll
    for (int mt = 0; mt < 2; mt++) {
        #pragma unroll
        for (int nt = 0; nt < 8; nt++) {
            int row = m0 + wm + mt*16 + grp;
            int col = n0 + wn + nt*8 + tig*2;
            float2 v01 = make_float2(acc[mt][nt][0], acc[mt][nt][1]);
            float2 v23 = make_float2(acc[mt][nt][2], acc[mt][nt][3]);
            if (BIAS) {
                float2 bv = *(const float2*)(bias + col);
                v01.x += bv.x; v01.y += bv.y;
                v23.x += bv.x; v23.y += bv.y;
            }
            if (RESID) {
                float2 r0 = *(const float2*)(Rs + (size_t)row * N + col);
                float2 r1 = *(const float2*)(Rs + (size_t)(row + 8) * N + col);
                v01.x += r0.x; v01.y += r0.y;
                v23.x += r1.x; v23.y += r1.y;
            }
            *(float2*)(C + (size_t)row * N + col) = v01;
            *(float2*)(C + (size_t)(row + 8) * N + col) = v23;
        }
    }
}

// ---------------------------------------------------------------------------
// Flash attention (fp32), __expf fast path
// ---------------------------------------------------------------------------
#define LDK 68
#define KTILE 128
#define FLASH_SMEM ((512 + 2*KTILE*LDK) * 4)

__global__ void __launch_bounds__(256) flash_kernel(
        const float* __restrict__ Q, const float* __restrict__ Kg,
        const float* __restrict__ Vg, float* __restrict__ O,
        int Sq, int Sk) {
    extern __shared__ float fsm[];
    float* q_s = fsm;
    float* K_s = fsm + 512;
    float* V_s = K_s + KTILE*LDK;

    const int tid = threadIdx.x;
    const int w = tid >> 5, lane = tid & 31;
    const int h = blockIdx.y, b = blockIdx.z;
    const int qrow = blockIdx.x * 8 + w;

    for (int i = tid; i < 8*16; i += 256) {
        int r = i >> 4, c4 = (i & 15) << 2;
        *(float4*)(q_s + r*64 + c4) =
            *(const float4*)(Q + ((size_t)(b*Sq + blockIdx.x*8 + r))*INNER_ + h*DH_ + c4);
    }

    float m = -1e30f, l = 0.f;
    float acc[64];
    #pragma unroll
    for (int d = 0; d < 64; d++) acc[d] = 0.f;

    const int ntiles = Sk / KTILE;
    for (int kt = 0; kt < ntiles; kt++) {
        __syncthreads();
        const int kbase = kt * KTILE;
        for (int i = tid; i < KTILE*16; i += 256) {
            int r = i >> 4, c4 = (i & 15) << 2;
            size_t gofs = ((size_t)(b*Sk + kbase + r))*INNER_ + h*DH_ + c4;
            float4 kv = *(const float4*)(Kg + gofs);
            float4 vv = *(const float4*)(Vg + gofs);
            K_s[r*LDK + c4+0] = kv.x; K_s[r*LDK + c4+1] = kv.y;
            K_s[r*LDK + c4+2] = kv.z; K_s[r*LDK + c4+3] = kv.w;
            V_s[r*LDK + c4+0] = vv.x; V_s[r*LDK + c4+1] = vv.y;
            V_s[r*LDK + c4+2] = vv.z; V_s[r*LDK + c4+3] = vv.w;
        }
        __syncthreads();

        float s0 = 0.f, s1 = 0.f, s2 = 0.f, s3 = 0.f;
        const float4* q4 = (const float4*)(q_s + w*64);
        const float4* k0p = (const float4*)(K_s + (      lane)*LDK);
        const float4* k1p = (const float4*)(K_s + ( 32 + lane)*LDK);
        const float4* k2p = (const float4*)(K_s + ( 64 + lane)*LDK);
        const float4* k3p = (const float4*)(K_s + ( 96 + lane)*LDK);
        #pragma unroll
        for (int d4 = 0; d4 < 16; d4++) {
            float4 qv = q4[d4];
            float4 a = k0p[d4], c = k1p[d4], e = k2p[d4], g = k3p[d4];
            s0 += qv.x*a.x + qv.y*a.y + qv.z*a.z + qv.w*a.w;
            s1 += qv.x*c.x + qv.y*c.y + qv.z*c.z + qv.w*c.w;
            s2 += qv.x*e.x + qv.y*e.y + qv.z*e.z + qv.w*e.w;
            s3 += qv.x*g.x + qv.y*g.y + qv.z*g.z + qv.w*g.w;
        }
        s0 *= 0.125f; s1 *= 0.125f; s2 *= 0.125f; s3 *= 0.125f;

        float mt = fmaxf(fmaxf(s0, s1), fmaxf(s2, s3));
        float mnew = fmaxf(m, mt);
        float corr = __expf(m - mnew);
        float p0 = __expf(s0 - mnew), p1 = __expf(s1 - mnew);
        float p2 = __expf(s2 - mnew), p3 = __expf(s3 - mnew);
        l = l * corr + (p0 + p1 + p2 + p3);
        m = mnew;

        const float4* v0p = (const float4*)(V_s + (      lane)*LDK);
        const float4* v1p = (const float4*)(V_s + ( 32 + lane)*LDK);
        const float4* v2p = (const float4*)(V_s + ( 64 + lane)*LDK);
        const float4* v3p = (const float4*)(V_s + ( 96 + lane)*LDK);
        #pragma unroll
        for (int d4 = 0; d4 < 16; d4++) {
            float4 a = v0p[d4], c = v1p[d4], e = v2p[d4], g = v3p[d4];
            int d = d4 * 4;
            acc[d+0] = acc[d+0]*corr + p0*a.x + p1*c.x + p2*e.x + p3*g.x;
            acc[d+1] = acc[d+1]*corr + p0*a.y + p1*c.y + p2*e.y + p3*g.y;
            acc[d+2] = acc[d+2]*corr + p0*a.z + p1*c.z + p2*e.z + p3*g.z;
            acc[d+3] = acc[d+3]*corr + p0*a.w + p1*c.w + p2*e.w + p3*g.w;
        }
    }

    #pragma unroll
    for (int off = 16; off; off >>= 1) {
        float m2 = __shfl_xor_sync(0xffffffffu, m, off);
        float l2 = __shfl_xor_sync(0xffffffffu, l, off);
        float M  = fmaxf(m, m2);
        float c1 = __expf(m - M), c2 = __expf(m2 - M);
        l = l*c1 + l2*c2;
        #pragma unroll
        for (int d = 0; d < 64; d++) {
            float o2 = __shfl_xor_sync(0xffffffffu, acc[d], off);
            acc[d] = acc[d]*c1 + o2*c2;
        }
        m = M;
    }

    float inv = 1.f / l;
    float* op = O + ((size_t)(b*Sq + qrow))*INNER_ + h*DH_;
    #pragma unroll
    for (int d = 0; d < 64; d++)
        if ((d & 31) == lane) op[d] = acc[d] * inv;
}

// ---------------------------------------------------------------------------
// GEGLU
// ---------------------------------------------------------------------------
__global__ void glu_kernel(const float* __restrict__ u, float* __restrict__ out) {
    int idx = blockIdx.x * blockDim.x + threadIdx.x;
    int row = idx >> 12;
    int j   = idx & (DFF_ - 1);
    float a = u[(size_t)row * (2*DFF_) + j];
    float g = u[(size_t)row * (2*DFF_) + DFF_ + j];
    float ge = 0.5f * g * (1.f + erff(g * 0.70710678118654752f));
    out[idx] = a * ge;
}

// ---------------------------------------------------------------------------
// Launch
// ---------------------------------------------------------------------------
static float* sym_addr(const void* s) {
    void* p = nullptr;
    cudaGetSymbolAddress(&p, s);
    return (float*)p;
}

extern "C" void kernel_launch(void* const* d_in, const int* in_sizes, int n_in,
                              void* d_out, int out_size) {
    const float* x_in   = (const float*)d_in[0];
    const float* t_in   = (const float*)d_in[1];
    const float* ctx_in = (const float*)d_in[2];
    const float* a1_wq = (const float*)d_in[3];
    const float* a1_wk = (const float*)d_in[4];
    const float* a1_wv = (const float*)d_in[5];
    const float* a1_wo = (const float*)d_in[6];
    const float* a1_bo = (const float*)d_in[7];
    const float* a2_wq = (const float*)d_in[8];
    const float* a2_wk = (const float*)d_in[9];
    const float* a2_wv = (const float*)d_in[10];
    const float* a2_wo = (const float*)d_in[11];
    const float* a2_bo = (const float*)d_in[12];
    const float* ff_w1 = (const float*)d_in[13];
    const float* ff_b1 = (const float*)d_in[14];
    const float* ff_w2 = (const float*)d_in[15];
    const float* ff_b2 = (const float*)d_in[16];
    const float* n1_w  = (const float*)d_in[17];
    const float* n1_b  = (const float*)d_in[18];
    const float* n2_w  = (const float*)d_in[19];
    const float* n2_b  = (const float*)d_in[20];
    const float* n3_w  = (const float*)d_in[21];
    const float* n3_b  = (const float*)d_in[22];
    float* out = (float*)d_out;

    float* px    = sym_addr(g_x);
    float* ph    = sym_addr(g_h);
    float* pq    = sym_addr(g_q);
    float* pk    = sym_addr(g_k);
    float* pv    = sym_addr(g_v);
    float* pattn = sym_addr(g_attn);
    float* pff1  = sym_addr(g_ff1);
    float* pglu  = sym_addr(g_glu);
    float* pemb  = sym_addr(g_emb);

    float* pa1wqT = sym_addr(g_a1wqT);
    float* pa1wkT = sym_addr(g_a1wkT);
    float* pa1wvT = sym_addr(g_a1wvT);
    float* pa1woT = sym_addr(g_a1woT);
    float* pa2wqT = sym_addr(g_a2wqT);
    float* pa2wkT = sym_addr(g_a2wkT);
    float* pa2wvT = sym_addr(g_a2wvT);
    float* pa2woT = sym_addr(g_a2woT);
    float* pffw1T = sym_addr(g_ffw1T);
    float* pffw2T = sym_addr(g_ffw2T);

    cudaFuncSetAttribute(flash_kernel,
                         cudaFuncAttributeMaxDynamicSharedMemorySize, FLASH_SMEM);

    const int M  = B_ * S_;      // 4096
    const int Mc = B_ * CTX_;    // 512
    dim3 blk256(256);
    dim3 tblk(32, 8);

    // ---- weight transposes ([K,N] -> [N,K]) ----
    transpose_kernel<<<dim3(INNER_/32, D_/32), tblk>>>(a1_wq, pa1wqT, D_, INNER_);
    transpose_kernel<<<dim3(INNER_/32, D_/32), tblk>>>(a1_wk, pa1wkT, D_, INNER_);
    transpose_kernel<<<dim3(INNER_/32, D_/32), tblk>>>(a1_wv, pa1wvT, D_, INNER_);
    transpose_kernel<<<dim3(D_/32, INNER_/32), tblk>>>(a1_wo, pa1woT, INNER_, D_);
    transpose_kernel<<<dim3(INNER_/32, D_/32), tblk>>>(a2_wq, pa2wqT, D_, INNER_);
    transpose_kernel<<<dim3(INNER_/32, D_/32), tblk>>>(a2_wk, pa2wkT, D_, INNER_);
    transpose_kernel<<<dim3(INNER_/32, D_/32), tblk>>>(a2_wv, pa2wvT, D_, INNER_);
    transpose_kernel<<<dim3(D_/32, INNER_/32), tblk>>>(a2_wo, pa2woT, INNER_, D_);
    transpose_kernel<<<dim3((2*DFF_)/32, D_/32), tblk>>>(ff_w1, pffw1T, D_, 2*DFF_);
    transpose_kernel<<<dim3(D_/32, DFF_/32), tblk>>>(ff_w2, pffw2T, DFF_, D_);

    // ---------------- phase 1: AdaLN + self-attention ----------------
    emb_kernel<<<(B_*2*D_)/256, blk256>>>(t_in, n1_w, n1_b, pemb);
    adaln_kernel<<<M, blk256>>>(x_in, pemb, ph);

    dim3 g1(INNER_/128, M/128);
    gemm_mma_kernel<false,false><<<g1, blk256>>>(ph, pa1wqT, nullptr, nullptr, pq, M, INNER_, D_);
    gemm_mma_kernel<false,false><<<g1, blk256>>>(ph, pa1wkT, nullptr, nullptr, pk, M, INNER_, D_);
    gemm_mma_kernel<false,false><<<g1, blk256>>>(ph, pa1wvT, nullptr, nullptr, pv, M, INNER_, D_);

    dim3 gf1(S_/8, H_, B_);
    flash_kernel<<<gf1, blk256, FLASH_SMEM>>>(pq, pk, pv, pattn, S_, S_);

    dim3 g2(D_/128, M/128);
    gemm_mma_kernel<true,true><<<g2, blk256>>>(pattn, pa1woT, a1_bo, x_in, px, M, D_, INNER_);

    // ---------------- phase 2: AdaLN + cross-attention ----------------
    emb_kernel<<<(B_*2*D_)/256, blk256>>>(t_in, n2_w, n2_b, pemb);
    adaln_kernel<<<M, blk256>>>(px, pemb, ph);

    gemm_mma_kernel<false,false><<<g1, blk256>>>(ph, pa2wqT, nullptr, nullptr, pq, M, INNER_, D_);
    dim3 g1c(INNER_/128, Mc/128);
    gemm_mma_kernel<false,false><<<g1c, blk256>>>(ctx_in, pa2wkT, nullptr, nullptr, pk, Mc, INNER_, D_);
    gemm_mma_kernel<false,false><<<g1c, blk256>>>(ctx_in, pa2wvT, nullptr, nullptr, pv, Mc, INNER_, D_);

    flash_kernel<<<gf1, blk256, FLASH_SMEM>>>(pq, pk, pv, pattn, S_, CTX_);

    gemm_mma_kernel<true,true><<<g2, blk256>>>(pattn, pa2woT, a2_bo, px, px, M, D_, INNER_);

    // ---------------- phase 3: AdaLN + GEGLU FFN ----------------
    emb_kernel<<<(B_*2*D_)/256, blk256>>>(t_in, n3_w, n3_b, pemb);
    adaln_kernel<<<M, blk256>>>(px, pemb, ph);

    dim3 g3((2*DFF_)/128, M/128);
    gemm_mma_kernel<true,false><<<g3, blk256>>>(ph, pffw1T, ff_b1, nullptr, pff1, M, 2*DFF_, D_);

    glu_kernel<<<(B_*S_*DFF_)/256, blk256>>>(pff1, pglu);

    dim3 g4(D_/128, M/128);
    gemm_mma_kernel<true,true><<<g4, blk256>>>(pglu, pffw2T, ff_b2, px, out, M, D_, DFF_);
}

// round 4
// speedup vs baseline: 3.2329x; 2.1530x over previous
#include <cuda_runtime.h>
#include <cuda_bf16.h>
#include <math.h>
#include <cstdint>

// ---------------------------------------------------------------------------
// Problem constants
// ---------------------------------------------------------------------------
#define B_   2
#define S_   2048
#define CTX_ 256
#define D_   1024
#define H_   16
#define DH_  64
#define INNER_ 1024
#define DFF_ 4096

__device__ __forceinline__ float to_tf32(float x) {
    float y;
    asm("cvt.rna.tf32.f32 %0, %1;" : "=f"(y) : "f"(x));
    return y;
}
__device__ __forceinline__ float ex2f(float x) {
    float y;
    asm("ex2.approx.f32 %0, %1;" : "=f"(y) : "f"(x));
    return y;
}

// ---------------------------------------------------------------------------
// Scratch (static device globals: no allocation allowed)
// ---------------------------------------------------------------------------
__device__ float g_x   [B_*S_*D_];
__device__ float g_h   [B_*S_*D_];
__device__ float g_q   [B_*S_*INNER_];
__device__ float g_k   [B_*S_*INNER_];
__device__ float g_v   [B_*S_*INNER_];
__device__ float g_attn[B_*S_*INNER_];
__device__ float g_ff1 [B_*S_*2*DFF_];
__device__ float g_glu [B_*S_*DFF_];
__device__ float g_emb [B_*2*D_];
// transposed weights: [N,K] K-major
__device__ float g_a1wqT[INNER_*D_];
__device__ float g_a1wkT[INNER_*D_];
__device__ float g_a1wvT[INNER_*D_];
__device__ float g_a1woT[D_*INNER_];
__device__ float g_a2wqT[INNER_*D_];
__device__ float g_a2wkT[INNER_*D_];
__device__ float g_a2wvT[INNER_*D_];
__device__ float g_a2woT[D_*INNER_];
__device__ float g_ffw1T[2*DFF_*D_];
__device__ float g_ffw2T[D_*DFF_];

// ---------------------------------------------------------------------------
// Transpose: src[R, C] -> dst[C, R]
// ---------------------------------------------------------------------------
__global__ void __launch_bounds__(256) transpose_kernel(const float* __restrict__ src,
                                                        float* __restrict__ dst,
                                                        int R, int C) {
    __shared__ float t[32][33];
    int bx = blockIdx.x * 32, by = blockIdx.y * 32;
    int x = bx + threadIdx.x;
    #pragma unroll
    for (int i = 0; i < 4; i++) {
        int y = by + threadIdx.y + i * 8;
        t[threadIdx.y + i*8][threadIdx.x] = src[(size_t)y * C + x];
    }
    __syncthreads();
    int x2 = by + threadIdx.x;
    #pragma unroll
    for (int i = 0; i < 4; i++) {
        int y2 = bx + threadIdx.y + i * 8;
        dst[(size_t)y2 * R + x2] = t[threadIdx.x][threadIdx.y + i*8];
    }
}

// ---------------------------------------------------------------------------
// emb = t @ W + b
// ---------------------------------------------------------------------------
__global__ void emb_kernel(const float* __restrict__ t,
                           const float* __restrict__ W,
                           const float* __restrict__ bias,
                           float* __restrict__ emb) {
    int j = blockIdx.x * blockDim.x + threadIdx.x;
    int b  = j / (2*D_);
    int jj = j - b * (2*D_);
    const float* tr = t + b * D_;
    float acc = bias[jj];
    #pragma unroll 8
    for (int k = 0; k < D_; k++)
        acc += tr[k] * W[k * (2*D_) + jj];
    emb[j] = acc;
}

// ---------------------------------------------------------------------------
// AdaLN
// ---------------------------------------------------------------------------
__global__ void __launch_bounds__(256) adaln_kernel(const float* __restrict__ x,
                                                    const float* __restrict__ emb,
                                                    float* __restrict__ out) {
    int row = blockIdx.x;
    int b   = row >> 11;
    const float* xr = x + (size_t)row * D_;
    int tid = threadIdx.x;

    float v[4];
    float s = 0.f, ss = 0.f;
    #pragma unroll
    for (int i = 0; i < 4; i++) {
        v[i] = xr[tid + i*256];
        s  += v[i];
        ss += v[i]*v[i];
    }
    #pragma unroll
    for (int off = 16; off; off >>= 1) {
        s  += __shfl_xor_sync(0xffffffffu, s,  off);
        ss += __shfl_xor_sync(0xffffffffu, ss, off);
    }
    __shared__ float rs[8], rss[8];
    __shared__ float s_mean, s_rstd;
    int w = tid >> 5, lane = tid & 31;
    if (lane == 0) { rs[w] = s; rss[w] = ss; }
    __syncthreads();
    if (tid == 0) {
        float S1 = 0.f, S2 = 0.f;
        #pragma unroll
        for (int i = 0; i < 8; i++) { S1 += rs[i]; S2 += rss[i]; }
        float mean = S1 * (1.f/D_);
        float var  = S2 * (1.f/D_) - mean*mean;
        s_mean = mean;
        s_rstd = rsqrtf(var + 1e-5f);
    }
    __syncthreads();
    float mean = s_mean, rstd = s_rstd;
    const float* eb = emb + b * (2*D_);
    float* orow = out + (size_t)row * D_;
    #pragma unroll
    for (int i = 0; i < 4; i++) {
        int j = tid + i*256;
        orow[j] = (v[i] - mean) * rstd * (1.f + eb[j]) + eb[D_ + j];
    }
}

// ---------------------------------------------------------------------------
// mma.sync tf32 GEMM: C[M,N] = A[M,K] @ Bt[N,K]^T   (+bias) (+resid)
// ---------------------------------------------------------------------------
#define LDT 20

__device__ __forceinline__ void mma_tf32(float* c, const uint32_t* a, const uint32_t* b) {
    asm volatile(
        "mma.sync.aligned.m16n8k8.row.col.f32.tf32.tf32.f32 "
        "{%0,%1,%2,%3}, {%4,%5,%6,%7}, {%8,%9}, {%0,%1,%2,%3};"
        : "+f"(c[0]), "+f"(c[1]), "+f"(c[2]), "+f"(c[3])
        : "r"(a[0]), "r"(a[1]), "r"(a[2]), "r"(a[3]), "r"(b[0]), "r"(b[1]));
}

template<bool BIAS, bool RESID>
__global__ void __launch_bounds__(256) gemm_mma_kernel(
        const float* __restrict__ A, const float* __restrict__ Bt,
        const float* __restrict__ bias, const float* __restrict__ Rs,
        float* __restrict__ C, int M, int N, int K) {
    __shared__ float As[2][128*LDT];
    __shared__ float Bs[2][128*LDT];

    const int tid  = threadIdx.x;
    const int wid  = tid >> 5, lane = tid & 31;
    const int grp  = lane >> 2, tig = lane & 3;
    const int wm   = (wid & 3) * 32;
    const int wn   = (wid >> 2) * 64;
    const int m0   = blockIdx.y * 128, n0 = blockIdx.x * 128;

    float acc[2][8][4];
    #pragma unroll
    for (int i = 0; i < 2; i++)
        #pragma unroll
        for (int j = 0; j < 8; j++)
            #pragma unroll
            for (int q = 0; q < 4; q++) acc[i][j][q] = 0.f;

    const int niter = K >> 4;

    {
        #pragma unroll
        for (int j = 0; j < 2; j++) {
            int idx = tid + j * 256;
            int r = idx >> 2, c4 = (idx & 3) << 2;
            float4 av = *(const float4*)(A  + (size_t)(m0 + r) * K + c4);
            float4 bv = *(const float4*)(Bt + (size_t)(n0 + r) * K + c4);
            float* ap = &As[0][r*LDT + c4];
            float* bp = &Bs[0][r*LDT + c4];
            ap[0]=to_tf32(av.x); ap[1]=to_tf32(av.y); ap[2]=to_tf32(av.z); ap[3]=to_tf32(av.w);
            bp[0]=to_tf32(bv.x); bp[1]=to_tf32(bv.y); bp[2]=to_tf32(bv.z); bp[3]=to_tf32(bv.w);
        }
    }
    __syncthreads();

    for (int it = 0; it < niter; ++it) {
        const int s = it & 1;
        float4 pav[2], pbv[2];
        if (it + 1 < niter) {
            const int k0 = (it + 1) << 4;
            #pragma unroll
            for (int j = 0; j < 2; j++) {
                int idx = tid + j * 256;
                int r = idx >> 2, c4 = (idx & 3) << 2;
                pav[j] = *(const float4*)(A  + (size_t)(m0 + r) * K + k0 + c4);
                pbv[j] = *(const float4*)(Bt + (size_t)(n0 + r) * K + k0 + c4);
            }
        }

        const float* as = As[s];
        const float* bs = Bs[s];
        #pragma unroll
        for (int kk = 0; kk < 16; kk += 8) {
            uint32_t af[2][4], bf[8][2];
            #pragma unroll
            for (int mt = 0; mt < 2; mt++) {
                int r = wm + mt*16 + grp;
                af[mt][0] = __float_as_uint(as[(r    )*LDT + kk + tig    ]);
                af[mt][1] = __float_as_uint(as[(r + 8)*LDT + kk + tig    ]);
                af[mt][2] = __float_as_uint(as[(r    )*LDT + kk + tig + 4]);
                af[mt][3] = __float_as_uint(as[(r + 8)*LDT + kk + tig + 4]);
            }
            #pragma unroll
            for (int nt = 0; nt < 8; nt++) {
                int r = wn + nt*8 + grp;
                bf[nt][0] = __float_as_uint(bs[r*LDT + kk + tig    ]);
                bf[nt][1] = __float_as_uint(bs[r*LDT + kk + tig + 4]);
            }
            #pragma unroll
            for (int mt = 0; mt < 2; mt++)
                #pragma unroll
                for (int nt = 0; nt < 8; nt++)
                    mma_tf32(acc[mt][nt], af[mt], bf[nt]);
        }

        if (it + 1 < niter) {
            const int s2 = s ^ 1;
            #pragma unroll
            for (int j = 0; j < 2; j++) {
                int idx = tid + j * 256;
                int r = idx >> 2, c4 = (idx & 3) << 2;
                float* ap = &As[s2][r*LDT + c4];
                float* bp = &Bs[s2][r*LDT + c4];
                ap[0]=to_tf32(pav[j].x); ap[1]=to_tf32(pav[j].y);
                ap[2]=to_tf32(pav[j].z); ap[3]=to_tf32(pav[j].w);
                bp[0]=to_tf32(pbv[j].x); bp[1]=to_tf32(pbv[j].y);
                bp[2]=to_tf32(pbv[j].z); bp[3]=to_tf32(pbv[j].w);
            }
        }
        __syncthreads();
    }

    #pragma unroll
    for (int mt = 0; mt < 2; mt++) {
        #pragma unroll
        for (int nt = 0; nt < 8; nt++) {
            int row = m0 + wm + mt*16 + grp;
            int col = n0 + wn + nt*8 + tig*2;
            float2 v01 = make_float2(acc[mt][nt][0], acc[mt][nt][1]);
            float2 v23 = make_float2(acc[mt][nt][2], acc[mt][nt][3]);
            if (BIAS) {
                float2 bv = *(const float2*)(bias + col);
                v01.x += bv.x; v01.y += bv.y;
                v23.x += bv.x; v23.y += bv.y;
            }
            if (RESID) {
                float2 r0 = *(const float2*)(Rs + (size_t)row * N + col);
                float2 r1 = *(const float2*)(Rs + (size_t)(row + 8) * N + col);
                v01.x += r0.x; v01.y += r0.y;
                v23.x += r1.x; v23.y += r1.y;
            }
            *(float2*)(C + (size_t)row * N + col) = v01;
            *(float2*)(C + (size_t)(row + 8) * N + col) = v23;
        }
    }
}

// ---------------------------------------------------------------------------
// Tensor-core flash attention (tf32 mma, fp32 softmax state).
// 1 CTA = 64 q-rows of one (b, h). 4 warps x 16 q-rows. KTILE = 64.
// Scores computed in log2 domain: Q pre-scaled by 0.125 * log2(e).
// SMEM pads: LDQ/LDK/LDP = 68 (bank-free grp*4+tig), LDV = 72 (tig*8+grp).
// ---------------------------------------------------------------------------
#define LDQ 68
#define LDV 72
#define LDP 68
#define FLASH_SMEM ((64*LDQ + 64*LDQ + 64*LDV + 64*LDP) * 4)

__global__ void __launch_bounds__(128) flash_mma_kernel(
        const float* __restrict__ Q, const float* __restrict__ Kg,
        const float* __restrict__ Vg, float* __restrict__ O,
        int Sq, int Sk) {
    extern __shared__ float fsm[];
    float* Qs = fsm;                 // 64 x LDQ
    float* Ks = Qs + 64*LDQ;         // 64 x LDQ
    float* Vs = Ks + 64*LDQ;         // 64 x LDV
    float* Ps = Vs + 64*LDV;         // 4 warps x 16 x LDP

    const int tid = threadIdx.x;
    const int wid = tid >> 5, lane = tid & 31;
    const int grp = lane >> 2, tig = lane & 3;
    const int h = blockIdx.y, b = blockIdx.z;
    const int q0 = blockIdx.x * 64;
    const int wq = wid * 16;
    float* Pw = Ps + wid * 16 * LDP;

    const float qscale = 0.125f * 1.4426950408889634f;   // 1/sqrt(64) * log2(e)

    // load Q tile (64 x 64), pre-scaled + tf32
    for (int i = tid; i < 64*16; i += 128) {
        int r = i >> 4, c4 = (i & 15) << 2;
        float4 qv = *(const float4*)(Q + ((size_t)(b*Sq + q0 + r))*INNER_ + h*DH_ + c4);
        float* qp = &Qs[r*LDQ + c4];
        qp[0] = to_tf32(qv.x * qscale); qp[1] = to_tf32(qv.y * qscale);
        qp[2] = to_tf32(qv.z * qscale); qp[3] = to_tf32(qv.w * qscale);
    }

    float o[8][4];
    #pragma unroll
    for (int nf = 0; nf < 8; nf++)
        #pragma unroll
        for (int q = 0; q < 4; q++) o[nf][q] = 0.f;
    float m0 = -1e30f, m1 = -1e30f, l0 = 0.f, l1 = 0.f;

    const int ntiles = Sk >> 6;
    for (int kt = 0; kt < ntiles; kt++) {
        __syncthreads();
        const int kbase = kt * 64;
        for (int i = tid; i < 64*16; i += 128) {
            int r = i >> 4, c4 = (i & 15) << 2;
            size_t gofs = ((size_t)(b*Sk + kbase + r))*INNER_ + h*DH_ + c4;
            float4 kv = *(const float4*)(Kg + gofs);
            float4 vv = *(const float4*)(Vg + gofs);
            float* kp = &Ks[r*LDQ + c4];
            kp[0] = to_tf32(kv.x); kp[1] = to_tf32(kv.y);
            kp[2] = to_tf32(kv.z); kp[3] = to_tf32(kv.w);
            float* vp = &Vs[r*LDV + c4];
            vp[0] = to_tf32(vv.x); vp[1] = to_tf32(vv.y);
            vp[2] = to_tf32(vv.z); vp[3] = to_tf32(vv.w);
        }
        __syncthreads();

        // S = Q K^T  (m16 x n64, k = 64)
        float sc[8][4];
        #pragma unroll
        for (int nf = 0; nf < 8; nf++)
            #pragma unroll
            for (int q = 0; q < 4; q++) sc[nf][q] = 0.f;

        #pragma unroll
        for (int kk = 0; kk < 64; kk += 8) {
            uint32_t af[4];
            af[0] = __float_as_uint(Qs[(wq + grp    )*LDQ + kk + tig    ]);
            af[1] = __float_as_uint(Qs[(wq + grp + 8)*LDQ + kk + tig    ]);
            af[2] = __float_as_uint(Qs[(wq + grp    )*LDQ + kk + tig + 4]);
            af[3] = __float_as_uint(Qs[(wq + grp + 8)*LDQ + kk + tig + 4]);
            #pragma unroll
            for (int nf = 0; nf < 8; nf++) {
                uint32_t bf[2];
                bf[0] = __float_as_uint(Ks[(nf*8 + grp)*LDQ + kk + tig    ]);
                bf[1] = __float_as_uint(Ks[(nf*8 + grp)*LDQ + kk + tig + 4]);
                mma_tf32(sc[nf], af, bf);
            }
        }

        // row max (rows grp -> c0,c1 ; grp+8 -> c2,c3)
        float r0 = -1e30f, r1 = -1e30f;
        #pragma unroll
        for (int nf = 0; nf < 8; nf++) {
            r0 = fmaxf(r0, fmaxf(sc[nf][0], sc[nf][1]));
            r1 = fmaxf(r1, fmaxf(sc[nf][2], sc[nf][3]));
        }
        r0 = fmaxf(r0, __shfl_xor_sync(0xffffffffu, r0, 1));
        r0 = fmaxf(r0, __shfl_xor_sync(0xffffffffu, r0, 2));
        r1 = fmaxf(r1, __shfl_xor_sync(0xffffffffu, r1, 1));
        r1 = fmaxf(r1, __shfl_xor_sync(0xffffffffu, r1, 2));

        float mn0 = fmaxf(m0, r0), mn1 = fmaxf(m1, r1);
        float corr0 = ex2f(m0 - mn0), corr1 = ex2f(m1 - mn1);
        m0 = mn0; m1 = mn1;

        // p = 2^(s - m), row sums, store P (tf32)
        float rs0 = 0.f, rs1 = 0.f;
        #pragma unroll
        for (int nf = 0; nf < 8; nf++) {
            float p0 = ex2f(sc[nf][0] - mn0);
            float p1 = ex2f(sc[nf][1] - mn0);
            float p2 = ex2f(sc[nf][2] - mn1);
            float p3 = ex2f(sc[nf][3] - mn1);
            rs0 += p0 + p1; rs1 += p2 + p3;
            Pw[(grp    )*LDP + nf*8 + 2*tig    ] = to_tf32(p0);
            Pw[(grp    )*LDP + nf*8 + 2*tig + 1] = to_tf32(p1);
            Pw[(grp + 8)*LDP + nf*8 + 2*tig    ] = to_tf32(p2);
            Pw[(grp + 8)*LDP + nf*8 + 2*tig + 1] = to_tf32(p3);
        }
        rs0 += __shfl_xor_sync(0xffffffffu, rs0, 1);
        rs0 += __shfl_xor_sync(0xffffffffu, rs0, 2);
        rs1 += __shfl_xor_sync(0xffffffffu, rs1, 1);
        rs1 += __shfl_xor_sync(0xffffffffu, rs1, 2);
        l0 = l0 * corr0 + rs0;
        l1 = l1 * corr1 + rs1;

        // rescale O accumulators
        #pragma unroll
        for (int nf = 0; nf < 8; nf++) {
            o[nf][0] *= corr0; o[nf][1] *= corr0;
            o[nf][2] *= corr1; o[nf][3] *= corr1;
        }

        __syncwarp();

        // O += P V   (A = Pw m16 x k64, B = Vs[k][n])
        #pragma unroll
        for (int kk = 0; kk < 64; kk += 8) {
            uint32_t af[4];
            af[0] = __float_as_uint(Pw[(grp    )*LDP + kk + tig    ]);
            af[1] = __float_as_uint(Pw[(grp + 8)*LDP + kk + tig    ]);
            af[2] = __float_as_uint(Pw[(grp    )*LDP + kk + tig + 4]);
            af[3] = __float_as_uint(Pw[(grp + 8)*LDP + kk + tig + 4]);
            #pragma unroll
            for (int nf = 0; nf < 8; nf++) {
                uint32_t bf[2];
                bf[0] = __float_as_uint(Vs[(kk + tig    )*LDV + nf*8 + grp]);
                bf[1] = __float_as_uint(Vs[(kk + tig + 4)*LDV + nf*8 + grp]);
                mma_tf32(o[nf], af, bf);
            }
        }
        __syncwarp();
    }

    float inv0 = 1.f / l0, inv1 = 1.f / l1;
    const size_t row0 = (size_t)(b*Sq + q0 + wq + grp);
    float* op0 = O + row0 * INNER_ + h*DH_;
    float* op1 = O + (row0 + 8) * INNER_ + h*DH_;
    #pragma unroll
    for (int nf = 0; nf < 8; nf++) {
        int col = nf*8 + 2*tig;
        *(float2*)(op0 + col) = make_float2(o[nf][0]*inv0, o[nf][1]*inv0);
        *(float2*)(op1 + col) = make_float2(o[nf][2]*inv1, o[nf][3]*inv1);
    }
}

// ---------------------------------------------------------------------------
// GEGLU
// ---------------------------------------------------------------------------
__global__ void glu_kernel(const float* __restrict__ u, float* __restrict__ out) {
    int idx = blockIdx.x * blockDim.x + threadIdx.x;
    int row = idx >> 12;
    int j   = idx & (DFF_ - 1);
    float a = u[(size_t)row * (2*DFF_) + j];
    float g = u[(size_t)row * (2*DFF_) + DFF_ + j];
    float ge = 0.5f * g * (1.f + erff(g * 0.70710678118654752f));
    out[idx] = a * ge;
}

// ---------------------------------------------------------------------------
// Launch
// ---------------------------------------------------------------------------
static float* sym_addr(const void* s) {
    void* p = nullptr;
    cudaGetSymbolAddress(&p, s);
    return (float*)p;
}

extern "C" void kernel_launch(void* const* d_in, const int* in_sizes, int n_in,
                              void* d_out, int out_size) {
    const float* x_in   = (const float*)d_in[0];
    const float* t_in   = (const float*)d_in[1];
    const float* ctx_in = (const float*)d_in[2];
    const float* a1_wq = (const float*)d_in[3];
    const float* a1_wk = (const float*)d_in[4];
    const float* a1_wv = (const float*)d_in[5];
    const float* a1_wo = (const float*)d_in[6];
    const float* a1_bo = (const float*)d_in[7];
    const float* a2_wq = (const float*)d_in[8];
    const float* a2_wk = (const float*)d_in[9];
    const float* a2_wv = (const float*)d_in[10];
    const float* a2_wo = (const float*)d_in[11];
    const float* a2_bo = (const float*)d_in[12];
    const float* ff_w1 = (const float*)d_in[13];
    const float* ff_b1 = (const float*)d_in[14];
    const float* ff_w2 = (const float*)d_in[15];
    const float* ff_b2 = (const float*)d_in[16];
    const float* n1_w  = (const float*)d_in[17];
    const float* n1_b  = (const float*)d_in[18];
    const float* n2_w  = (const float*)d_in[19];
    const float* n2_b  = (const float*)d_in[20];
    const float* n3_w  = (const float*)d_in[21];
    const float* n3_b  = (const float*)d_in[22];
    float* out = (float*)d_out;

    float* px    = sym_addr(g_x);
    float* ph    = sym_addr(g_h);
    float* pq    = sym_addr(g_q);
    float* pk    = sym_addr(g_k);
    float* pv    = sym_addr(g_v);
    float* pattn = sym_addr(g_attn);
    float* pff1  = sym_addr(g_ff1);
    float* pglu  = sym_addr(g_glu);
    float* pemb  = sym_addr(g_emb);

    float* pa1wqT = sym_addr(g_a1wqT);
    float* pa1wkT = sym_addr(g_a1wkT);
    float* pa1wvT = sym_addr(g_a1wvT);
    float* pa1woT = sym_addr(g_a1woT);
    float* pa2wqT = sym_addr(g_a2wqT);
    float* pa2wkT = sym_addr(g_a2wkT);
    float* pa2wvT = sym_addr(g_a2wvT);
    float* pa2woT = sym_addr(g_a2woT);
    float* pffw1T = sym_addr(g_ffw1T);
    float* pffw2T = sym_addr(g_ffw2T);

    cudaFuncSetAttribute(flash_mma_kernel,
                         cudaFuncAttributeMaxDynamicSharedMemorySize, FLASH_SMEM);

    const int M  = B_ * S_;      // 4096
    const int Mc = B_ * CTX_;    // 512
    dim3 blk256(256);
    dim3 blk128(128);
    dim3 tblk(32, 8);

    // ---- weight transposes ([K,N] -> [N,K]) ----
    transpose_kernel<<<dim3(INNER_/32, D_/32), tblk>>>(a1_wq, pa1wqT, D_, INNER_);
    transpose_kernel<<<dim3(INNER_/32, D_/32), tblk>>>(a1_wk, pa1wkT, D_, INNER_);
    transpose_kernel<<<dim3(INNER_/32, D_/32), tblk>>>(a1_wv, pa1wvT, D_, INNER_);
    transpose_kernel<<<dim3(D_/32, INNER_/32), tblk>>>(a1_wo, pa1woT, INNER_, D_);
    transpose_kernel<<<dim3(INNER_/32, D_/32), tblk>>>(a2_wq, pa2wqT, D_, INNER_);
    transpose_kernel<<<dim3(INNER_/32, D_/32), tblk>>>(a2_wk, pa2wkT, D_, INNER_);
    transpose_kernel<<<dim3(INNER_/32, D_/32), tblk>>>(a2_wv, pa2wvT, D_, INNER_);
    transpose_kernel<<<dim3(D_/32, INNER_/32), tblk>>>(a2_wo, pa2woT, INNER_, D_);
    transpose_kernel<<<dim3((2*DFF_)/32, D_/32), tblk>>>(ff_w1, pffw1T, D_, 2*DFF_);
    transpose_kernel<<<dim3(D_/32, DFF_/32), tblk>>>(ff_w2, pffw2T, DFF_, D_);

    // ---------------- phase 1: AdaLN + self-attention ----------------
    emb_kernel<<<(B_*2*D_)/256, blk256>>>(t_in, n1_w, n1_b, pemb);
    adaln_kernel<<<M, blk256>>>(x_in, pemb, ph);

    dim3 g1(INNER_/128, M/128);
    gemm_mma_kernel<false,false><<<g1, blk256>>>(ph, pa1wqT, nullptr, nullptr, pq, M, INNER_, D_);
    gemm_mma_kernel<false,false><<<g1, blk256>>>(ph, pa1wkT, nullptr, nullptr, pk, M, INNER_, D_);
    gemm_mma_kernel<false,false><<<g1, blk256>>>(ph, pa1wvT, nullptr, nullptr, pv, M, INNER_, D_);

    dim3 gf1(S_/64, H_, B_);
    flash_mma_kernel<<<gf1, blk128, FLASH_SMEM>>>(pq, pk, pv, pattn, S_, S_);

    dim3 g2(D_/128, M/128);
    gemm_mma_kernel<true,true><<<g2, blk256>>>(pattn, pa1woT, a1_bo, x_in, px, M, D_, INNER_);

    // ---------------- phase 2: AdaLN + cross-attention ----------------
    emb_kernel<<<(B_*2*D_)/256, blk256>>>(t_in, n2_w, n2_b, pemb);
    adaln_kernel<<<M, blk256>>>(px, pemb, ph);

    gemm_mma_kernel<false,false><<<g1, blk256>>>(ph, pa2wqT, nullptr, nullptr, pq, M, INNER_, D_);
    dim3 g1c(INNER_/128, Mc/128);
    gemm_mma_kernel<false,false><<<g1c, blk256>>>(ctx_in, pa2wkT, nullptr, nullptr, pk, Mc, INNER_, D_);
    gemm_mma_kernel<false,false><<<g1c, blk256>>>(ctx_in, pa2wvT, nullptr, nullptr, pv, Mc, INNER_, D_);

    flash_mma_kernel<<<gf1, blk128, FLASH_SMEM>>>(pq, pk, pv, pattn, S_, CTX_);

    gemm_mma_kernel<true,true><<<g2, blk256>>>(pattn, pa2woT, a2_bo, px, px, M, D_, INNER_);

    // ---------------- phase 3: AdaLN + GEGLU FFN ----------------
    emb_kernel<<<(B_*2*D_)/256, blk256>>>(t_in, n3_w, n3_b, pemb);
    adaln_kernel<<<M, blk256>>>(px, pemb, ph);

    dim3 g3((2*DFF_)/128, M/128);
    gemm_mma_kernel<true,false><<<g3, blk256>>>(ph, pffw1T, ff_b1, nullptr, pff1, M, 2*DFF_, D_);

    glu_kernel<<<(B_*S_*DFF_)/256, blk256>>>(pff1, pglu);

    dim3 g4(D_/128, M/128);
    gemm_mma_kernel<true,true><<<g4, blk256>>>(pglu, pffw2T, ff_b2, px, out, M, D_, DFF_);
}

// round 6
// speedup vs baseline: 6.0157x; 1.8608x over previous
#include <cuda_runtime.h>
#include <cuda_fp16.h>
#include <math.h>
#include <cstdint>

// ---------------------------------------------------------------------------
// Problem constants
// ---------------------------------------------------------------------------
#define B_   2
#define S_   2048
#define CTX_ 256
#define D_   1024
#define H_   16
#define DH_  64
#define INNER_ 1024
#define DFF_ 4096

__device__ __forceinline__ uint32_t smem_u32(const void* p) {
    uint32_t a;
    asm("{ .reg .u64 t; cvta.to.shared.u64 t, %1; cvt.u32.u64 %0, t; }"
        : "=r"(a) : "l"(p));
    return a;
}
__device__ __forceinline__ void cp16(uint32_t dst, const void* src) {
    asm volatile("cp.async.cg.shared.global [%0], [%1], 16;" :: "r"(dst), "l"(src));
}
#define CP_COMMIT()  asm volatile("cp.async.commit_group;" ::: "memory")
#define CP_WAIT0()   asm volatile("cp.async.wait_group 0;" ::: "memory")

__device__ __forceinline__ float ex2f(float x) {
    float y;
    asm("ex2.approx.f32 %0, %1;" : "=f"(y) : "f"(x));
    return y;
}
__device__ __forceinline__ uint32_t h2_u32(__half2 h) {
    union { __half2 h; uint32_t u; } c;
    c.h = h;
    return c.u;
}
__device__ __forceinline__ void mma_f16(float* c, const uint32_t* a, const uint32_t* b) {
    asm volatile(
        "mma.sync.aligned.m16n8k16.row.col.f32.f16.f16.f32 "
        "{%0,%1,%2,%3}, {%4,%5,%6,%7}, {%8,%9}, {%0,%1,%2,%3};"
        : "+f"(c[0]), "+f"(c[1]), "+f"(c[2]), "+f"(c[3])
        : "r"(a[0]), "r"(a[1]), "r"(a[2]), "r"(a[3]), "r"(b[0]), "r"(b[1]));
}
__device__ __forceinline__ void ldmx2t(uint32_t& b0, uint32_t& b1, uint32_t addr) {
    asm volatile("ldmatrix.sync.aligned.m8n8.x2.trans.shared.b16 {%0,%1}, [%2];"
        : "=r"(b0), "=r"(b1) : "r"(addr));
}

// ---------------------------------------------------------------------------
// Scratch (static device globals)
// ---------------------------------------------------------------------------
__device__ float  g_x   [B_*S_*D_];        // residual stream (fp32)
__device__ float  g_emb [B_*2*D_];
__device__ __half g_hh  [B_*S_*D_];        // normed activations (half)
__device__ __half g_qh  [B_*S_*INNER_];
__device__ __half g_kh  [B_*S_*INNER_];
__device__ __half g_vh  [B_*S_*INNER_];
__device__ __half g_atth[B_*S_*INNER_];
__device__ __half g_ff1h[B_*S_*2*DFF_];
__device__ __half g_gluh[B_*S_*DFF_];
__device__ __half g_ctxh[B_*CTX_*D_];
// transposed half weights: [N,K] K-major
__device__ __half g_a1wqT[INNER_*D_];
__device__ __half g_a1wkT[INNER_*D_];
__device__ __half g_a1wvT[INNER_*D_];
__device__ __half g_a1woT[D_*INNER_];
__device__ __half g_a2wqT[INNER_*D_];
__device__ __half g_a2wkT[INNER_*D_];
__device__ __half g_a2wvT[INNER_*D_];
__device__ __half g_a2woT[D_*INNER_];
__device__ __half g_ffw1T[2*DFF_*D_];
__device__ __half g_ffw2T[D_*DFF_];

// ---------------------------------------------------------------------------
// Transpose + fp32 -> fp16: src[R, C] float -> dst[C, R] half
// ---------------------------------------------------------------------------
__global__ void __launch_bounds__(256) transpose_h_kernel(const float* __restrict__ src,
                                                          __half* __restrict__ dst,
                                                          int R, int C) {
    __shared__ float t[32][33];
    int bx = blockIdx.x * 32, by = blockIdx.y * 32;
    int x = bx + threadIdx.x;
    #pragma unroll
    for (int i = 0; i < 4; i++) {
        int y = by + threadIdx.y + i * 8;
        t[threadIdx.y + i*8][threadIdx.x] = src[(size_t)y * C + x];
    }
    __syncthreads();
    int x2 = by + threadIdx.x;
    #pragma unroll
    for (int i = 0; i < 4; i++) {
        int y2 = bx + threadIdx.y + i * 8;
        dst[(size_t)y2 * R + x2] = __float2half_rn(t[threadIdx.x][threadIdx.y + i*8]);
    }
}

// fp32 -> fp16 convert
__global__ void cvt_h_kernel(const float* __restrict__ src, __half* __restrict__ dst) {
    int i = blockIdx.x * blockDim.x + threadIdx.x;
    dst[i] = __float2half_rn(src[i]);
}

// ---------------------------------------------------------------------------
// emb = t @ W + b
// ---------------------------------------------------------------------------
__global__ void emb_kernel(const float* __restrict__ t,
                           const float* __restrict__ W,
                           const float* __restrict__ bias,
                           float* __restrict__ emb) {
    int j = blockIdx.x * blockDim.x + threadIdx.x;
    int b  = j / (2*D_);
    int jj = j - b * (2*D_);
    const float* tr = t + b * D_;
    float acc = bias[jj];
    #pragma unroll 8
    for (int k = 0; k < D_; k++)
        acc += tr[k] * W[k * (2*D_) + jj];
    emb[j] = acc;
}

// ---------------------------------------------------------------------------
// AdaLN -> half output
// ---------------------------------------------------------------------------
__global__ void __launch_bounds__(256) adaln_kernel(const float* __restrict__ x,
                                                    const float* __restrict__ emb,
                                                    __half* __restrict__ out) {
    int row = blockIdx.x;
    int b   = row >> 11;
    const float* xr = x + (size_t)row * D_;
    int tid = threadIdx.x;

    float v[4];
    float s = 0.f, ss = 0.f;
    #pragma unroll
    for (int i = 0; i < 4; i++) {
        v[i] = xr[tid + i*256];
        s  += v[i];
        ss += v[i]*v[i];
    }
    #pragma unroll
    for (int off = 16; off; off >>= 1) {
        s  += __shfl_xor_sync(0xffffffffu, s,  off);
        ss += __shfl_xor_sync(0xffffffffu, ss, off);
    }
    __shared__ float rs[8], rss[8];
    __shared__ float s_mean, s_rstd;
    int w = tid >> 5, lane = tid & 31;
    if (lane == 0) { rs[w] = s; rss[w] = ss; }
    __syncthreads();
    if (tid == 0) {
        float S1 = 0.f, S2 = 0.f;
        #pragma unroll
        for (int i = 0; i < 8; i++) { S1 += rs[i]; S2 += rss[i]; }
        float mean = S1 * (1.f/D_);
        float var  = S2 * (1.f/D_) - mean*mean;
        s_mean = mean;
        s_rstd = rsqrtf(var + 1e-5f);
    }
    __syncthreads();
    float mean = s_mean, rstd = s_rstd;
    const float* eb = emb + b * (2*D_);
    __half* orow = out + (size_t)row * D_;
    #pragma unroll
    for (int i = 0; i < 4; i++) {
        int j = tid + i*256;
        orow[j] = __float2half_rn((v[i] - mean) * rstd * (1.f + eb[j]) + eb[D_ + j]);
    }
}

// ---------------------------------------------------------------------------
// fp16 mma GEMM: C[M,N] = A[M,K]h @ Bt[N,K]h^T   (+bias f32) (+resid f32)
// Block tile 128x128x32; 8 warps 4(M)x2(N); warp tile 32x64; cp.async pipeline.
// SMEM row stride 40 halves -> conflict-free (stride 20 words mod 32).
// ---------------------------------------------------------------------------
#define LDG2 40

template<bool BIAS, bool RESID, bool OUTH>
__global__ void __launch_bounds__(256) gemm_h_kernel(
        const __half* __restrict__ A, const __half* __restrict__ Bt,
        const float* __restrict__ bias, const float* __restrict__ Rs,
        void* __restrict__ Cv, int M, int N, int K) {
    __shared__ __half As[2][128*LDG2];
    __shared__ __half Bs[2][128*LDG2];

    const int tid  = threadIdx.x;
    const int wid  = tid >> 5, lane = tid & 31;
    const int grp  = lane >> 2, tig = lane & 3;
    const int wm   = (wid & 3) * 32;
    const int wn   = (wid >> 2) * 64;
    const int m0   = blockIdx.y * 128, n0 = blockIdx.x * 128;

    const uint32_t as_u = smem_u32(As), bs_u = smem_u32(Bs);

    float acc[2][8][4];
    #pragma unroll
    for (int i = 0; i < 2; i++)
        #pragma unroll
        for (int j = 0; j < 8; j++)
            #pragma unroll
            for (int q = 0; q < 4; q++) acc[i][j][q] = 0.f;

    const int niter = K >> 5;

    auto issue = [&](int it, int s) {
        const int k0 = it << 5;
        #pragma unroll
        for (int j = 0; j < 2; j++) {
            int idx = tid + j * 256;
            int r = idx >> 2, c8 = (idx & 3) << 3;
            cp16(as_u + (uint32_t)(s*128*LDG2 + r*LDG2 + c8)*2,
                 A + (size_t)(m0 + r) * K + k0 + c8);
            cp16(bs_u + (uint32_t)(s*128*LDG2 + r*LDG2 + c8)*2,
                 Bt + (size_t)(n0 + r) * K + k0 + c8);
        }
        CP_COMMIT();
    };

    issue(0, 0);

    for (int it = 0; it < niter; ++it) {
        const int s = it & 1;
        CP_WAIT0();
        __syncthreads();
        if (it + 1 < niter) issue(it + 1, s ^ 1);

        const __half* as = As[s];
        const __half* bs = Bs[s];
        #pragma unroll
        for (int kk = 0; kk < 32; kk += 16) {
            uint32_t af[2][4], bf[8][2];
            #pragma unroll
            for (int mt = 0; mt < 2; mt++) {
                int r = wm + mt*16 + grp;
                af[mt][0] = *(const uint32_t*)&as[(r    )*LDG2 + kk + 2*tig    ];
                af[mt][1] = *(const uint32_t*)&as[(r + 8)*LDG2 + kk + 2*tig    ];
                af[mt][2] = *(const uint32_t*)&as[(r    )*LDG2 + kk + 2*tig + 8];
                af[mt][3] = *(const uint32_t*)&as[(r + 8)*LDG2 + kk + 2*tig + 8];
            }
            #pragma unroll
            for (int nt = 0; nt < 8; nt++) {
                int r = wn + nt*8 + grp;
                bf[nt][0] = *(const uint32_t*)&bs[r*LDG2 + kk + 2*tig    ];
                bf[nt][1] = *(const uint32_t*)&bs[r*LDG2 + kk + 2*tig + 8];
            }
            #pragma unroll
            for (int mt = 0; mt < 2; mt++)
                #pragma unroll
                for (int nt = 0; nt < 8; nt++)
                    mma_f16(acc[mt][nt], af[mt], bf[nt]);
        }
        __syncthreads();
    }

    // Epilogue
    #pragma unroll
    for (int mt = 0; mt < 2; mt++) {
        #pragma unroll
        for (int nt = 0; nt < 8; nt++) {
            int row = m0 + wm + mt*16 + grp;
            int col = n0 + wn + nt*8 + tig*2;
            float2 v01 = make_float2(acc[mt][nt][0], acc[mt][nt][1]);
            float2 v23 = make_float2(acc[mt][nt][2], acc[mt][nt][3]);
            if (BIAS) {
                float2 bv = *(const float2*)(bias + col);
                v01.x += bv.x; v01.y += bv.y;
                v23.x += bv.x; v23.y += bv.y;
            }
            if (RESID) {
                float2 r0 = *(const float2*)(Rs + (size_t)row * N + col);
                float2 r1 = *(const float2*)(Rs + (size_t)(row + 8) * N + col);
                v01.x += r0.x; v01.y += r0.y;
                v23.x += r1.x; v23.y += r1.y;
            }
            if (OUTH) {
                __half* Ch = (__half*)Cv;
                *(__half2*)(Ch + (size_t)row * N + col) = __floats2half2_rn(v01.x, v01.y);
                *(__half2*)(Ch + (size_t)(row + 8) * N + col) = __floats2half2_rn(v23.x, v23.y);
            } else {
                float* Cf = (float*)Cv;
                *(float2*)(Cf + (size_t)row * N + col) = v01;
                *(float2*)(Cf + (size_t)(row + 8) * N + col) = v23;
            }
        }
    }
}

// ---------------------------------------------------------------------------
// fp16 flash attention. 1 CTA = 64 q-rows of one (b,h); 4 warps x 16 q.
// KTILE=64, cp.async double-buffered K/V, P kept in registers (C->A reuse),
// V via ldmatrix.x2.trans. Row stride 72 halves (36 words) -> conflict-free.
// ---------------------------------------------------------------------------
#define LDF 72

__global__ void __launch_bounds__(128) flash_h_kernel(
        const __half* __restrict__ Q, const __half* __restrict__ Kg,
        const __half* __restrict__ Vg, __half* __restrict__ O,
        int Sq, int Sk) {
    __shared__ __half Qs[64*LDF];
    __shared__ __half Ks[2][64*LDF];
    __shared__ __half Vs[2][64*LDF];

    const int tid = threadIdx.x;
    const int wid = tid >> 5, lane = tid & 31;
    const int grp = lane >> 2, tig = lane & 3;
    const int h = blockIdx.y, b = blockIdx.z;
    const int q0 = blockIdx.x * 64;
    const int wq = wid * 16;
    const int vrow = lane & 15;   // ldmatrix x2 row addressing (rows 0-15)

    const uint32_t qs_u = smem_u32(Qs);
    const uint32_t ks_u = smem_u32(Ks);
    const uint32_t vs_u = smem_u32(Vs);

    const float qscale = 0.125f * 1.4426950408889634f;

    #pragma unroll
    for (int j = 0; j < 4; j++) {
        int i = tid + j * 128;
        int r = i >> 3, c8 = (i & 7) << 3;
        cp16(qs_u + (uint32_t)(r*LDF + c8)*2,
             Q + ((size_t)(b*Sq + q0 + r))*INNER_ + h*DH_ + c8);
    }
    auto issue_kv = [&](int kt, int s) {
        const int kbase = kt * 64;
        #pragma unroll
        for (int j = 0; j < 4; j++) {
            int i = tid + j * 128;
            int r = i >> 3, c8 = (i & 7) << 3;
            size_t gofs = ((size_t)(b*Sk + kbase + r))*INNER_ + h*DH_ + c8;
            cp16(ks_u + (uint32_t)(s*64*LDF + r*LDF + c8)*2, Kg + gofs);
            cp16(vs_u + (uint32_t)(s*64*LDF + r*LDF + c8)*2, Vg + gofs);
        }
        CP_COMMIT();
    };
    issue_kv(0, 0);

    float o[8][4];
    #pragma unroll
    for (int nf = 0; nf < 8; nf++)
        #pragma unroll
        for (int q = 0; q < 4; q++) o[nf][q] = 0.f;
    float m0 = -1e30f, m1 = -1e30f, l0 = 0.f, l1 = 0.f;

    const int ntiles = Sk >> 6;
    for (int kt = 0; kt < ntiles; kt++) {
        const int s = kt & 1;
        CP_WAIT0();
        __syncthreads();
        if (kt + 1 < ntiles) issue_kv(kt + 1, s ^ 1);

        const __half* ks = Ks[s];
        float sc[8][4];
        #pragma unroll
        for (int nf = 0; nf < 8; nf++)
            #pragma unroll
            for (int q = 0; q < 4; q++) sc[nf][q] = 0.f;

        #pragma unroll
        for (int kk = 0; kk < 64; kk += 16) {
            uint32_t af[4];
            af[0] = *(const uint32_t*)&Qs[(wq + grp    )*LDF + kk + 2*tig    ];
            af[1] = *(const uint32_t*)&Qs[(wq + grp + 8)*LDF + kk + 2*tig    ];
            af[2] = *(const uint32_t*)&Qs[(wq + grp    )*LDF + kk + 2*tig + 8];
            af[3] = *(const uint32_t*)&Qs[(wq + grp + 8)*LDF + kk + 2*tig + 8];
            #pragma unroll
            for (int nf = 0; nf < 8; nf++) {
                uint32_t bf[2];
                bf[0] = *(const uint32_t*)&ks[(nf*8 + grp)*LDF + kk + 2*tig    ];
                bf[1] = *(const uint32_t*)&ks[(nf*8 + grp)*LDF + kk + 2*tig + 8];
                mma_f16(sc[nf], af, bf);
            }
        }

        // online softmax (scores scaled in log2 domain)
        float r0 = -1e30f, r1 = -1e30f;
        #pragma unroll
        for (int nf = 0; nf < 8; nf++) {
            r0 = fmaxf(r0, fmaxf(sc[nf][0], sc[nf][1]));
            r1 = fmaxf(r1, fmaxf(sc[nf][2], sc[nf][3]));
        }
        r0 = fmaxf(r0, __shfl_xor_sync(0xffffffffu, r0, 1));
        r0 = fmaxf(r0, __shfl_xor_sync(0xffffffffu, r0, 2));
        r1 = fmaxf(r1, __shfl_xor_sync(0xffffffffu, r1, 1));
        r1 = fmaxf(r1, __shfl_xor_sync(0xffffffffu, r1, 2));

        float mn0 = fmaxf(m0, r0 * qscale), mn1 = fmaxf(m1, r1 * qscale);
        float corr0 = ex2f(m0 - mn0), corr1 = ex2f(m1 - mn1);
        m0 = mn0; m1 = mn1;

        float rs0 = 0.f, rs1 = 0.f;
        uint32_t ph[8][2];
        #pragma unroll
        for (int nf = 0; nf < 8; nf++) {
            float p0 = ex2f(fmaf(sc[nf][0], qscale, -mn0));
            float p1 = ex2f(fmaf(sc[nf][1], qscale, -mn0));
            float p2 = ex2f(fmaf(sc[nf][2], qscale, -mn1));
            float p3 = ex2f(fmaf(sc[nf][3], qscale, -mn1));
            rs0 += p0 + p1; rs1 += p2 + p3;
            ph[nf][0] = h2_u32(__floats2half2_rn(p0, p1));
            ph[nf][1] = h2_u32(__floats2half2_rn(p2, p3));
        }
        rs0 += __shfl_xor_sync(0xffffffffu, rs0, 1);
        rs0 += __shfl_xor_sync(0xffffffffu, rs0, 2);
        rs1 += __shfl_xor_sync(0xffffffffu, rs1, 1);
        rs1 += __shfl_xor_sync(0xffffffffu, rs1, 2);
        l0 = l0 * corr0 + rs0;
        l1 = l1 * corr1 + rs1;

        #pragma unroll
        for (int nf = 0; nf < 8; nf++) {
            o[nf][0] *= corr0; o[nf][1] *= corr0;
            o[nf][2] *= corr1; o[nf][3] *= corr1;
        }

        // O += P V ;  P from registers, V via ldmatrix.trans
        const uint32_t vb = vs_u + (uint32_t)(s*64*LDF)*2;
        #pragma unroll
        for (int kk = 0; kk < 64; kk += 16) {
            const int nf2 = kk >> 3;
            uint32_t af[4] = { ph[nf2][0], ph[nf2][1], ph[nf2+1][0], ph[nf2+1][1] };
            #pragma unroll
            for (int nf = 0; nf < 8; nf++) {
                uint32_t b0, b1;
                ldmx2t(b0, b1, vb + (uint32_t)((kk + vrow)*LDF + nf*8)*2);
                uint32_t bf[2] = { b0, b1 };
                mma_f16(o[nf], af, bf);
            }
        }
    }

    float inv0 = 1.f / l0, inv1 = 1.f / l1;
    const size_t row0 = (size_t)(b*Sq + q0 + wq + grp);
    __half* op0 = O + row0 * INNER_ + h*DH_;
    __half* op1 = O + (row0 + 8) * INNER_ + h*DH_;
    #pragma unroll
    for (int nf = 0; nf < 8; nf++) {
        int col = nf*8 + 2*tig;
        *(__half2*)(op0 + col) = __floats2half2_rn(o[nf][0]*inv0, o[nf][1]*inv0);
        *(__half2*)(op1 + col) = __floats2half2_rn(o[nf][2]*inv1, o[nf][3]*inv1);
    }
}

// ---------------------------------------------------------------------------
// GEGLU (half in, half out, fp32 math)
// ---------------------------------------------------------------------------
__global__ void glu_kernel(const __half* __restrict__ u, __half* __restrict__ out) {
    int idx = blockIdx.x * blockDim.x + threadIdx.x;
    int row = idx >> 12;
    int j   = idx & (DFF_ - 1);
    float a = __half2float(u[(size_t)row * (2*DFF_) + j]);
    float g = __half2float(u[(size_t)row * (2*DFF_) + DFF_ + j]);
    float ge = 0.5f * g * (1.f + erff(g * 0.70710678118654752f));
    out[idx] = __float2half_rn(a * ge);
}

// ---------------------------------------------------------------------------
// Launch
// ---------------------------------------------------------------------------
template<typename T>
static T* sym_addr_t(const void* s) {
    void* p = nullptr;
    cudaGetSymbolAddress(&p, s);
    return (T*)p;
}

extern "C" void kernel_launch(void* const* d_in, const int* in_sizes, int n_in,
                              void* d_out, int out_size) {
    const float* x_in   = (const float*)d_in[0];
    const float* t_in   = (const float*)d_in[1];
    const float* ctx_in = (const float*)d_in[2];
    const float* a1_wq = (const float*)d_in[3];
    const float* a1_wk = (const float*)d_in[4];
    const float* a1_wv = (const float*)d_in[5];
    const float* a1_wo = (const float*)d_in[6];
    const float* a1_bo = (const float*)d_in[7];
    const float* a2_wq = (const float*)d_in[8];
    const float* a2_wk = (const float*)d_in[9];
    const float* a2_wv = (const float*)d_in[10];
    const float* a2_wo = (const float*)d_in[11];
    const float* a2_bo = (const float*)d_in[12];
    const float* ff_w1 = (const float*)d_in[13];
    const float* ff_b1 = (const float*)d_in[14];
    const float* ff_w2 = (const float*)d_in[15];
    const float* ff_b2 = (const float*)d_in[16];
    const float* n1_w  = (const float*)d_in[17];
    const float* n1_b  = (const float*)d_in[18];
    const float* n2_w  = (const float*)d_in[19];
    const float* n2_b  = (const float*)d_in[20];
    const float* n3_w  = (const float*)d_in[21];
    const float* n3_b  = (const float*)d_in[22];
    float* out = (float*)d_out;

    float*  px    = sym_addr_t<float>(g_x);
    float*  pemb  = sym_addr_t<float>(g_emb);
    __half* phh   = sym_addr_t<__half>(g_hh);
    __half* pqh   = sym_addr_t<__half>(g_qh);
    __half* pkh   = sym_addr_t<__half>(g_kh);
    __half* pvh   = sym_addr_t<__half>(g_vh);
    __half* path  = sym_addr_t<__half>(g_atth);
    __half* pff1h = sym_addr_t<__half>(g_ff1h);
    __half* pgluh = sym_addr_t<__half>(g_gluh);
    __half* pctxh = sym_addr_t<__half>(g_ctxh);

    __half* pa1wqT = sym_addr_t<__half>(g_a1wqT);
    __half* pa1wkT = sym_addr_t<__half>(g_a1wkT);
    __half* pa1wvT = sym_addr_t<__half>(g_a1wvT);
    __half* pa1woT = sym_addr_t<__half>(g_a1woT);
    __half* pa2wqT = sym_addr_t<__half>(g_a2wqT);
    __half* pa2wkT = sym_addr_t<__half>(g_a2wkT);
    __half* pa2wvT = sym_addr_t<__half>(g_a2wvT);
    __half* pa2woT = sym_addr_t<__half>(g_a2woT);
    __half* pffw1T = sym_addr_t<__half>(g_ffw1T);
    __half* pffw2T = sym_addr_t<__half>(g_ffw2T);

    const int M  = B_ * S_;      // 4096
    const int Mc = B_ * CTX_;    // 512
    dim3 blk256(256);
    dim3 blk128(128);
    dim3 tblk(32, 8);

    // ---- weight transposes + converts ----
    transpose_h_kernel<<<dim3(INNER_/32, D_/32), tblk>>>(a1_wq, pa1wqT, D_, INNER_);
    transpose_h_kernel<<<dim3(INNER_/32, D_/32), tblk>>>(a1_wk, pa1wkT, D_, INNER_);
    transpose_h_kernel<<<dim3(INNER_/32, D_/32), tblk>>>(a1_wv, pa1wvT, D_, INNER_);
    transpose_h_kernel<<<dim3(D_/32, INNER_/32), tblk>>>(a1_wo, pa1woT, INNER_, D_);
    transpose_h_kernel<<<dim3(INNER_/32, D_/32), tblk>>>(a2_wq, pa2wqT, D_, INNER_);
    transpose_h_kernel<<<dim3(INNER_/32, D_/32), tblk>>>(a2_wk, pa2wkT, D_, INNER_);
    transpose_h_kernel<<<dim3(INNER_/32, D_/32), tblk>>>(a2_wv, pa2wvT, D_, INNER_);
    transpose_h_kernel<<<dim3(D_/32, INNER_/32), tblk>>>(a2_wo, pa2woT, INNER_, D_);
    transpose_h_kernel<<<dim3((2*DFF_)/32, D_/32), tblk>>>(ff_w1, pffw1T, D_, 2*DFF_);
    transpose_h_kernel<<<dim3(D_/32, DFF_/32), tblk>>>(ff_w2, pffw2T, DFF_, D_);
    cvt_h_kernel<<<(B_*CTX_*D_)/256, blk256>>>(ctx_in, pctxh);

    // ---------------- phase 1: AdaLN + self-attention ----------------
    emb_kernel<<<(B_*2*D_)/256, blk256>>>(t_in, n1_w, n1_b, pemb);
    adaln_kernel<<<M, blk256>>>(x_in, pemb, phh);

    dim3 g1(INNER_/128, M/128);
    gemm_h_kernel<false,false,true><<<g1, blk256>>>(phh, pa1wqT, nullptr, nullptr, pqh, M, INNER_, D_);
    gemm_h_kernel<false,false,true><<<g1, blk256>>>(phh, pa1wkT, nullptr, nullptr, pkh, M, INNER_, D_);
    gemm_h_kernel<false,false,true><<<g1, blk256>>>(phh, pa1wvT, nullptr, nullptr, pvh, M, INNER_, D_);

    dim3 gf1(S_/64, H_, B_);
    flash_h_kernel<<<gf1, blk128>>>(pqh, pkh, pvh, path, S_, S_);

    dim3 g2(D_/128, M/128);
    gemm_h_kernel<true,true,false><<<g2, blk256>>>(path, pa1woT, a1_bo, x_in, px, M, D_, INNER_);

    // ---------------- phase 2: AdaLN + cross-attention ----------------
    emb_kernel<<<(B_*2*D_)/256, blk256>>>(t_in, n2_w, n2_b, pemb);
    adaln_kernel<<<M, blk256>>>(px, pemb, phh);

    gemm_h_kernel<false,false,true><<<g1, blk256>>>(phh, pa2wqT, nullptr, nullptr, pqh, M, INNER_, D_);
    dim3 g1c(INNER_/128, Mc/128);
    gemm_h_kernel<false,false,true><<<g1c, blk256>>>(pctxh, pa2wkT, nullptr, nullptr, pkh, Mc, INNER_, D_);
    gemm_h_kernel<false,false,true><<<g1c, blk256>>>(pctxh, pa2wvT, nullptr, nullptr, pvh, Mc, INNER_, D_);

    flash_h_kernel<<<gf1, blk128>>>(pqh, pkh, pvh, path, S_, CTX_);

    gemm_h_kernel<true,true,false><<<g2, blk256>>>(path, pa2woT, a2_bo, px, px, M, D_, INNER_);

    // ---------------- phase 3: AdaLN + GEGLU FFN ----------------
    emb_kernel<<<(B_*2*D_)/256, blk256>>>(t_in, n3_w, n3_b, pemb);
    adaln_kernel<<<M, blk256>>>(px, pemb, phh);

    dim3 g3((2*DFF_)/128, M/128);
    gemm_h_kernel<true,false,true><<<g3, blk256>>>(phh, pffw1T, ff_b1, nullptr, pff1h, M, 2*DFF_, D_);

    glu_kernel<<<(B_*S_*DFF_)/256, blk256>>>(pff1h, pgluh);

    dim3 g4(D_/128, M/128);
    gemm_h_kernel<true,true,false><<<g4, blk256>>>(pgluh, pffw2T, ff_b2, px, out, M, D_, DFF_);
}

// round 7
// speedup vs baseline: 6.8036x; 1.1310x over previous
#include <cuda_runtime.h>
#include <cuda_fp16.h>
#include <math.h>
#include <cstdint>

// ---------------------------------------------------------------------------
// Problem constants
// ---------------------------------------------------------------------------
#define B_   2
#define S_   2048
#define CTX_ 256
#define D_   1024
#define H_   16
#define DH_  64
#define INNER_ 1024
#define DFF_ 4096

__device__ __forceinline__ uint32_t smem_u32(const void* p) {
    uint32_t a;
    asm("{ .reg .u64 t; cvta.to.shared.u64 t, %1; cvt.u32.u64 %0, t; }"
        : "=r"(a) : "l"(p));
    return a;
}
__device__ __forceinline__ void cp16(uint32_t dst, const void* src) {
    asm volatile("cp.async.cg.shared.global [%0], [%1], 16;" :: "r"(dst), "l"(src));
}
#define CP_COMMIT()  asm volatile("cp.async.commit_group;" ::: "memory")
#define CP_WAIT0()   asm volatile("cp.async.wait_group 0;" ::: "memory")

__device__ __forceinline__ float ex2f(float x) {
    float y;
    asm("ex2.approx.f32 %0, %1;" : "=f"(y) : "f"(x));
    return y;
}
__device__ __forceinline__ uint32_t h2_u32(__half2 h) {
    union { __half2 h; uint32_t u; } c;
    c.h = h;
    return c.u;
}
__device__ __forceinline__ void mma_f16(float* c, const uint32_t* a, const uint32_t* b) {
    asm volatile(
        "mma.sync.aligned.m16n8k16.row.col.f32.f16.f16.f32 "
        "{%0,%1,%2,%3}, {%4,%5,%6,%7}, {%8,%9}, {%0,%1,%2,%3};"
        : "+f"(c[0]), "+f"(c[1]), "+f"(c[2]), "+f"(c[3])
        : "r"(a[0]), "r"(a[1]), "r"(a[2]), "r"(a[3]), "r"(b[0]), "r"(b[1]));
}
__device__ __forceinline__ void ldmx4(uint32_t* r, uint32_t addr) {
    asm volatile("ldmatrix.sync.aligned.m8n8.x4.shared.b16 {%0,%1,%2,%3}, [%4];"
        : "=r"(r[0]), "=r"(r[1]), "=r"(r[2]), "=r"(r[3]) : "r"(addr));
}
__device__ __forceinline__ void ldmx2t(uint32_t& b0, uint32_t& b1, uint32_t addr) {
    asm volatile("ldmatrix.sync.aligned.m8n8.x2.trans.shared.b16 {%0,%1}, [%2];"
        : "=r"(b0), "=r"(b1) : "r"(addr));
}

// ---------------------------------------------------------------------------
// Scratch (static device globals)
// ---------------------------------------------------------------------------
__device__ float  g_x   [B_*S_*D_];        // residual stream (fp32)
__device__ float  g_emb [B_*2*D_];
__device__ float  g_b1i [2*DFF_];          // interleaved ff bias
__device__ __half g_hh  [B_*S_*D_];
__device__ __half g_qh  [B_*S_*INNER_];
__device__ __half g_qkvh[B_*S_*3*INNER_];
__device__ __half g_kvh [B_*CTX_*2*INNER_];
__device__ __half g_atth[B_*S_*INNER_];
__device__ __half g_gluh[B_*S_*DFF_];
__device__ __half g_ctxh[B_*CTX_*D_];
// transposed half weights: [N,K] K-major
__device__ __half g_qkv1T[3*INNER_*D_];
__device__ __half g_a1woT[D_*INNER_];
__device__ __half g_a2wqT[INNER_*D_];
__device__ __half g_kv2T [2*INNER_*D_];
__device__ __half g_a2woT[D_*INNER_];
__device__ __half g_ffw1T[2*DFF_*D_];     // GLU-interleaved rows
__device__ __half g_ffw2T[D_*DFF_];

// ---------------------------------------------------------------------------
// Transpose + fp32 -> fp16: src[R, C] float -> dst[C, R] half
// ---------------------------------------------------------------------------
__global__ void __launch_bounds__(256) transpose_h_kernel(const float* __restrict__ src,
                                                          __half* __restrict__ dst,
                                                          int R, int C) {
    __shared__ float t[32][33];
    int bx = blockIdx.x * 32, by = blockIdx.y * 32;
    int x = bx + threadIdx.x;
    #pragma unroll
    for (int i = 0; i < 4; i++) {
        int y = by + threadIdx.y + i * 8;
        t[threadIdx.y + i*8][threadIdx.x] = src[(size_t)y * C + x];
    }
    __syncthreads();
    int x2 = by + threadIdx.x;
    #pragma unroll
    for (int i = 0; i < 4; i++) {
        int y2 = bx + threadIdx.y + i * 8;
        dst[(size_t)y2 * R + x2] = __float2half_rn(t[threadIdx.x][threadIdx.y + i*8]);
    }
}

// Transpose with GLU row interleave: dst row = (c<DFF) ? 2c : 2(c-DFF)+1
__global__ void __launch_bounds__(256) transpose_h_glu_kernel(const float* __restrict__ src,
                                                              __half* __restrict__ dst,
                                                              int R, int C) {
    __shared__ float t[32][33];
    int bx = blockIdx.x * 32, by = blockIdx.y * 32;
    int x = bx + threadIdx.x;
    #pragma unroll
    for (int i = 0; i < 4; i++) {
        int y = by + threadIdx.y + i * 8;
        t[threadIdx.y + i*8][threadIdx.x] = src[(size_t)y * C + x];
    }
    __syncthreads();
    int x2 = by + threadIdx.x;
    #pragma unroll
    for (int i = 0; i < 4; i++) {
        int c = bx + threadIdx.y + i * 8;
        int nr = (c < DFF_) ? 2*c : 2*(c - DFF_) + 1;
        dst[(size_t)nr * R + x2] = __float2half_rn(t[threadIdx.x][threadIdx.y + i*8]);
    }
}

__global__ void cvt_h_kernel(const float* __restrict__ src, __half* __restrict__ dst) {
    int i = blockIdx.x * blockDim.x + threadIdx.x;
    dst[i] = __float2half_rn(src[i]);
}

__global__ void bias_ilv_kernel(const float* __restrict__ b, float* __restrict__ bi) {
    int j = blockIdx.x * blockDim.x + threadIdx.x;   // < DFF
    bi[2*j]   = b[j];
    bi[2*j+1] = b[DFF_ + j];
}

// ---------------------------------------------------------------------------
// emb = t @ W + b
// ---------------------------------------------------------------------------
__global__ void emb_kernel(const float* __restrict__ t,
                           const float* __restrict__ W,
                           const float* __restrict__ bias,
                           float* __restrict__ emb) {
    int j = blockIdx.x * blockDim.x + threadIdx.x;
    int b  = j / (2*D_);
    int jj = j - b * (2*D_);
    const float* tr = t + b * D_;
    float acc = bias[jj];
    #pragma unroll 8
    for (int k = 0; k < D_; k++)
        acc += tr[k] * W[k * (2*D_) + jj];
    emb[j] = acc;
}

// ---------------------------------------------------------------------------
// AdaLN -> half output
// ---------------------------------------------------------------------------
__global__ void __launch_bounds__(256) adaln_kernel(const float* __restrict__ x,
                                                    const float* __restrict__ emb,
                                                    __half* __restrict__ out) {
    int row = blockIdx.x;
    int b   = row >> 11;
    const float* xr = x + (size_t)row * D_;
    int tid = threadIdx.x;

    float v[4];
    float s = 0.f, ss = 0.f;
    #pragma unroll
    for (int i = 0; i < 4; i++) {
        v[i] = xr[tid + i*256];
        s  += v[i];
        ss += v[i]*v[i];
    }
    #pragma unroll
    for (int off = 16; off; off >>= 1) {
        s  += __shfl_xor_sync(0xffffffffu, s,  off);
        ss += __shfl_xor_sync(0xffffffffu, ss, off);
    }
    __shared__ float rs[8], rss[8];
    __shared__ float s_mean, s_rstd;
    int w = tid >> 5, lane = tid & 31;
    if (lane == 0) { rs[w] = s; rss[w] = ss; }
    __syncthreads();
    if (tid == 0) {
        float S1 = 0.f, S2 = 0.f;
        #pragma unroll
        for (int i = 0; i < 8; i++) { S1 += rs[i]; S2 += rss[i]; }
        float mean = S1 * (1.f/D_);
        float var  = S2 * (1.f/D_) - mean*mean;
        s_mean = mean;
        s_rstd = rsqrtf(var + 1e-5f);
    }
    __syncthreads();
    float mean = s_mean, rstd = s_rstd;
    const float* eb = emb + b * (2*D_);
    __half* orow = out + (size_t)row * D_;
    #pragma unroll
    for (int i = 0; i < 4; i++) {
        int j = tid + i*256;
        orow[j] = __float2half_rn((v[i] - mean) * rstd * (1.f + eb[j]) + eb[D_ + j]);
    }
}

// ---------------------------------------------------------------------------
// fp16 mma GEMM with ldmatrix fragments.
// Block tile 128x128x32; 8 warps 4(M)x2(N); warp tile 32x64.
// Epilogues: plain half, fp32(+bias)(+resid), or fused GEGLU (interleaved W).
// ---------------------------------------------------------------------------
#define LDG2 40

template<bool BIAS, bool RESID, bool OUTH, bool GLU>
__global__ void __launch_bounds__(256) gemm_h_kernel(
        const __half* __restrict__ A, const __half* __restrict__ Bt,
        const float* __restrict__ bias, const float* __restrict__ Rs,
        void* __restrict__ Cv, int M, int N, int K) {
    __shared__ __half As[2][128*LDG2];
    __shared__ __half Bs[2][128*LDG2];

    const int tid  = threadIdx.x;
    const int wid  = tid >> 5, lane = tid & 31;
    const int grp  = lane >> 2, tig = lane & 3;
    const int wm   = (wid & 3) * 32;
    const int wn   = (wid >> 2) * 64;
    const int m0   = blockIdx.y * 128, n0 = blockIdx.x * 128;

    const uint32_t as_u = smem_u32(As), bs_u = smem_u32(Bs);

    // ldmatrix lane addressing
    const int a_row = (lane & 15);             // + wm + mt*16
    const int a_col = (lane >> 4) << 3;        // + kk
    const int b_row = ((lane >> 4) << 3) + (lane & 7);  // + wn + p*16
    const int b_col = ((lane >> 3) & 1) << 3;  // + kk

    float acc[2][8][4];
    #pragma unroll
    for (int i = 0; i < 2; i++)
        #pragma unroll
        for (int j = 0; j < 8; j++)
            #pragma unroll
            for (int q = 0; q < 4; q++) acc[i][j][q] = 0.f;

    const int niter = K >> 5;

    auto issue = [&](int it, int s) {
        const int k0 = it << 5;
        #pragma unroll
        for (int j = 0; j < 2; j++) {
            int idx = tid + j * 256;
            int r = idx >> 2, c8 = (idx & 3) << 3;
            cp16(as_u + (uint32_t)(s*128*LDG2 + r*LDG2 + c8)*2,
                 A + (size_t)(m0 + r) * K + k0 + c8);
            cp16(bs_u + (uint32_t)(s*128*LDG2 + r*LDG2 + c8)*2,
                 Bt + (size_t)(n0 + r) * K + k0 + c8);
        }
        CP_COMMIT();
    };

    issue(0, 0);

    for (int it = 0; it < niter; ++it) {
        const int s = it & 1;
        CP_WAIT0();
        __syncthreads();
        if (it + 1 < niter) issue(it + 1, s ^ 1);

        const uint32_t as_b = as_u + (uint32_t)(s*128*LDG2)*2;
        const uint32_t bs_b = bs_u + (uint32_t)(s*128*LDG2)*2;
        #pragma unroll
        for (int kk = 0; kk < 32; kk += 16) {
            uint32_t af[2][4], bf[8][2];
            #pragma unroll
            for (int mt = 0; mt < 2; mt++)
                ldmx4(af[mt], as_b + (uint32_t)((wm + mt*16 + a_row)*LDG2 + kk + a_col)*2);
            #pragma unroll
            for (int p = 0; p < 4; p++) {
                uint32_t r4[4];
                ldmx4(r4, bs_b + (uint32_t)((wn + p*16 + b_row)*LDG2 + kk + b_col)*2);
                bf[2*p  ][0] = r4[0]; bf[2*p  ][1] = r4[1];
                bf[2*p+1][0] = r4[2]; bf[2*p+1][1] = r4[3];
            }
            #pragma unroll
            for (int mt = 0; mt < 2; mt++)
                #pragma unroll
                for (int nt = 0; nt < 8; nt++)
                    mma_f16(acc[mt][nt], af[mt], bf[nt]);
        }
        __syncthreads();
    }

    // Epilogue
    #pragma unroll
    for (int mt = 0; mt < 2; mt++) {
        #pragma unroll
        for (int nt = 0; nt < 8; nt++) {
            int row = m0 + wm + mt*16 + grp;
            int col = n0 + wn + nt*8 + tig*2;
            float2 v01 = make_float2(acc[mt][nt][0], acc[mt][nt][1]);
            float2 v23 = make_float2(acc[mt][nt][2], acc[mt][nt][3]);
            if (BIAS) {
                float2 bv = *(const float2*)(bias + col);
                v01.x += bv.x; v01.y += bv.y;
                v23.x += bv.x; v23.y += bv.y;
            }
            if (GLU) {
                // (v.x, v.y) = (a_j, gate_j), j = col/2 ; out = a * gelu(g)
                __half* Gh = (__half*)Cv;
                int j = col >> 1;
                float g0 = v01.y, g1 = v23.y;
                float ge0 = 0.5f * g0 * (1.f + erff(g0 * 0.70710678118654752f));
                float ge1 = 0.5f * g1 * (1.f + erff(g1 * 0.70710678118654752f));
                Gh[(size_t)row * DFF_ + j]       = __float2half_rn(v01.x * ge0);
                Gh[(size_t)(row + 8) * DFF_ + j] = __float2half_rn(v23.x * ge1);
            } else {
                if (RESID) {
                    float2 r0 = *(const float2*)(Rs + (size_t)row * N + col);
                    float2 r1 = *(const float2*)(Rs + (size_t)(row + 8) * N + col);
                    v01.x += r0.x; v01.y += r0.y;
                    v23.x += r1.x; v23.y += r1.y;
                }
                if (OUTH) {
                    __half* Ch = (__half*)Cv;
                    *(__half2*)(Ch + (size_t)row * N + col) = __floats2half2_rn(v01.x, v01.y);
                    *(__half2*)(Ch + (size_t)(row + 8) * N + col) = __floats2half2_rn(v23.x, v23.y);
                } else {
                    float* Cf = (float*)Cv;
                    *(float2*)(Cf + (size_t)row * N + col) = v01;
                    *(float2*)(Cf + (size_t)(row + 8) * N + col) = v23;
                }
            }
        }
    }
}

// ---------------------------------------------------------------------------
// fp16 flash attention with explicit Q/K/V row strides.
// ---------------------------------------------------------------------------
#define LDF 72

__global__ void __launch_bounds__(128) flash_h_kernel(
        const __half* __restrict__ Q, int qstr,
        const __half* __restrict__ Kg, int kstr,
        const __half* __restrict__ Vg, int vstr,
        __half* __restrict__ O,
        int Sq, int Sk) {
    __shared__ __half Qs[64*LDF];
    __shared__ __half Ks[2][64*LDF];
    __shared__ __half Vs[2][64*LDF];

    const int tid = threadIdx.x;
    const int wid = tid >> 5, lane = tid & 31;
    const int grp = lane >> 2, tig = lane & 3;
    const int h = blockIdx.y, b = blockIdx.z;
    const int q0 = blockIdx.x * 64;
    const int wq = wid * 16;
    const int vrow = lane & 15;

    const uint32_t qs_u = smem_u32(Qs);
    const uint32_t ks_u = smem_u32(Ks);
    const uint32_t vs_u = smem_u32(Vs);

    const float qscale = 0.125f * 1.4426950408889634f;

    #pragma unroll
    for (int j = 0; j < 4; j++) {
        int i = tid + j * 128;
        int r = i >> 3, c8 = (i & 7) << 3;
        cp16(qs_u + (uint32_t)(r*LDF + c8)*2,
             Q + ((size_t)(b*Sq + q0 + r))*qstr + h*DH_ + c8);
    }
    auto issue_kv = [&](int kt, int s) {
        const int kbase = kt * 64;
        #pragma unroll
        for (int j = 0; j < 4; j++) {
            int i = tid + j * 128;
            int r = i >> 3, c8 = (i & 7) << 3;
            cp16(ks_u + (uint32_t)(s*64*LDF + r*LDF + c8)*2,
                 Kg + ((size_t)(b*Sk + kbase + r))*kstr + h*DH_ + c8);
            cp16(vs_u + (uint32_t)(s*64*LDF + r*LDF + c8)*2,
                 Vg + ((size_t)(b*Sk + kbase + r))*vstr + h*DH_ + c8);
        }
        CP_COMMIT();
    };
    issue_kv(0, 0);

    float o[8][4];
    #pragma unroll
    for (int nf = 0; nf < 8; nf++)
        #pragma unroll
        for (int q = 0; q < 4; q++) o[nf][q] = 0.f;
    float m0 = -1e30f, m1 = -1e30f, l0 = 0.f, l1 = 0.f;

    const int ntiles = Sk >> 6;
    for (int kt = 0; kt < ntiles; kt++) {
        const int s = kt & 1;
        CP_WAIT0();
        __syncthreads();
        if (kt + 1 < ntiles) issue_kv(kt + 1, s ^ 1);

        const __half* ks = Ks[s];
        float sc[8][4];
        #pragma unroll
        for (int nf = 0; nf < 8; nf++)
            #pragma unroll
            for (int q = 0; q < 4; q++) sc[nf][q] = 0.f;

        #pragma unroll
        for (int kk = 0; kk < 64; kk += 16) {
            uint32_t af[4];
            af[0] = *(const uint32_t*)&Qs[(wq + grp    )*LDF + kk + 2*tig    ];
            af[1] = *(const uint32_t*)&Qs[(wq + grp + 8)*LDF + kk + 2*tig    ];
            af[2] = *(const uint32_t*)&Qs[(wq + grp    )*LDF + kk + 2*tig + 8];
            af[3] = *(const uint32_t*)&Qs[(wq + grp + 8)*LDF + kk + 2*tig + 8];
            #pragma unroll
            for (int nf = 0; nf < 8; nf++) {
                uint32_t bf[2];
                bf[0] = *(const uint32_t*)&ks[(nf*8 + grp)*LDF + kk + 2*tig    ];
                bf[1] = *(const uint32_t*)&ks[(nf*8 + grp)*LDF + kk + 2*tig + 8];
                mma_f16(sc[nf], af, bf);
            }
        }

        float r0 = -1e30f, r1 = -1e30f;
        #pragma unroll
        for (int nf = 0; nf < 8; nf++) {
            r0 = fmaxf(r0, fmaxf(sc[nf][0], sc[nf][1]));
            r1 = fmaxf(r1, fmaxf(sc[nf][2], sc[nf][3]));
        }
        r0 = fmaxf(r0, __shfl_xor_sync(0xffffffffu, r0, 1));
        r0 = fmaxf(r0, __shfl_xor_sync(0xffffffffu, r0, 2));
        r1 = fmaxf(r1, __shfl_xor_sync(0xffffffffu, r1, 1));
        r1 = fmaxf(r1, __shfl_xor_sync(0xffffffffu, r1, 2));

        float mn0 = fmaxf(m0, r0 * qscale), mn1 = fmaxf(m1, r1 * qscale);
        float corr0 = ex2f(m0 - mn0), corr1 = ex2f(m1 - mn1);
        m0 = mn0; m1 = mn1;

        float rs0 = 0.f, rs1 = 0.f;
        uint32_t ph[8][2];
        #pragma unroll
        for (int nf = 0; nf < 8; nf++) {
            float p0 = ex2f(fmaf(sc[nf][0], qscale, -mn0));
            float p1 = ex2f(fmaf(sc[nf][1], qscale, -mn0));
            float p2 = ex2f(fmaf(sc[nf][2], qscale, -mn1));
            float p3 = ex2f(fmaf(sc[nf][3], qscale, -mn1));
            rs0 += p0 + p1; rs1 += p2 + p3;
            ph[nf][0] = h2_u32(__floats2half2_rn(p0, p1));
            ph[nf][1] = h2_u32(__floats2half2_rn(p2, p3));
        }
        rs0 += __shfl_xor_sync(0xffffffffu, rs0, 1);
        rs0 += __shfl_xor_sync(0xffffffffu, rs0, 2);
        rs1 += __shfl_xor_sync(0xffffffffu, rs1, 1);
        rs1 += __shfl_xor_sync(0xffffffffu, rs1, 2);
        l0 = l0 * corr0 + rs0;
        l1 = l1 * corr1 + rs1;

        #pragma unroll
        for (int nf = 0; nf < 8; nf++) {
            o[nf][0] *= corr0; o[nf][1] *= corr0;
            o[nf][2] *= corr1; o[nf][3] *= corr1;
        }

        const uint32_t vb = vs_u + (uint32_t)(s*64*LDF)*2;
        #pragma unroll
        for (int kk = 0; kk < 64; kk += 16) {
            const int nf2 = kk >> 3;
            uint32_t af[4] = { ph[nf2][0], ph[nf2][1], ph[nf2+1][0], ph[nf2+1][1] };
            #pragma unroll
            for (int nf = 0; nf < 8; nf++) {
                uint32_t b0, b1;
                ldmx2t(b0, b1, vb + (uint32_t)((kk + vrow)*LDF + nf*8)*2);
                uint32_t bf[2] = { b0, b1 };
                mma_f16(o[nf], af, bf);
            }
        }
    }

    float inv0 = 1.f / l0, inv1 = 1.f / l1;
    const size_t row0 = (size_t)(b*Sq + q0 + wq + grp);
    __half* op0 = O + row0 * INNER_ + h*DH_;
    __half* op1 = O + (row0 + 8) * INNER_ + h*DH_;
    #pragma unroll
    for (int nf = 0; nf < 8; nf++) {
        int col = nf*8 + 2*tig;
        *(__half2*)(op0 + col) = __floats2half2_rn(o[nf][0]*inv0, o[nf][1]*inv0);
        *(__half2*)(op1 + col) = __floats2half2_rn(o[nf][2]*inv1, o[nf][3]*inv1);
    }
}

// ---------------------------------------------------------------------------
// Launch
// ---------------------------------------------------------------------------
template<typename T>
static T* sym_addr_t(const void* s) {
    void* p = nullptr;
    cudaGetSymbolAddress(&p, s);
    return (T*)p;
}

extern "C" void kernel_launch(void* const* d_in, const int* in_sizes, int n_in,
                              void* d_out, int out_size) {
    const float* x_in   = (const float*)d_in[0];
    const float* t_in   = (const float*)d_in[1];
    const float* ctx_in = (const float*)d_in[2];
    const float* a1_wq = (const float*)d_in[3];
    const float* a1_wk = (const float*)d_in[4];
    const float* a1_wv = (const float*)d_in[5];
    const float* a1_wo = (const float*)d_in[6];
    const float* a1_bo = (const float*)d_in[7];
    const float* a2_wq = (const float*)d_in[8];
    const float* a2_wk = (const float*)d_in[9];
    const float* a2_wv = (const float*)d_in[10];
    const float* a2_wo = (const float*)d_in[11];
    const float* a2_bo = (const float*)d_in[12];
    const float* ff_w1 = (const float*)d_in[13];
    const float* ff_b1 = (const float*)d_in[14];
    const float* ff_w2 = (const float*)d_in[15];
    const float* ff_b2 = (const float*)d_in[16];
    const float* n1_w  = (const float*)d_in[17];
    const float* n1_b  = (const float*)d_in[18];
    const float* n2_w  = (const float*)d_in[19];
    const float* n2_b  = (const float*)d_in[20];
    const float* n3_w  = (const float*)d_in[21];
    const float* n3_b  = (const float*)d_in[22];
    float* out = (float*)d_out;

    float*  px    = sym_addr_t<float>(g_x);
    float*  pemb  = sym_addr_t<float>(g_emb);
    float*  pb1i  = sym_addr_t<float>(g_b1i);
    __half* phh   = sym_addr_t<__half>(g_hh);
    __half* pqh   = sym_addr_t<__half>(g_qh);
    __half* pqkvh = sym_addr_t<__half>(g_qkvh);
    __half* pkvh  = sym_addr_t<__half>(g_kvh);
    __half* path  = sym_addr_t<__half>(g_atth);
    __half* pgluh = sym_addr_t<__half>(g_gluh);
    __half* pctxh = sym_addr_t<__half>(g_ctxh);

    __half* pqkv1T = sym_addr_t<__half>(g_qkv1T);
    __half* pa1woT = sym_addr_t<__half>(g_a1woT);
    __half* pa2wqT = sym_addr_t<__half>(g_a2wqT);
    __half* pkv2T  = sym_addr_t<__half>(g_kv2T);
    __half* pa2woT = sym_addr_t<__half>(g_a2woT);
    __half* pffw1T = sym_addr_t<__half>(g_ffw1T);
    __half* pffw2T = sym_addr_t<__half>(g_ffw2T);

    const int M  = B_ * S_;      // 4096
    const int Mc = B_ * CTX_;    // 512
    dim3 blk256(256);
    dim3 blk128(128);
    dim3 tblk(32, 8);

    // ---- weight transposes + converts ----
    transpose_h_kernel<<<dim3(INNER_/32, D_/32), tblk>>>(a1_wq, pqkv1T, D_, INNER_);
    transpose_h_kernel<<<dim3(INNER_/32, D_/32), tblk>>>(a1_wk, pqkv1T + (size_t)INNER_*D_, D_, INNER_);
    transpose_h_kernel<<<dim3(INNER_/32, D_/32), tblk>>>(a1_wv, pqkv1T + (size_t)2*INNER_*D_, D_, INNER_);
    transpose_h_kernel<<<dim3(D_/32, INNER_/32), tblk>>>(a1_wo, pa1woT, INNER_, D_);
    transpose_h_kernel<<<dim3(INNER_/32, D_/32), tblk>>>(a2_wq, pa2wqT, D_, INNER_);
    transpose_h_kernel<<<dim3(INNER_/32, D_/32), tblk>>>(a2_wk, pkv2T, D_, INNER_);
    transpose_h_kernel<<<dim3(INNER_/32, D_/32), tblk>>>(a2_wv, pkv2T + (size_t)INNER_*D_, D_, INNER_);
    transpose_h_kernel<<<dim3(D_/32, INNER_/32), tblk>>>(a2_wo, pa2woT, INNER_, D_);
    transpose_h_glu_kernel<<<dim3((2*DFF_)/32, D_/32), tblk>>>(ff_w1, pffw1T, D_, 2*DFF_);
    transpose_h_kernel<<<dim3(D_/32, DFF_/32), tblk>>>(ff_w2, pffw2T, DFF_, D_);
    cvt_h_kernel<<<(B_*CTX_*D_)/256, blk256>>>(ctx_in, pctxh);
    bias_ilv_kernel<<<DFF_/256, blk256>>>(ff_b1, pb1i);

    // ---------------- phase 1: AdaLN + self-attention ----------------
    emb_kernel<<<(B_*2*D_)/256, blk256>>>(t_in, n1_w, n1_b, pemb);
    adaln_kernel<<<M, blk256>>>(x_in, pemb, phh);

    dim3 gqkv((3*INNER_)/128, M/128);
    gemm_h_kernel<false,false,true,false><<<gqkv, blk256>>>(phh, pqkv1T, nullptr, nullptr, pqkvh, M, 3*INNER_, D_);

    dim3 gf1(S_/64, H_, B_);
    flash_h_kernel<<<gf1, blk128>>>(pqkvh, 3*INNER_, pqkvh + INNER_, 3*INNER_,
                                    pqkvh + 2*INNER_, 3*INNER_, path, S_, S_);

    dim3 g2(D_/128, M/128);
    gemm_h_kernel<true,true,false,false><<<g2, blk256>>>(path, pa1woT, a1_bo, x_in, px, M, D_, INNER_);

    // ---------------- phase 2: AdaLN + cross-attention ----------------
    emb_kernel<<<(B_*2*D_)/256, blk256>>>(t_in, n2_w, n2_b, pemb);
    adaln_kernel<<<M, blk256>>>(px, pemb, phh);

    dim3 g1(INNER_/128, M/128);
    gemm_h_kernel<false,false,true,false><<<g1, blk256>>>(phh, pa2wqT, nullptr, nullptr, pqh, M, INNER_, D_);
    dim3 gkv((2*INNER_)/128, Mc/128);
    gemm_h_kernel<false,false,true,false><<<gkv, blk256>>>(pctxh, pkv2T, nullptr, nullptr, pkvh, Mc, 2*INNER_, D_);

    flash_h_kernel<<<gf1, blk128>>>(pqh, INNER_, pkvh, 2*INNER_,
                                    pkvh + INNER_, 2*INNER_, path, S_, CTX_);

    gemm_h_kernel<true,true,false,false><<<g2, blk256>>>(path, pa2woT, a2_bo, px, px, M, D_, INNER_);

    // ---------------- phase 3: AdaLN + fused GEGLU FFN ----------------
    emb_kernel<<<(B_*2*D_)/256, blk256>>>(t_in, n3_w, n3_b, pemb);
    adaln_kernel<<<M, blk256>>>(px, pemb, phh);

    dim3 g3((2*DFF_)/128, M/128);
    gemm_h_kernel<true,false,true,true><<<g3, blk256>>>(phh, pffw1T, pb1i, nullptr, pgluh, M, 2*DFF_, D_);

    dim3 g4(D_/128, M/128);
    gemm_h_kernel<true,true,false,false><<<g4, blk256>>>(pgluh, pffw2T, ff_b2, px, out, M, D_, DFF_);
}

// round 8
// speedup vs baseline: 7.9676x; 1.1711x over previous
#include <cuda_runtime.h>
#include <cuda_fp16.h>
#include <math.h>
#include <cstdint>

// ---------------------------------------------------------------------------
// Problem constants
// ---------------------------------------------------------------------------
#define B_   2
#define S_   2048
#define CTX_ 256
#define D_   1024
#define H_   16
#define DH_  64
#define INNER_ 1024
#define DFF_ 4096

__device__ __forceinline__ uint32_t smem_u32(const void* p) {
    uint32_t a;
    asm("{ .reg .u64 t; cvta.to.shared.u64 t, %1; cvt.u32.u64 %0, t; }"
        : "=r"(a) : "l"(p));
    return a;
}
__device__ __forceinline__ void cp16(uint32_t dst, const void* src) {
    asm volatile("cp.async.cg.shared.global [%0], [%1], 16;" :: "r"(dst), "l"(src));
}
#define CP_COMMIT()  asm volatile("cp.async.commit_group;" ::: "memory")
#define CP_WAIT0()   asm volatile("cp.async.wait_group 0;" ::: "memory")
#define CP_WAIT1()   asm volatile("cp.async.wait_group 1;" ::: "memory")

__device__ __forceinline__ float ex2f(float x) {
    float y;
    asm("ex2.approx.f32 %0, %1;" : "=f"(y) : "f"(x));
    return y;
}
__device__ __forceinline__ uint32_t h2_u32(__half2 h) {
    union { __half2 h; uint32_t u; } c;
    c.h = h;
    return c.u;
}
__device__ __forceinline__ void mma_f16(float* c, const uint32_t* a, const uint32_t* b) {
    asm volatile(
        "mma.sync.aligned.m16n8k16.row.col.f32.f16.f16.f32 "
        "{%0,%1,%2,%3}, {%4,%5,%6,%7}, {%8,%9}, {%0,%1,%2,%3};"
        : "+f"(c[0]), "+f"(c[1]), "+f"(c[2]), "+f"(c[3])
        : "r"(a[0]), "r"(a[1]), "r"(a[2]), "r"(a[3]), "r"(b[0]), "r"(b[1]));
}
__device__ __forceinline__ void ldmx4(uint32_t* r, uint32_t addr) {
    asm volatile("ldmatrix.sync.aligned.m8n8.x4.shared.b16 {%0,%1,%2,%3}, [%4];"
        : "=r"(r[0]), "=r"(r[1]), "=r"(r[2]), "=r"(r[3]) : "r"(addr));
}
__device__ __forceinline__ void ldmx2t(uint32_t& b0, uint32_t& b1, uint32_t addr) {
    asm volatile("ldmatrix.sync.aligned.m8n8.x2.trans.shared.b16 {%0,%1}, [%2];"
        : "=r"(b0), "=r"(b1) : "r"(addr));
}

// ---------------------------------------------------------------------------
// Scratch (static device globals)
// ---------------------------------------------------------------------------
__device__ float  g_x   [B_*S_*D_];
__device__ float  g_emb [3*B_*2*D_];
__device__ float  g_b1i [2*DFF_];
__device__ __half g_hh  [B_*S_*D_];
__device__ __half g_qh  [B_*S_*INNER_];
__device__ __half g_qkvh[B_*S_*3*INNER_];
__device__ __half g_kvh [B_*CTX_*2*INNER_];
__device__ __half g_atth[B_*S_*INNER_];
__device__ __half g_gluh[B_*S_*DFF_];
__device__ __half g_ctxh[B_*CTX_*D_];
__device__ __half g_qkv1T[3*INNER_*D_];
__device__ __half g_a1woT[D_*INNER_];
__device__ __half g_a2wqT[INNER_*D_];
__device__ __half g_kv2T [2*INNER_*D_];
__device__ __half g_a2woT[D_*INNER_];
__device__ __half g_ffw1T[2*DFF_*D_];     // GLU-interleaved rows
__device__ __half g_ffw2T[D_*DFF_];

// ---------------------------------------------------------------------------
// Merged weight prep: all transposes in one launch.
// Each segment: src[R,C] f32 -> dst[C,R] half (optional GLU row interleave).
// ---------------------------------------------------------------------------
struct PrepSeg {
    const float* src;
    __half* dst;
    int R, C;       // src dims
    int glu;        // GLU interleave flag
    int tile0;      // first global tile id
};
struct PrepParams {
    PrepSeg seg[10];
    int total;
};

__global__ void __launch_bounds__(256) prep_kernel(PrepParams P) {
    __shared__ float t[32][33];
    int bid = blockIdx.x;
    // find segment
    int si = 0;
    #pragma unroll
    for (int i = 1; i < 10; i++)
        if (bid >= P.seg[i].tile0) si = i;
    const PrepSeg sg = P.seg[si];
    int local = bid - sg.tile0;
    int tilesX = sg.C >> 5;
    int bx = (local % tilesX) << 5;
    int by = (local / tilesX) << 5;

    int tx = threadIdx.x & 31, ty = threadIdx.x >> 5;
    int x = bx + tx;
    #pragma unroll
    for (int i = 0; i < 4; i++) {
        int y = by + ty + i * 8;
        t[ty + i*8][tx] = sg.src[(size_t)y * sg.C + x];
    }
    __syncthreads();
    int x2 = by + tx;
    #pragma unroll
    for (int i = 0; i < 4; i++) {
        int c = bx + ty + i * 8;
        int nr = c;
        if (sg.glu) nr = (c < DFF_) ? 2*c : 2*(c - DFF_) + 1;
        sg.dst[(size_t)nr * sg.R + x2] = __float2half_rn(t[tx][ty + i*8]);
    }
}

__global__ void cvt_h_kernel(const float* __restrict__ src, __half* __restrict__ dst) {
    int i = blockIdx.x * blockDim.x + threadIdx.x;
    dst[i] = __float2half_rn(src[i]);
}
__global__ void bias_ilv_kernel(const float* __restrict__ b, float* __restrict__ bi) {
    int j = blockIdx.x * blockDim.x + threadIdx.x;
    bi[2*j]   = b[j];
    bi[2*j+1] = b[DFF_ + j];
}

// ---------------------------------------------------------------------------
// Merged emb: all three AdaLN linears in one launch.
// emb[p][b][j] = t[b] @ Wp + bp,  p = 0..2
// ---------------------------------------------------------------------------
__global__ void emb3_kernel(const float* __restrict__ t,
                            const float* __restrict__ W0, const float* __restrict__ b0,
                            const float* __restrict__ W1, const float* __restrict__ b1,
                            const float* __restrict__ W2, const float* __restrict__ b2,
                            float* __restrict__ emb) {
    int j = blockIdx.x * blockDim.x + threadIdx.x;   // < 3*B*2D
    int p  = j / (B_*2*D_);
    int r  = j - p * (B_*2*D_);
    int b  = r / (2*D_);
    int jj = r - b * (2*D_);
    const float* W = (p == 0) ? W0 : (p == 1) ? W1 : W2;
    const float* bb = (p == 0) ? b0 : (p == 1) ? b1 : b2;
    const float* tr = t + b * D_;
    float acc = bb[jj];
    #pragma unroll 8
    for (int k = 0; k < D_; k++)
        acc += tr[k] * W[k * (2*D_) + jj];
    emb[j] = acc;
}

// ---------------------------------------------------------------------------
// AdaLN -> half output
// ---------------------------------------------------------------------------
__global__ void __launch_bounds__(256) adaln_kernel(const float* __restrict__ x,
                                                    const float* __restrict__ emb,
                                                    __half* __restrict__ out) {
    int row = blockIdx.x;
    int b   = row >> 11;
    const float* xr = x + (size_t)row * D_;
    int tid = threadIdx.x;

    float v[4];
    float s = 0.f, ss = 0.f;
    #pragma unroll
    for (int i = 0; i < 4; i++) {
        v[i] = xr[tid + i*256];
        s  += v[i];
        ss += v[i]*v[i];
    }
    #pragma unroll
    for (int off = 16; off; off >>= 1) {
        s  += __shfl_xor_sync(0xffffffffu, s,  off);
        ss += __shfl_xor_sync(0xffffffffu, ss, off);
    }
    __shared__ float rs[8], rss[8];
    __shared__ float s_mean, s_rstd;
    int w = tid >> 5, lane = tid & 31;
    if (lane == 0) { rs[w] = s; rss[w] = ss; }
    __syncthreads();
    if (tid == 0) {
        float S1 = 0.f, S2 = 0.f;
        #pragma unroll
        for (int i = 0; i < 8; i++) { S1 += rs[i]; S2 += rss[i]; }
        float mean = S1 * (1.f/D_);
        float var  = S2 * (1.f/D_) - mean*mean;
        s_mean = mean;
        s_rstd = rsqrtf(var + 1e-5f);
    }
    __syncthreads();
    float mean = s_mean, rstd = s_rstd;
    const float* eb = emb + b * (2*D_);
    __half* orow = out + (size_t)row * D_;
    #pragma unroll
    for (int i = 0; i < 4; i++) {
        int j = tid + i*256;
        orow[j] = __float2half_rn((v[i] - mean) * rstd * (1.f + eb[j]) + eb[D_ + j]);
    }
}

// ---------------------------------------------------------------------------
// fp16 mma GEMM, 3-stage cp.async pipeline, ldmatrix fragments.
// Block tile 128x128x32; 8 warps 4(M)x2(N); dynamic smem 3*(2*128*LDG2*2)B.
// ---------------------------------------------------------------------------
#define LDG2 40
#define GEMM_SMEM (3 * 2 * 128 * LDG2 * 2)   // stages * (A+B) * rows * stride * sizeof(half)

template<bool BIAS, bool RESID, bool OUTH, bool GLU>
__global__ void __launch_bounds__(256) gemm_h_kernel(
        const __half* __restrict__ A, const __half* __restrict__ Bt,
        const float* __restrict__ bias, const float* __restrict__ Rs,
        void* __restrict__ Cv, int M, int N, int K) {
    extern __shared__ __half sh[];
    // stage s: A at sh + s*2*128*LDG2, B at +128*LDG2

    const int tid  = threadIdx.x;
    const int wid  = tid >> 5, lane = tid & 31;
    const int grp  = lane >> 2, tig = lane & 3;
    const int wm   = (wid & 3) * 32;
    const int wn   = (wid >> 2) * 64;
    const int m0   = blockIdx.y * 128, n0 = blockIdx.x * 128;

    const uint32_t sm_u = smem_u32(sh);

    const int a_row = (lane & 15);
    const int a_col = (lane >> 4) << 3;
    const int b_row = ((lane >> 4) << 3) + (lane & 7);
    const int b_col = ((lane >> 3) & 1) << 3;

    float acc[2][8][4];
    #pragma unroll
    for (int i = 0; i < 2; i++)
        #pragma unroll
        for (int j = 0; j < 8; j++)
            #pragma unroll
            for (int q = 0; q < 4; q++) acc[i][j][q] = 0.f;

    const int niter = K >> 5;

    auto issue = [&](int it, int s) {
        const int k0 = it << 5;
        const uint32_t ab = sm_u + (uint32_t)(s*2*128*LDG2)*2;
        const uint32_t bb = ab + (uint32_t)(128*LDG2)*2;
        #pragma unroll
        for (int j = 0; j < 2; j++) {
            int idx = tid + j * 256;
            int r = idx >> 2, c8 = (idx & 3) << 3;
            cp16(ab + (uint32_t)(r*LDG2 + c8)*2, A  + (size_t)(m0 + r) * K + k0 + c8);
            cp16(bb + (uint32_t)(r*LDG2 + c8)*2, Bt + (size_t)(n0 + r) * K + k0 + c8);
        }
        CP_COMMIT();
    };

    issue(0, 0);
    if (niter > 1) issue(1, 1);

    int s = 0;
    for (int it = 0; it < niter; ++it) {
        if (it + 1 < niter) CP_WAIT1(); else CP_WAIT0();
        __syncthreads();
        if (it + 2 < niter) issue(it + 2, (s + 2) % 3);

        const uint32_t as_b = sm_u + (uint32_t)(s*2*128*LDG2)*2;
        const uint32_t bs_b = as_b + (uint32_t)(128*LDG2)*2;
        #pragma unroll
        for (int kk = 0; kk < 32; kk += 16) {
            uint32_t af[2][4], bf[8][2];
            #pragma unroll
            for (int mt = 0; mt < 2; mt++)
                ldmx4(af[mt], as_b + (uint32_t)((wm + mt*16 + a_row)*LDG2 + kk + a_col)*2);
            #pragma unroll
            for (int p = 0; p < 4; p++) {
                uint32_t r4[4];
                ldmx4(r4, bs_b + (uint32_t)((wn + p*16 + b_row)*LDG2 + kk + b_col)*2);
                bf[2*p  ][0] = r4[0]; bf[2*p  ][1] = r4[1];
                bf[2*p+1][0] = r4[2]; bf[2*p+1][1] = r4[3];
            }
            #pragma unroll
            for (int mt = 0; mt < 2; mt++)
                #pragma unroll
                for (int nt = 0; nt < 8; nt++)
                    mma_f16(acc[mt][nt], af[mt], bf[nt]);
        }
        __syncthreads();
        s = (s + 1) % 3;
    }

    // Epilogue
    #pragma unroll
    for (int mt = 0; mt < 2; mt++) {
        #pragma unroll
        for (int nt = 0; nt < 8; nt++) {
            int row = m0 + wm + mt*16 + grp;
            int col = n0 + wn + nt*8 + tig*2;
            float2 v01 = make_float2(acc[mt][nt][0], acc[mt][nt][1]);
            float2 v23 = make_float2(acc[mt][nt][2], acc[mt][nt][3]);
            if (BIAS) {
                float2 bv = *(const float2*)(bias + col);
                v01.x += bv.x; v01.y += bv.y;
                v23.x += bv.x; v23.y += bv.y;
            }
            if (GLU) {
                __half* Gh = (__half*)Cv;
                int j = col >> 1;
                float g0 = v01.y, g1 = v23.y;
                float ge0 = 0.5f * g0 * (1.f + erff(g0 * 0.70710678118654752f));
                float ge1 = 0.5f * g1 * (1.f + erff(g1 * 0.70710678118654752f));
                Gh[(size_t)row * DFF_ + j]       = __float2half_rn(v01.x * ge0);
                Gh[(size_t)(row + 8) * DFF_ + j] = __float2half_rn(v23.x * ge1);
            } else {
                if (RESID) {
                    float2 r0 = *(const float2*)(Rs + (size_t)row * N + col);
                    float2 r1 = *(const float2*)(Rs + (size_t)(row + 8) * N + col);
                    v01.x += r0.x; v01.y += r0.y;
                    v23.x += r1.x; v23.y += r1.y;
                }
                if (OUTH) {
                    __half* Ch = (__half*)Cv;
                    *(__half2*)(Ch + (size_t)row * N + col) = __floats2half2_rn(v01.x, v01.y);
                    *(__half2*)(Ch + (size_t)(row + 8) * N + col) = __floats2half2_rn(v23.x, v23.y);
                } else {
                    float* Cf = (float*)Cv;
                    *(float2*)(Cf + (size_t)row * N + col) = v01;
                    *(float2*)(Cf + (size_t)(row + 8) * N + col) = v23;
                }
            }
        }
    }
}

// ---------------------------------------------------------------------------
// fp16 flash attention with explicit Q/K/V row strides.
// ---------------------------------------------------------------------------
#define LDF 72

__global__ void __launch_bounds__(128) flash_h_kernel(
        const __half* __restrict__ Q, int qstr,
        const __half* __restrict__ Kg, int kstr,
        const __half* __restrict__ Vg, int vstr,
        __half* __restrict__ O,
        int Sq, int Sk) {
    __shared__ __half Qs[64*LDF];
    __shared__ __half Ks[2][64*LDF];
    __shared__ __half Vs[2][64*LDF];

    const int tid = threadIdx.x;
    const int wid = tid >> 5, lane = tid & 31;
    const int grp = lane >> 2, tig = lane & 3;
    const int h = blockIdx.y, b = blockIdx.z;
    const int q0 = blockIdx.x * 64;
    const int wq = wid * 16;
    const int vrow = lane & 15;

    const uint32_t qs_u = smem_u32(Qs);
    const uint32_t ks_u = smem_u32(Ks);
    const uint32_t vs_u = smem_u32(Vs);

    const float qscale = 0.125f * 1.4426950408889634f;

    #pragma unroll
    for (int j = 0; j < 4; j++) {
        int i = tid + j * 128;
        int r = i >> 3, c8 = (i & 7) << 3;
        cp16(qs_u + (uint32_t)(r*LDF + c8)*2,
             Q + ((size_t)(b*Sq + q0 + r))*qstr + h*DH_ + c8);
    }
    auto issue_kv = [&](int kt, int s) {
        const int kbase = kt * 64;
        #pragma unroll
        for (int j = 0; j < 4; j++) {
            int i = tid + j * 128;
            int r = i >> 3, c8 = (i & 7) << 3;
            cp16(ks_u + (uint32_t)(s*64*LDF + r*LDF + c8)*2,
                 Kg + ((size_t)(b*Sk + kbase + r))*kstr + h*DH_ + c8);
            cp16(vs_u + (uint32_t)(s*64*LDF + r*LDF + c8)*2,
                 Vg + ((size_t)(b*Sk + kbase + r))*vstr + h*DH_ + c8);
        }
        CP_COMMIT();
    };
    issue_kv(0, 0);

    float o[8][4];
    #pragma unroll
    for (int nf = 0; nf < 8; nf++)
        #pragma unroll
        for (int q = 0; q < 4; q++) o[nf][q] = 0.f;
    float m0 = -1e30f, m1 = -1e30f, l0 = 0.f, l1 = 0.f;

    const int ntiles = Sk >> 6;
    for (int kt = 0; kt < ntiles; kt++) {
        const int s = kt & 1;
        CP_WAIT0();
        __syncthreads();
        if (kt + 1 < ntiles) issue_kv(kt + 1, s ^ 1);

        const __half* ks = Ks[s];
        float sc[8][4];
        #pragma unroll
        for (int nf = 0; nf < 8; nf++)
            #pragma unroll
            for (int q = 0; q < 4; q++) sc[nf][q] = 0.f;

        #pragma unroll
        for (int kk = 0; kk < 64; kk += 16) {
            uint32_t af[4];
            af[0] = *(const uint32_t*)&Qs[(wq + grp    )*LDF + kk + 2*tig    ];
            af[1] = *(const uint32_t*)&Qs[(wq + grp + 8)*LDF + kk + 2*tig    ];
            af[2] = *(const uint32_t*)&Qs[(wq + grp    )*LDF + kk + 2*tig + 8];
            af[3] = *(const uint32_t*)&Qs[(wq + grp + 8)*LDF + kk + 2*tig + 8];
            #pragma unroll
            for (int nf = 0; nf < 8; nf++) {
                uint32_t bf[2];
                bf[0] = *(const uint32_t*)&ks[(nf*8 + grp)*LDF + kk + 2*tig    ];
                bf[1] = *(const uint32_t*)&ks[(nf*8 + grp)*LDF + kk + 2*tig + 8];
                mma_f16(sc[nf], af, bf);
            }
        }

        float r0 = -1e30f, r1 = -1e30f;
        #pragma unroll
        for (int nf = 0; nf < 8; nf++) {
            r0 = fmaxf(r0, fmaxf(sc[nf][0], sc[nf][1]));
            r1 = fmaxf(r1, fmaxf(sc[nf][2], sc[nf][3]));
        }
        r0 = fmaxf(r0, __shfl_xor_sync(0xffffffffu, r0, 1));
        r0 = fmaxf(r0, __shfl_xor_sync(0xffffffffu, r0, 2));
        r1 = fmaxf(r1, __shfl_xor_sync(0xffffffffu, r1, 1));
        r1 = fmaxf(r1, __shfl_xor_sync(0xffffffffu, r1, 2));

        float mn0 = fmaxf(m0, r0 * qscale), mn1 = fmaxf(m1, r1 * qscale);
        float corr0 = ex2f(m0 - mn0), corr1 = ex2f(m1 - mn1);
        m0 = mn0; m1 = mn1;

        float rs0 = 0.f, rs1 = 0.f;
        uint32_t ph[8][2];
        #pragma unroll
        for (int nf = 0; nf < 8; nf++) {
            float p0 = ex2f(fmaf(sc[nf][0], qscale, -mn0));
            float p1 = ex2f(fmaf(sc[nf][1], qscale, -mn0));
            float p2 = ex2f(fmaf(sc[nf][2], qscale, -mn1));
            float p3 = ex2f(fmaf(sc[nf][3], qscale, -mn1));
            rs0 += p0 + p1; rs1 += p2 + p3;
            ph[nf][0] = h2_u32(__floats2half2_rn(p0, p1));
            ph[nf][1] = h2_u32(__floats2half2_rn(p2, p3));
        }
        rs0 += __shfl_xor_sync(0xffffffffu, rs0, 1);
        rs0 += __shfl_xor_sync(0xffffffffu, rs0, 2);
        rs1 += __shfl_xor_sync(0xffffffffu, rs1, 1);
        rs1 += __shfl_xor_sync(0xffffffffu, rs1, 2);
        l0 = l0 * corr0 + rs0;
        l1 = l1 * corr1 + rs1;

        #pragma unroll
        for (int nf = 0; nf < 8; nf++) {
            o[nf][0] *= corr0; o[nf][1] *= corr0;
            o[nf][2] *= corr1; o[nf][3] *= corr1;
        }

        const uint32_t vb = vs_u + (uint32_t)(s*64*LDF)*2;
        #pragma unroll
        for (int kk = 0; kk < 64; kk += 16) {
            const int nf2 = kk >> 3;
            uint32_t af[4] = { ph[nf2][0], ph[nf2][1], ph[nf2+1][0], ph[nf2+1][1] };
            #pragma unroll
            for (int nf = 0; nf < 8; nf++) {
                uint32_t b0, b1;
                ldmx2t(b0, b1, vb + (uint32_t)((kk + vrow)*LDF + nf*8)*2);
                uint32_t bf[2] = { b0, b1 };
                mma_f16(o[nf], af, bf);
            }
        }
    }

    float inv0 = 1.f / l0, inv1 = 1.f / l1;
    const size_t row0 = (size_t)(b*Sq + q0 + wq + grp);
    __half* op0 = O + row0 * INNER_ + h*DH_;
    __half* op1 = O + (row0 + 8) * INNER_ + h*DH_;
    #pragma unroll
    for (int nf = 0; nf < 8; nf++) {
        int col = nf*8 + 2*tig;
        *(__half2*)(op0 + col) = __floats2half2_rn(o[nf][0]*inv0, o[nf][1]*inv0);
        *(__half2*)(op1 + col) = __floats2half2_rn(o[nf][2]*inv1, o[nf][3]*inv1);
    }
}

// ---------------------------------------------------------------------------
// Launch
// ---------------------------------------------------------------------------
template<typename T>
static T* sym_addr_t(const void* s) {
    void* p = nullptr;
    cudaGetSymbolAddress(&p, s);
    return (T*)p;
}

extern "C" void kernel_launch(void* const* d_in, const int* in_sizes, int n_in,
                              void* d_out, int out_size) {
    const float* x_in   = (const float*)d_in[0];
    const float* t_in   = (const float*)d_in[1];
    const float* ctx_in = (const float*)d_in[2];
    const float* a1_wq = (const float*)d_in[3];
    const float* a1_wk = (const float*)d_in[4];
    const float* a1_wv = (const float*)d_in[5];
    const float* a1_wo = (const float*)d_in[6];
    const float* a1_bo = (const float*)d_in[7];
    const float* a2_wq = (const float*)d_in[8];
    const float* a2_wk = (const float*)d_in[9];
    const float* a2_wv = (const float*)d_in[10];
    const float* a2_wo = (const float*)d_in[11];
    const float* a2_bo = (const float*)d_in[12];
    const float* ff_w1 = (const float*)d_in[13];
    const float* ff_b1 = (const float*)d_in[14];
    const float* ff_w2 = (const float*)d_in[15];
    const float* ff_b2 = (const float*)d_in[16];
    const float* n1_w  = (const float*)d_in[17];
    const float* n1_b  = (const float*)d_in[18];
    const float* n2_w  = (const float*)d_in[19];
    const float* n2_b  = (const float*)d_in[20];
    const float* n3_w  = (const float*)d_in[21];
    const float* n3_b  = (const float*)d_in[22];
    float* out = (float*)d_out;

    float*  px    = sym_addr_t<float>(g_x);
    float*  pemb  = sym_addr_t<float>(g_emb);
    float*  pb1i  = sym_addr_t<float>(g_b1i);
    __half* phh   = sym_addr_t<__half>(g_hh);
    __half* pqh   = sym_addr_t<__half>(g_qh);
    __half* pqkvh = sym_addr_t<__half>(g_qkvh);
    __half* pkvh  = sym_addr_t<__half>(g_kvh);
    __half* path  = sym_addr_t<__half>(g_atth);
    __half* pgluh = sym_addr_t<__half>(g_gluh);
    __half* pctxh = sym_addr_t<__half>(g_ctxh);

    __half* pqkv1T = sym_addr_t<__half>(g_qkv1T);
    __half* pa1woT = sym_addr_t<__half>(g_a1woT);
    __half* pa2wqT = sym_addr_t<__half>(g_a2wqT);
    __half* pkv2T  = sym_addr_t<__half>(g_kv2T);
    __half* pa2woT = sym_addr_t<__half>(g_a2woT);
    __half* pffw1T = sym_addr_t<__half>(g_ffw1T);
    __half* pffw2T = sym_addr_t<__half>(g_ffw2T);

    // set dynamic smem limits (idempotent)
    cudaFuncSetAttribute(gemm_h_kernel<false,false,true,false>,
                         cudaFuncAttributeMaxDynamicSharedMemorySize, GEMM_SMEM);
    cudaFuncSetAttribute(gemm_h_kernel<true,true,false,false>,
                         cudaFuncAttributeMaxDynamicSharedMemorySize, GEMM_SMEM);
    cudaFuncSetAttribute(gemm_h_kernel<true,false,true,true>,
                         cudaFuncAttributeMaxDynamicSharedMemorySize, GEMM_SMEM);

    const int M  = B_ * S_;      // 4096
    const int Mc = B_ * CTX_;    // 512
    dim3 blk256(256);
    dim3 blk128(128);

    // ---- merged weight prep ----
    PrepParams P;
    int t0 = 0;
    auto addseg = [&](int i, const float* src, __half* dst, int R, int C, int glu) {
        P.seg[i] = {src, dst, R, C, glu, t0};
        t0 += (C >> 5) * (R >> 5);
    };
    addseg(0, a1_wq, pqkv1T,                      D_, INNER_, 0);
    addseg(1, a1_wk, pqkv1T + (size_t)INNER_*D_,  D_, INNER_, 0);
    addseg(2, a1_wv, pqkv1T + (size_t)2*INNER_*D_,D_, INNER_, 0);
    addseg(3, a1_wo, pa1woT, INNER_, D_, 0);
    addseg(4, a2_wq, pa2wqT, D_, INNER_, 0);
    addseg(5, a2_wk, pkv2T,  D_, INNER_, 0);
    addseg(6, a2_wv, pkv2T + (size_t)INNER_*D_, D_, INNER_, 0);
    addseg(7, a2_wo, pa2woT, INNER_, D_, 0);
    addseg(8, ff_w1, pffw1T, D_, 2*DFF_, 1);
    addseg(9, ff_w2, pffw2T, DFF_, D_, 0);
    P.total = t0;
    prep_kernel<<<t0, blk256>>>(P);
    cvt_h_kernel<<<(B_*CTX_*D_)/256, blk256>>>(ctx_in, pctxh);
    bias_ilv_kernel<<<DFF_/256, blk256>>>(ff_b1, pb1i);

    emb3_kernel<<<(3*B_*2*D_)/256, blk256>>>(t_in, n1_w, n1_b, n2_w, n2_b, n3_w, n3_b, pemb);

    // ---------------- phase 1: AdaLN + self-attention ----------------
    adaln_kernel<<<M, blk256>>>(x_in, pemb, phh);

    dim3 gqkv((3*INNER_)/128, M/128);
    gemm_h_kernel<false,false,true,false><<<gqkv, blk256, GEMM_SMEM>>>(phh, pqkv1T, nullptr, nullptr, pqkvh, M, 3*INNER_, D_);

    dim3 gf1(S_/64, H_, B_);
    flash_h_kernel<<<gf1, blk128>>>(pqkvh, 3*INNER_, pqkvh + INNER_, 3*INNER_,
                                    pqkvh + 2*INNER_, 3*INNER_, path, S_, S_);

    dim3 g2(D_/128, M/128);
    gemm_h_kernel<true,true,false,false><<<g2, blk256, GEMM_SMEM>>>(path, pa1woT, a1_bo, x_in, px, M, D_, INNER_);

    // ---------------- phase 2: AdaLN + cross-attention ----------------
    adaln_kernel<<<M, blk256>>>(px, pemb + B_*2*D_, phh);

    dim3 g1(INNER_/128, M/128);
    gemm_h_kernel<false,false,true,false><<<g1, blk256, GEMM_SMEM>>>(phh, pa2wqT, nullptr, nullptr, pqh, M, INNER_, D_);
    dim3 gkv((2*INNER_)/128, Mc/128);
    gemm_h_kernel<false,false,true,false><<<gkv, blk256, GEMM_SMEM>>>(pctxh, pkv2T, nullptr, nullptr, pkvh, Mc, 2*INNER_, D_);

    flash_h_kernel<<<gf1, blk128>>>(pqh, INNER_, pkvh, 2*INNER_,
                                    pkvh + INNER_, 2*INNER_, path, S_, CTX_);

    gemm_h_kernel<true,true,false,false><<<g2, blk256, GEMM_SMEM>>>(path, pa2woT, a2_bo, px, px, M, D_, INNER_);

    // ---------------- phase 3: AdaLN + fused GEGLU FFN ----------------
    adaln_kernel<<<M, blk256>>>(px, pemb + 2*B_*2*D_, phh);

    dim3 g3((2*DFF_)/128, M/128);
    gemm_h_kernel<true,false,true,true><<<g3, blk256, GEMM_SMEM>>>(phh, pffw1T, pb1i, nullptr, pgluh, M, 2*DFF_, D_);

    dim3 g4(D_/128, M/128);
    gemm_h_kernel<true,true,false,false><<<g4, blk256, GEMM_SMEM>>>(pgluh, pffw2T, ff_b2, px, out, M, D_, DFF_);
}

// round 9
// speedup vs baseline: 8.5822x; 1.0771x over previous
#include <cuda_runtime.h>
#include <cuda_fp16.h>
#include <math.h>
#include <cstdint>

// ---------------------------------------------------------------------------
// Problem constants
// ---------------------------------------------------------------------------
#define B_   2
#define S_   2048
#define CTX_ 256
#define D_   1024
#define H_   16
#define DH_  64
#define INNER_ 1024
#define DFF_ 4096
#define EMB_N   (3*B_*2*D_)    // 12288
#define EMB_KS  8

__device__ __forceinline__ uint32_t smem_u32(const void* p) {
    uint32_t a;
    asm("{ .reg .u64 t; cvta.to.shared.u64 t, %1; cvt.u32.u64 %0, t; }"
        : "=r"(a) : "l"(p));
    return a;
}
__device__ __forceinline__ void cp16(uint32_t dst, const void* src) {
    asm volatile("cp.async.cg.shared.global [%0], [%1], 16;" :: "r"(dst), "l"(src));
}
#define CP_COMMIT()  asm volatile("cp.async.commit_group;" ::: "memory")
#define CP_WAIT0()   asm volatile("cp.async.wait_group 0;" ::: "memory")
#define CP_WAIT1()   asm volatile("cp.async.wait_group 1;" ::: "memory")

__device__ __forceinline__ float ex2f(float x) {
    float y;
    asm("ex2.approx.f32 %0, %1;" : "=f"(y) : "f"(x));
    return y;
}
__device__ __forceinline__ uint32_t h2_u32(__half2 h) {
    union { __half2 h; uint32_t u; } c;
    c.h = h;
    return c.u;
}
__device__ __forceinline__ void mma_f16(float* c, const uint32_t* a, const uint32_t* b) {
    asm volatile(
        "mma.sync.aligned.m16n8k16.row.col.f32.f16.f16.f32 "
        "{%0,%1,%2,%3}, {%4,%5,%6,%7}, {%8,%9}, {%0,%1,%2,%3};"
        : "+f"(c[0]), "+f"(c[1]), "+f"(c[2]), "+f"(c[3])
        : "r"(a[0]), "r"(a[1]), "r"(a[2]), "r"(a[3]), "r"(b[0]), "r"(b[1]));
}
__device__ __forceinline__ void ldmx4(uint32_t* r, uint32_t addr) {
    asm volatile("ldmatrix.sync.aligned.m8n8.x4.shared.b16 {%0,%1,%2,%3}, [%4];"
        : "=r"(r[0]), "=r"(r[1]), "=r"(r[2]), "=r"(r[3]) : "r"(addr));
}
__device__ __forceinline__ void ldmx2t(uint32_t& b0, uint32_t& b1, uint32_t addr) {
    asm volatile("ldmatrix.sync.aligned.m8n8.x2.trans.shared.b16 {%0,%1}, [%2];"
        : "=r"(b0), "=r"(b1) : "r"(addr));
}

// ---------------------------------------------------------------------------
// Scratch (static device globals)
// ---------------------------------------------------------------------------
__device__ float  g_x   [B_*S_*D_];
__device__ float  g_emb [EMB_N];
__device__ float  g_embp[EMB_KS*EMB_N];
__device__ float  g_b1i [2*DFF_];
__device__ __half g_hh  [B_*S_*D_];
__device__ __half g_qh  [B_*S_*INNER_];
__device__ __half g_qkvh[B_*S_*3*INNER_];
__device__ __half g_kvh [B_*CTX_*2*INNER_];
__device__ __half g_atth[B_*S_*INNER_];
__device__ __half g_gluh[B_*S_*DFF_];
__device__ __half g_ctxh[B_*CTX_*D_];
__device__ __half g_qkv1T[3*INNER_*D_];
__device__ __half g_a1woT[D_*INNER_];
__device__ __half g_a2wqT[INNER_*D_];
__device__ __half g_kv2T [2*INNER_*D_];
__device__ __half g_a2woT[D_*INNER_];
__device__ __half g_ffw1T[2*DFF_*D_];     // GLU-interleaved rows
__device__ __half g_ffw2T[D_*DFF_];

// ---------------------------------------------------------------------------
// Merged weight prep: all transposes in one launch.
// ---------------------------------------------------------------------------
struct PrepSeg {
    const float* src;
    __half* dst;
    int R, C;
    int glu;
    int tile0;
};
struct PrepParams {
    PrepSeg seg[10];
    int total;
};

__global__ void __launch_bounds__(256) prep_kernel(PrepParams P) {
    __shared__ float t[32][33];
    int bid = blockIdx.x;
    int si = 0;
    #pragma unroll
    for (int i = 1; i < 10; i++)
        if (bid >= P.seg[i].tile0) si = i;
    const PrepSeg sg = P.seg[si];
    int local = bid - sg.tile0;
    int tilesX = sg.C >> 5;
    int bx = (local % tilesX) << 5;
    int by = (local / tilesX) << 5;

    int tx = threadIdx.x & 31, ty = threadIdx.x >> 5;
    int x = bx + tx;
    #pragma unroll
    for (int i = 0; i < 4; i++) {
        int y = by + ty + i * 8;
        t[ty + i*8][tx] = sg.src[(size_t)y * sg.C + x];
    }
    __syncthreads();
    int x2 = by + tx;
    #pragma unroll
    for (int i = 0; i < 4; i++) {
        int c = bx + ty + i * 8;
        int nr = c;
        if (sg.glu) nr = (c < DFF_) ? 2*c : 2*(c - DFF_) + 1;
        sg.dst[(size_t)nr * sg.R + x2] = __float2half_rn(t[tx][ty + i*8]);
    }
}

__global__ void cvt_h_kernel(const float* __restrict__ src, __half* __restrict__ dst) {
    int i = blockIdx.x * blockDim.x + threadIdx.x;
    dst[i] = __float2half_rn(src[i]);
}
__global__ void bias_ilv_kernel(const float* __restrict__ b, float* __restrict__ bi) {
    int j = blockIdx.x * blockDim.x + threadIdx.x;
    bi[2*j]   = b[j];
    bi[2*j+1] = b[DFF_ + j];
}

// ---------------------------------------------------------------------------
// Split-K AdaLN embedding.
// Stage 1: partial dot over K=128 slice -> g_embp[ks][j]
// Stage 2: deterministic reduce + bias -> g_emb[j]
// ---------------------------------------------------------------------------
__global__ void emb_sk_kernel(const float* __restrict__ t,
                              const float* __restrict__ W0,
                              const float* __restrict__ W1,
                              const float* __restrict__ W2,
                              float* __restrict__ embp) {
    int j  = blockIdx.x * blockDim.x + threadIdx.x;   // < EMB_N
    int ks = blockIdx.y;
    int p  = j / (B_*2*D_);
    int r  = j - p * (B_*2*D_);
    int b  = r / (2*D_);
    int jj = r - b * (2*D_);
    const float* W = (p == 0) ? W0 : (p == 1) ? W1 : W2;
    const float* tr = t + b * D_ + ks * (D_/EMB_KS);
    const float* Wp = W + (size_t)(ks * (D_/EMB_KS)) * (2*D_) + jj;
    float acc = 0.f;
    #pragma unroll 8
    for (int k = 0; k < D_/EMB_KS; k++)
        acc += tr[k] * Wp[(size_t)k * (2*D_)];
    embp[(size_t)ks * EMB_N + j] = acc;
}

__global__ void emb_red_kernel(const float* __restrict__ embp,
                               const float* __restrict__ b0,
                               const float* __restrict__ b1,
                               const float* __restrict__ b2,
                               float* __restrict__ emb) {
    int j = blockIdx.x * blockDim.x + threadIdx.x;
    int p  = j / (B_*2*D_);
    int r  = j - p * (B_*2*D_);
    int jj = r % (2*D_);
    const float* bb = (p == 0) ? b0 : (p == 1) ? b1 : b2;
    float acc = bb[jj];
    #pragma unroll
    for (int ks = 0; ks < EMB_KS; ks++)
        acc += embp[(size_t)ks * EMB_N + j];
    emb[j] = acc;
}

// ---------------------------------------------------------------------------
// AdaLN -> half output
// ---------------------------------------------------------------------------
__global__ void __launch_bounds__(256) adaln_kernel(const float* __restrict__ x,
                                                    const float* __restrict__ emb,
                                                    __half* __restrict__ out) {
    int row = blockIdx.x;
    int b   = row >> 11;
    const float* xr = x + (size_t)row * D_;
    int tid = threadIdx.x;

    float v[4];
    float s = 0.f, ss = 0.f;
    #pragma unroll
    for (int i = 0; i < 4; i++) {
        v[i] = xr[tid + i*256];
        s  += v[i];
        ss += v[i]*v[i];
    }
    #pragma unroll
    for (int off = 16; off; off >>= 1) {
        s  += __shfl_xor_sync(0xffffffffu, s,  off);
        ss += __shfl_xor_sync(0xffffffffu, ss, off);
    }
    __shared__ float rs[8], rss[8];
    __shared__ float s_mean, s_rstd;
    int w = tid >> 5, lane = tid & 31;
    if (lane == 0) { rs[w] = s; rss[w] = ss; }
    __syncthreads();
    if (tid == 0) {
        float S1 = 0.f, S2 = 0.f;
        #pragma unroll
        for (int i = 0; i < 8; i++) { S1 += rs[i]; S2 += rss[i]; }
        float mean = S1 * (1.f/D_);
        float var  = S2 * (1.f/D_) - mean*mean;
        s_mean = mean;
        s_rstd = rsqrtf(var + 1e-5f);
    }
    __syncthreads();
    float mean = s_mean, rstd = s_rstd;
    const float* eb = emb + b * (2*D_);
    __half* orow = out + (size_t)row * D_;
    #pragma unroll
    for (int i = 0; i < 4; i++) {
        int j = tid + i*256;
        orow[j] = __float2half_rn((v[i] - mean) * rstd * (1.f + eb[j]) + eb[D_ + j]);
    }
}

// ---------------------------------------------------------------------------
// fp16 mma GEMM, 3-stage cp.async pipeline, ldmatrix fragments.
// ---------------------------------------------------------------------------
#define LDG2 40
#define GEMM_SMEM (3 * 2 * 128 * LDG2 * 2)

template<bool BIAS, bool RESID, bool OUTH, bool GLU>
__global__ void __launch_bounds__(256) gemm_h_kernel(
        const __half* __restrict__ A, const __half* __restrict__ Bt,
        const float* __restrict__ bias, const float* __restrict__ Rs,
        void* __restrict__ Cv, int M, int N, int K) {
    extern __shared__ __half sh[];

    const int tid  = threadIdx.x;
    const int wid  = tid >> 5, lane = tid & 31;
    const int grp  = lane >> 2, tig = lane & 3;
    const int wm   = (wid & 3) * 32;
    const int wn   = (wid >> 2) * 64;
    const int m0   = blockIdx.y * 128, n0 = blockIdx.x * 128;

    const uint32_t sm_u = smem_u32(sh);

    const int a_row = (lane & 15);
    const int a_col = (lane >> 4) << 3;
    const int b_row = ((lane >> 4) << 3) + (lane & 7);
    const int b_col = ((lane >> 3) & 1) << 3;

    float acc[2][8][4];
    #pragma unroll
    for (int i = 0; i < 2; i++)
        #pragma unroll
        for (int j = 0; j < 8; j++)
            #pragma unroll
            for (int q = 0; q < 4; q++) acc[i][j][q] = 0.f;

    const int niter = K >> 5;

    auto issue = [&](int it, int s) {
        const int k0 = it << 5;
        const uint32_t ab = sm_u + (uint32_t)(s*2*128*LDG2)*2;
        const uint32_t bb = ab + (uint32_t)(128*LDG2)*2;
        #pragma unroll
        for (int j = 0; j < 2; j++) {
            int idx = tid + j * 256;
            int r = idx >> 2, c8 = (idx & 3) << 3;
            cp16(ab + (uint32_t)(r*LDG2 + c8)*2, A  + (size_t)(m0 + r) * K + k0 + c8);
            cp16(bb + (uint32_t)(r*LDG2 + c8)*2, Bt + (size_t)(n0 + r) * K + k0 + c8);
        }
        CP_COMMIT();
    };

    issue(0, 0);
    if (niter > 1) issue(1, 1);

    int s = 0;
    for (int it = 0; it < niter; ++it) {
        if (it + 1 < niter) CP_WAIT1(); else CP_WAIT0();
        __syncthreads();
        if (it + 2 < niter) issue(it + 2, (s + 2) % 3);

        const uint32_t as_b = sm_u + (uint32_t)(s*2*128*LDG2)*2;
        const uint32_t bs_b = as_b + (uint32_t)(128*LDG2)*2;
        #pragma unroll
        for (int kk = 0; kk < 32; kk += 16) {
            uint32_t af[2][4], bf[8][2];
            #pragma unroll
            for (int mt = 0; mt < 2; mt++)
                ldmx4(af[mt], as_b + (uint32_t)((wm + mt*16 + a_row)*LDG2 + kk + a_col)*2);
            #pragma unroll
            for (int p = 0; p < 4; p++) {
                uint32_t r4[4];
                ldmx4(r4, bs_b + (uint32_t)((wn + p*16 + b_row)*LDG2 + kk + b_col)*2);
                bf[2*p  ][0] = r4[0]; bf[2*p  ][1] = r4[1];
                bf[2*p+1][0] = r4[2]; bf[2*p+1][1] = r4[3];
            }
            #pragma unroll
            for (int mt = 0; mt < 2; mt++)
                #pragma unroll
                for (int nt = 0; nt < 8; nt++)
                    mma_f16(acc[mt][nt], af[mt], bf[nt]);
        }
        __syncthreads();
        s = (s + 1) % 3;
    }

    // Epilogue
    #pragma unroll
    for (int mt = 0; mt < 2; mt++) {
        #pragma unroll
        for (int nt = 0; nt < 8; nt++) {
            int row = m0 + wm + mt*16 + grp;
            int col = n0 + wn + nt*8 + tig*2;
            float2 v01 = make_float2(acc[mt][nt][0], acc[mt][nt][1]);
            float2 v23 = make_float2(acc[mt][nt][2], acc[mt][nt][3]);
            if (BIAS) {
                float2 bv = *(const float2*)(bias + col);
                v01.x += bv.x; v01.y += bv.y;
                v23.x += bv.x; v23.y += bv.y;
            }
            if (GLU) {
                __half* Gh = (__half*)Cv;
                int j = col >> 1;
                float g0 = v01.y, g1 = v23.y;
                float ge0 = 0.5f * g0 * (1.f + erff(g0 * 0.70710678118654752f));
                float ge1 = 0.5f * g1 * (1.f + erff(g1 * 0.70710678118654752f));
                Gh[(size_t)row * DFF_ + j]       = __float2half_rn(v01.x * ge0);
                Gh[(size_t)(row + 8) * DFF_ + j] = __float2half_rn(v23.x * ge1);
            } else {
                if (RESID) {
                    float2 r0 = *(const float2*)(Rs + (size_t)row * N + col);
                    float2 r1 = *(const float2*)(Rs + (size_t)(row + 8) * N + col);
                    v01.x += r0.x; v01.y += r0.y;
                    v23.x += r1.x; v23.y += r1.y;
                }
                if (OUTH) {
                    __half* Ch = (__half*)Cv;
                    *(__half2*)(Ch + (size_t)row * N + col) = __floats2half2_rn(v01.x, v01.y);
                    *(__half2*)(Ch + (size_t)(row + 8) * N + col) = __floats2half2_rn(v23.x, v23.y);
                } else {
                    float* Cf = (float*)Cv;
                    *(float2*)(Cf + (size_t)row * N + col) = v01;
                    *(float2*)(Cf + (size_t)(row + 8) * N + col) = v23;
                }
            }
        }
    }
}

// ---------------------------------------------------------------------------
// fp16 flash attention with explicit Q/K/V row strides.
// ---------------------------------------------------------------------------
#define LDF 72

__global__ void __launch_bounds__(128) flash_h_kernel(
        const __half* __restrict__ Q, int qstr,
        const __half* __restrict__ Kg, int kstr,
        const __half* __restrict__ Vg, int vstr,
        __half* __restrict__ O,
        int Sq, int Sk) {
    __shared__ __half Qs[64*LDF];
    __shared__ __half Ks[2][64*LDF];
    __shared__ __half Vs[2][64*LDF];

    const int tid = threadIdx.x;
    const int wid = tid >> 5, lane = tid & 31;
    const int grp = lane >> 2, tig = lane & 3;
    const int h = blockIdx.y, b = blockIdx.z;
    const int q0 = blockIdx.x * 64;
    const int wq = wid * 16;
    const int vrow = lane & 15;

    const uint32_t qs_u = smem_u32(Qs);
    const uint32_t ks_u = smem_u32(Ks);
    const uint32_t vs_u = smem_u32(Vs);

    const float qscale = 0.125f * 1.4426950408889634f;

    #pragma unroll
    for (int j = 0; j < 4; j++) {
        int i = tid + j * 128;
        int r = i >> 3, c8 = (i & 7) << 3;
        cp16(qs_u + (uint32_t)(r*LDF + c8)*2,
             Q + ((size_t)(b*Sq + q0 + r))*qstr + h*DH_ + c8);
    }
    auto issue_kv = [&](int kt, int s) {
        const int kbase = kt * 64;
        #pragma unroll
        for (int j = 0; j < 4; j++) {
            int i = tid + j * 128;
            int r = i >> 3, c8 = (i & 7) << 3;
            cp16(ks_u + (uint32_t)(s*64*LDF + r*LDF + c8)*2,
                 Kg + ((size_t)(b*Sk + kbase + r))*kstr + h*DH_ + c8);
            cp16(vs_u + (uint32_t)(s*64*LDF + r*LDF + c8)*2,
                 Vg + ((size_t)(b*Sk + kbase + r))*vstr + h*DH_ + c8);
        }
        CP_COMMIT();
    };
    issue_kv(0, 0);

    float o[8][4];
    #pragma unroll
    for (int nf = 0; nf < 8; nf++)
        #pragma unroll
        for (int q = 0; q < 4; q++) o[nf][q] = 0.f;
    float m0 = -1e30f, m1 = -1e30f, l0 = 0.f, l1 = 0.f;

    const int ntiles = Sk >> 6;
    for (int kt = 0; kt < ntiles; kt++) {
        const int s = kt & 1;
        CP_WAIT0();
        __syncthreads();
        if (kt + 1 < ntiles) issue_kv(kt + 1, s ^ 1);

        const __half* ks = Ks[s];
        float sc[8][4];
        #pragma unroll
        for (int nf = 0; nf < 8; nf++)
            #pragma unroll
            for (int q = 0; q < 4; q++) sc[nf][q] = 0.f;

        #pragma unroll
        for (int kk = 0; kk < 64; kk += 16) {
            uint32_t af[4];
            af[0] = *(const uint32_t*)&Qs[(wq + grp    )*LDF + kk + 2*tig    ];
            af[1] = *(const uint32_t*)&Qs[(wq + grp + 8)*LDF + kk + 2*tig    ];
            af[2] = *(const uint32_t*)&Qs[(wq + grp    )*LDF + kk + 2*tig + 8];
            af[3] = *(const uint32_t*)&Qs[(wq + grp + 8)*LDF + kk + 2*tig + 8];
            #pragma unroll
            for (int nf = 0; nf < 8; nf++) {
                uint32_t bf[2];
                bf[0] = *(const uint32_t*)&ks[(nf*8 + grp)*LDF + kk + 2*tig    ];
                bf[1] = *(const uint32_t*)&ks[(nf*8 + grp)*LDF + kk + 2*tig + 8];
                mma_f16(sc[nf], af, bf);
            }
        }

        float r0 = -1e30f, r1 = -1e30f;
        #pragma unroll
        for (int nf = 0; nf < 8; nf++) {
            r0 = fmaxf(r0, fmaxf(sc[nf][0], sc[nf][1]));
            r1 = fmaxf(r1, fmaxf(sc[nf][2], sc[nf][3]));
        }
        r0 = fmaxf(r0, __shfl_xor_sync(0xffffffffu, r0, 1));
        r0 = fmaxf(r0, __shfl_xor_sync(0xffffffffu, r0, 2));
        r1 = fmaxf(r1, __shfl_xor_sync(0xffffffffu, r1, 1));
        r1 = fmaxf(r1, __shfl_xor_sync(0xffffffffu, r1, 2));

        float mn0 = fmaxf(m0, r0 * qscale), mn1 = fmaxf(m1, r1 * qscale);
        float corr0 = ex2f(m0 - mn0), corr1 = ex2f(m1 - mn1);
        m0 = mn0; m1 = mn1;

        float rs0 = 0.f, rs1 = 0.f;
        uint32_t ph[8][2];
        #pragma unroll
        for (int nf = 0; nf < 8; nf++) {
            float p0 = ex2f(fmaf(sc[nf][0], qscale, -mn0));
            float p1 = ex2f(fmaf(sc[nf][1], qscale, -mn0));
            float p2 = ex2f(fmaf(sc[nf][2], qscale, -mn1));
            float p3 = ex2f(fmaf(sc[nf][3], qscale, -mn1));
            rs0 += p0 + p1; rs1 += p2 + p3;
            ph[nf][0] = h2_u32(__floats2half2_rn(p0, p1));
            ph[nf][1] = h2_u32(__floats2half2_rn(p2, p3));
        }
        rs0 += __shfl_xor_sync(0xffffffffu, rs0, 1);
        rs0 += __shfl_xor_sync(0xffffffffu, rs0, 2);
        rs1 += __shfl_xor_sync(0xffffffffu, rs1, 1);
        rs1 += __shfl_xor_sync(0xffffffffu, rs1, 2);
        l0 = l0 * corr0 + rs0;
        l1 = l1 * corr1 + rs1;

        #pragma unroll
        for (int nf = 0; nf < 8; nf++) {
            o[nf][0] *= corr0; o[nf][1] *= corr0;
            o[nf][2] *= corr1; o[nf][3] *= corr1;
        }

        const uint32_t vb = vs_u + (uint32_t)(s*64*LDF)*2;
        #pragma unroll
        for (int kk = 0; kk < 64; kk += 16) {
            const int nf2 = kk >> 3;
            uint32_t af[4] = { ph[nf2][0], ph[nf2][1], ph[nf2+1][0], ph[nf2+1][1] };
            #pragma unroll
            for (int nf = 0; nf < 8; nf++) {
                uint32_t b0, b1;
                ldmx2t(b0, b1, vb + (uint32_t)((kk + vrow)*LDF + nf*8)*2);
                uint32_t bf[2] = { b0, b1 };
                mma_f16(o[nf], af, bf);
            }
        }
    }

    float inv0 = 1.f / l0, inv1 = 1.f / l1;
    const size_t row0 = (size_t)(b*Sq + q0 + wq + grp);
    __half* op0 = O + row0 * INNER_ + h*DH_;
    __half* op1 = O + (row0 + 8) * INNER_ + h*DH_;
    #pragma unroll
    for (int nf = 0; nf < 8; nf++) {
        int col = nf*8 + 2*tig;
        *(__half2*)(op0 + col) = __floats2half2_rn(o[nf][0]*inv0, o[nf][1]*inv0);
        *(__half2*)(op1 + col) = __floats2half2_rn(o[nf][2]*inv1, o[nf][3]*inv1);
    }
}

// ---------------------------------------------------------------------------
// Launch
// ---------------------------------------------------------------------------
template<typename T>
static T* sym_addr_t(const void* s) {
    void* p = nullptr;
    cudaGetSymbolAddress(&p, s);
    return (T*)p;
}

extern "C" void kernel_launch(void* const* d_in, const int* in_sizes, int n_in,
                              void* d_out, int out_size) {
    const float* x_in   = (const float*)d_in[0];
    const float* t_in   = (const float*)d_in[1];
    const float* ctx_in = (const float*)d_in[2];
    const float* a1_wq = (const float*)d_in[3];
    const float* a1_wk = (const float*)d_in[4];
    const float* a1_wv = (const float*)d_in[5];
    const float* a1_wo = (const float*)d_in[6];
    const float* a1_bo = (const float*)d_in[7];
    const float* a2_wq = (const float*)d_in[8];
    const float* a2_wk = (const float*)d_in[9];
    const float* a2_wv = (const float*)d_in[10];
    const float* a2_wo = (const float*)d_in[11];
    const float* a2_bo = (const float*)d_in[12];
    const float* ff_w1 = (const float*)d_in[13];
    const float* ff_b1 = (const float*)d_in[14];
    const float* ff_w2 = (const float*)d_in[15];
    const float* ff_b2 = (const float*)d_in[16];
    const float* n1_w  = (const float*)d_in[17];
    const float* n1_b  = (const float*)d_in[18];
    const float* n2_w  = (const float*)d_in[19];
    const float* n2_b  = (const float*)d_in[20];
    const float* n3_w  = (const float*)d_in[21];
    const float* n3_b  = (const float*)d_in[22];
    float* out = (float*)d_out;

    float*  px    = sym_addr_t<float>(g_x);
    float*  pemb  = sym_addr_t<float>(g_emb);
    float*  pembp = sym_addr_t<float>(g_embp);
    float*  pb1i  = sym_addr_t<float>(g_b1i);
    __half* phh   = sym_addr_t<__half>(g_hh);
    __half* pqh   = sym_addr_t<__half>(g_qh);
    __half* pqkvh = sym_addr_t<__half>(g_qkvh);
    __half* pkvh  = sym_addr_t<__half>(g_kvh);
    __half* path  = sym_addr_t<__half>(g_atth);
    __half* pgluh = sym_addr_t<__half>(g_gluh);
    __half* pctxh = sym_addr_t<__half>(g_ctxh);

    __half* pqkv1T = sym_addr_t<__half>(g_qkv1T);
    __half* pa1woT = sym_addr_t<__half>(g_a1woT);
    __half* pa2wqT = sym_addr_t<__half>(g_a2wqT);
    __half* pkv2T  = sym_addr_t<__half>(g_kv2T);
    __half* pa2woT = sym_addr_t<__half>(g_a2woT);
    __half* pffw1T = sym_addr_t<__half>(g_ffw1T);
    __half* pffw2T = sym_addr_t<__half>(g_ffw2T);

    cudaFuncSetAttribute(gemm_h_kernel<false,false,true,false>,
                         cudaFuncAttributeMaxDynamicSharedMemorySize, GEMM_SMEM);
    cudaFuncSetAttribute(gemm_h_kernel<true,true,false,false>,
                         cudaFuncAttributeMaxDynamicSharedMemorySize, GEMM_SMEM);
    cudaFuncSetAttribute(gemm_h_kernel<true,false,true,true>,
                         cudaFuncAttributeMaxDynamicSharedMemorySize, GEMM_SMEM);

    const int M  = B_ * S_;      // 4096
    const int Mc = B_ * CTX_;    // 512
    dim3 blk256(256);
    dim3 blk128(128);

    // ---- split-K embeddings ----
    dim3 gemb(EMB_N/256, EMB_KS);
    emb_sk_kernel<<<gemb, blk256>>>(t_in, n1_w, n2_w, n3_w, pembp);
    emb_red_kernel<<<EMB_N/256, blk256>>>(pembp, n1_b, n2_b, n3_b, pemb);

    // ---- merged weight prep ----
    PrepParams P;
    int t0 = 0;
    auto addseg = [&](int i, const float* src, __half* dst, int R, int C, int glu) {
        P.seg[i] = {src, dst, R, C, glu, t0};
        t0 += (C >> 5) * (R >> 5);
    };
    addseg(0, a1_wq, pqkv1T,                      D_, INNER_, 0);
    addseg(1, a1_wk, pqkv1T + (size_t)INNER_*D_,  D_, INNER_, 0);
    addseg(2, a1_wv, pqkv1T + (size_t)2*INNER_*D_,D_, INNER_, 0);
    addseg(3, a1_wo, pa1woT, INNER_, D_, 0);
    addseg(4, a2_wq, pa2wqT, D_, INNER_, 0);
    addseg(5, a2_wk, pkv2T,  D_, INNER_, 0);
    addseg(6, a2_wv, pkv2T + (size_t)INNER_*D_, D_, INNER_, 0);
    addseg(7, a2_wo, pa2woT, INNER_, D_, 0);
    addseg(8, ff_w1, pffw1T, D_, 2*DFF_, 1);
    addseg(9, ff_w2, pffw2T, DFF_, D_, 0);
    P.total = t0;
    prep_kernel<<<t0, blk256>>>(P);
    cvt_h_kernel<<<(B_*CTX_*D_)/256, blk256>>>(ctx_in, pctxh);
    bias_ilv_kernel<<<DFF_/256, blk256>>>(ff_b1, pb1i);

    // ---------------- phase 1: AdaLN + self-attention ----------------
    adaln_kernel<<<M, blk256>>>(x_in, pemb, phh);

    dim3 gqkv((3*INNER_)/128, M/128);
    gemm_h_kernel<false,false,true,false><<<gqkv, blk256, GEMM_SMEM>>>(phh, pqkv1T, nullptr, nullptr, pqkvh, M, 3*INNER_, D_);

    dim3 gf1(S_/64, H_, B_);
    flash_h_kernel<<<gf1, blk128>>>(pqkvh, 3*INNER_, pqkvh + INNER_, 3*INNER_,
                                    pqkvh + 2*INNER_, 3*INNER_, path, S_, S_);

    dim3 g2(D_/128, M/128);
    gemm_h_kernel<true,true,false,false><<<g2, blk256, GEMM_SMEM>>>(path, pa1woT, a1_bo, x_in, px, M, D_, INNER_);

    // ---------------- phase 2: AdaLN + cross-attention ----------------
    adaln_kernel<<<M, blk256>>>(px, pemb + B_*2*D_, phh);

    dim3 g1(INNER_/128, M/128);
    gemm_h_kernel<false,false,true,false><<<g1, blk256, GEMM_SMEM>>>(phh, pa2wqT, nullptr, nullptr, pqh, M, INNER_, D_);
    dim3 gkv((2*INNER_)/128, Mc/128);
    gemm_h_kernel<false,false,true,false><<<gkv, blk256, GEMM_SMEM>>>(pctxh, pkv2T, nullptr, nullptr, pkvh, Mc, 2*INNER_, D_);

    flash_h_kernel<<<gf1, blk128>>>(pqh, INNER_, pkvh, 2*INNER_,
                                    pkvh + INNER_, 2*INNER_, path, S_, CTX_);

    gemm_h_kernel<true,true,false,false><<<g2, blk256, GEMM_SMEM>>>(path, pa2woT, a2_bo, px, px, M, D_, INNER_);

    // ---------------- phase 3: AdaLN + fused GEGLU FFN ----------------
    adaln_kernel<<<M, blk256>>>(px, pemb + 2*B_*2*D_, phh);

    dim3 g3((2*DFF_)/128, M/128);
    gemm_h_kernel<true,false,true,true><<<g3, blk256, GEMM_SMEM>>>(phh, pffw1T, pb1i, nullptr, pgluh, M, 2*DFF_, D_);

    dim3 g4(D_/128, M/128);
    gemm_h_kernel<true,true,false,false><<<g4, blk256, GEMM_SMEM>>>(pgluh, pffw2T, ff_b2, px, out, M, D_, DFF_);
}

// round 10
// speedup vs baseline: 8.8874x; 1.0356x over previous
#include <cuda_runtime.h>
#include <cuda_fp16.h>
#include <math.h>
#include <cstdint>

// ---------------------------------------------------------------------------
// Problem constants
// ---------------------------------------------------------------------------
#define B_   2
#define S_   2048
#define CTX_ 256
#define D_   1024
#define H_   16
#define DH_  64
#define INNER_ 1024
#define DFF_ 4096
#define EMB_N   (3*B_*2*D_)    // 12288
#define EMB_KS  8

__device__ __forceinline__ uint32_t smem_u32(const void* p) {
    uint32_t a;
    asm("{ .reg .u64 t; cvta.to.shared.u64 t, %1; cvt.u32.u64 %0, t; }"
        : "=r"(a) : "l"(p));
    return a;
}
__device__ __forceinline__ void cp16(uint32_t dst, const void* src) {
    asm volatile("cp.async.cg.shared.global [%0], [%1], 16;" :: "r"(dst), "l"(src));
}
#define CP_COMMIT()  asm volatile("cp.async.commit_group;" ::: "memory")
#define CP_WAIT0()   asm volatile("cp.async.wait_group 0;" ::: "memory")
#define CP_WAIT1()   asm volatile("cp.async.wait_group 1;" ::: "memory")

__device__ __forceinline__ float ex2f(float x) {
    float y;
    asm("ex2.approx.f32 %0, %1;" : "=f"(y) : "f"(x));
    return y;
}
__device__ __forceinline__ uint32_t h2_u32(__half2 h) {
    union { __half2 h; uint32_t u; } c;
    c.h = h;
    return c.u;
}
__device__ __forceinline__ void mma_f16(float* c, const uint32_t* a, const uint32_t* b) {
    asm volatile(
        "mma.sync.aligned.m16n8k16.row.col.f32.f16.f16.f32 "
        "{%0,%1,%2,%3}, {%4,%5,%6,%7}, {%8,%9}, {%0,%1,%2,%3};"
        : "+f"(c[0]), "+f"(c[1]), "+f"(c[2]), "+f"(c[3])
        : "r"(a[0]), "r"(a[1]), "r"(a[2]), "r"(a[3]), "r"(b[0]), "r"(b[1]));
}
__device__ __forceinline__ void ldmx4(uint32_t* r, uint32_t addr) {
    asm volatile("ldmatrix.sync.aligned.m8n8.x4.shared.b16 {%0,%1,%2,%3}, [%4];"
        : "=r"(r[0]), "=r"(r[1]), "=r"(r[2]), "=r"(r[3]) : "r"(addr));
}
__device__ __forceinline__ void ldmx2t(uint32_t& b0, uint32_t& b1, uint32_t addr) {
    asm volatile("ldmatrix.sync.aligned.m8n8.x2.trans.shared.b16 {%0,%1}, [%2];"
        : "=r"(b0), "=r"(b1) : "r"(addr));
}

// ---------------------------------------------------------------------------
// Scratch (static device globals)
// ---------------------------------------------------------------------------
__device__ float  g_x   [B_*S_*D_];
__device__ float  g_emb [EMB_N];
__device__ float  g_embp[EMB_KS*EMB_N];
__device__ float  g_b1i [2*DFF_];
__device__ __half g_hh  [B_*S_*D_];
__device__ __half g_qh  [B_*S_*INNER_];
__device__ __half g_qkvh[B_*S_*3*INNER_];
__device__ __half g_kvh [B_*CTX_*2*INNER_];
__device__ __half g_atth[B_*S_*INNER_];
__device__ __half g_gluh[B_*S_*DFF_];
__device__ __half g_ctxh[B_*CTX_*D_];
__device__ __half g_qkv1T[3*INNER_*D_];
__device__ __half g_a1woT[D_*INNER_];
__device__ __half g_a2wqT[INNER_*D_];
__device__ __half g_kv2T [2*INNER_*D_];
__device__ __half g_a2woT[D_*INNER_];
__device__ __half g_ffw1T[2*DFF_*D_];     // GLU-interleaved rows
__device__ __half g_ffw2T[D_*DFF_];

// ---------------------------------------------------------------------------
// Merged weight prep: all transposes in one launch.
// ---------------------------------------------------------------------------
struct PrepSeg {
    const float* src;
    __half* dst;
    int R, C;
    int glu;
    int tile0;
};
struct PrepParams {
    PrepSeg seg[10];
    int total;
};

__global__ void __launch_bounds__(256) prep_kernel(PrepParams P) {
    __shared__ float t[32][33];
    int bid = blockIdx.x;
    int si = 0;
    #pragma unroll
    for (int i = 1; i < 10; i++)
        if (bid >= P.seg[i].tile0) si = i;
    const PrepSeg sg = P.seg[si];
    int local = bid - sg.tile0;
    int tilesX = sg.C >> 5;
    int bx = (local % tilesX) << 5;
    int by = (local / tilesX) << 5;

    int tx = threadIdx.x & 31, ty = threadIdx.x >> 5;
    int x = bx + tx;
    #pragma unroll
    for (int i = 0; i < 4; i++) {
        int y = by + ty + i * 8;
        t[ty + i*8][tx] = sg.src[(size_t)y * sg.C + x];
    }
    __syncthreads();
    int x2 = by + tx;
    #pragma unroll
    for (int i = 0; i < 4; i++) {
        int c = bx + ty + i * 8;
        int nr = c;
        if (sg.glu) nr = (c < DFF_) ? 2*c : 2*(c - DFF_) + 1;
        sg.dst[(size_t)nr * sg.R + x2] = __float2half_rn(t[tx][ty + i*8]);
    }
}

__global__ void cvt_h_kernel(const float* __restrict__ src, __half* __restrict__ dst) {
    int i = blockIdx.x * blockDim.x + threadIdx.x;
    dst[i] = __float2half_rn(src[i]);
}
__global__ void bias_ilv_kernel(const float* __restrict__ b, float* __restrict__ bi) {
    int j = blockIdx.x * blockDim.x + threadIdx.x;
    bi[2*j]   = b[j];
    bi[2*j+1] = b[DFF_ + j];
}

// ---------------------------------------------------------------------------
// Split-K AdaLN embedding.
// ---------------------------------------------------------------------------
__global__ void emb_sk_kernel(const float* __restrict__ t,
                              const float* __restrict__ W0,
                              const float* __restrict__ W1,
                              const float* __restrict__ W2,
                              float* __restrict__ embp) {
    int j  = blockIdx.x * blockDim.x + threadIdx.x;   // < EMB_N
    int ks = blockIdx.y;
    int p  = j / (B_*2*D_);
    int r  = j - p * (B_*2*D_);
    int b  = r / (2*D_);
    int jj = r - b * (2*D_);
    const float* W = (p == 0) ? W0 : (p == 1) ? W1 : W2;
    const float* tr = t + b * D_ + ks * (D_/EMB_KS);
    const float* Wp = W + (size_t)(ks * (D_/EMB_KS)) * (2*D_) + jj;
    float acc = 0.f;
    #pragma unroll 8
    for (int k = 0; k < D_/EMB_KS; k++)
        acc += tr[k] * Wp[(size_t)k * (2*D_)];
    embp[(size_t)ks * EMB_N + j] = acc;
}

__global__ void emb_red_kernel(const float* __restrict__ embp,
                               const float* __restrict__ b0,
                               const float* __restrict__ b1,
                               const float* __restrict__ b2,
                               float* __restrict__ emb) {
    int j = blockIdx.x * blockDim.x + threadIdx.x;
    int p  = j / (B_*2*D_);
    int r  = j - p * (B_*2*D_);
    int jj = r % (2*D_);
    const float* bb = (p == 0) ? b0 : (p == 1) ? b1 : b2;
    float acc = bb[jj];
    #pragma unroll
    for (int ks = 0; ks < EMB_KS; ks++)
        acc += embp[(size_t)ks * EMB_N + j];
    emb[j] = acc;
}

// ---------------------------------------------------------------------------
// AdaLN -> half. Warp-per-row (8 rows per 256-thread block, no block syncs).
// ---------------------------------------------------------------------------
__global__ void __launch_bounds__(256) adaln_kernel(const float* __restrict__ x,
                                                    const float* __restrict__ emb,
                                                    __half* __restrict__ out) {
    const int w = threadIdx.x >> 5, lane = threadIdx.x & 31;
    const int row = blockIdx.x * 8 + w;
    const int b   = row >> 11;
    const float* xr = x + (size_t)row * D_;

    float4 v[8];
    float s = 0.f, ss = 0.f;
    #pragma unroll
    for (int i = 0; i < 8; i++) {
        v[i] = *(const float4*)(xr + (i*32 + lane)*4);
        s  += v[i].x + v[i].y + v[i].z + v[i].w;
        ss += v[i].x*v[i].x + v[i].y*v[i].y + v[i].z*v[i].z + v[i].w*v[i].w;
    }
    #pragma unroll
    for (int off = 16; off; off >>= 1) {
        s  += __shfl_xor_sync(0xffffffffu, s,  off);
        ss += __shfl_xor_sync(0xffffffffu, ss, off);
    }
    float mean = s * (1.f/D_);
    float var  = ss * (1.f/D_) - mean*mean;
    float rstd = rsqrtf(var + 1e-5f);

    const float* eb = emb + b * (2*D_);
    __half* orow = out + (size_t)row * D_;
    #pragma unroll
    for (int i = 0; i < 8; i++) {
        int j = (i*32 + lane)*4;
        float4 sc = *(const float4*)(eb + j);
        float4 sh = *(const float4*)(eb + D_ + j);
        float a0 = (v[i].x - mean) * rstd * (1.f + sc.x) + sh.x;
        float a1 = (v[i].y - mean) * rstd * (1.f + sc.y) + sh.y;
        float a2 = (v[i].z - mean) * rstd * (1.f + sc.z) + sh.z;
        float a3 = (v[i].w - mean) * rstd * (1.f + sc.w) + sh.w;
        uint2 pk;
        pk.x = h2_u32(__floats2half2_rn(a0, a1));
        pk.y = h2_u32(__floats2half2_rn(a2, a3));
        *(uint2*)(orow + j) = pk;
    }
}

// ---------------------------------------------------------------------------
// fp16 mma GEMM, 3-stage cp.async pipeline, ldmatrix fragments.
// ---------------------------------------------------------------------------
#define LDG2 40
#define GEMM_SMEM (3 * 2 * 128 * LDG2 * 2)

template<bool BIAS, bool RESID, bool OUTH, bool GLU>
__global__ void __launch_bounds__(256) gemm_h_kernel(
        const __half* __restrict__ A, const __half* __restrict__ Bt,
        const float* __restrict__ bias, const float* __restrict__ Rs,
        void* __restrict__ Cv, int M, int N, int K) {
    extern __shared__ __half sh[];

    const int tid  = threadIdx.x;
    const int wid  = tid >> 5, lane = tid & 31;
    const int grp  = lane >> 2, tig = lane & 3;
    const int wm   = (wid & 3) * 32;
    const int wn   = (wid >> 2) * 64;
    const int m0   = blockIdx.y * 128, n0 = blockIdx.x * 128;

    const uint32_t sm_u = smem_u32(sh);

    const int a_row = (lane & 15);
    const int a_col = (lane >> 4) << 3;
    const int b_row = ((lane >> 4) << 3) + (lane & 7);
    const int b_col = ((lane >> 3) & 1) << 3;

    float acc[2][8][4];
    #pragma unroll
    for (int i = 0; i < 2; i++)
        #pragma unroll
        for (int j = 0; j < 8; j++)
            #pragma unroll
            for (int q = 0; q < 4; q++) acc[i][j][q] = 0.f;

    const int niter = K >> 5;

    auto issue = [&](int it, int s) {
        const int k0 = it << 5;
        const uint32_t ab = sm_u + (uint32_t)(s*2*128*LDG2)*2;
        const uint32_t bb = ab + (uint32_t)(128*LDG2)*2;
        #pragma unroll
        for (int j = 0; j < 2; j++) {
            int idx = tid + j * 256;
            int r = idx >> 2, c8 = (idx & 3) << 3;
            cp16(ab + (uint32_t)(r*LDG2 + c8)*2, A  + (size_t)(m0 + r) * K + k0 + c8);
            cp16(bb + (uint32_t)(r*LDG2 + c8)*2, Bt + (size_t)(n0 + r) * K + k0 + c8);
        }
        CP_COMMIT();
    };

    issue(0, 0);
    if (niter > 1) issue(1, 1);

    int s = 0;
    for (int it = 0; it < niter; ++it) {
        if (it + 1 < niter) CP_WAIT1(); else CP_WAIT0();
        __syncthreads();
        if (it + 2 < niter) issue(it + 2, (s + 2) % 3);

        const uint32_t as_b = sm_u + (uint32_t)(s*2*128*LDG2)*2;
        const uint32_t bs_b = as_b + (uint32_t)(128*LDG2)*2;
        #pragma unroll
        for (int kk = 0; kk < 32; kk += 16) {
            uint32_t af[2][4], bf[8][2];
            #pragma unroll
            for (int mt = 0; mt < 2; mt++)
                ldmx4(af[mt], as_b + (uint32_t)((wm + mt*16 + a_row)*LDG2 + kk + a_col)*2);
            #pragma unroll
            for (int p = 0; p < 4; p++) {
                uint32_t r4[4];
                ldmx4(r4, bs_b + (uint32_t)((wn + p*16 + b_row)*LDG2 + kk + b_col)*2);
                bf[2*p  ][0] = r4[0]; bf[2*p  ][1] = r4[1];
                bf[2*p+1][0] = r4[2]; bf[2*p+1][1] = r4[3];
            }
            #pragma unroll
            for (int mt = 0; mt < 2; mt++)
                #pragma unroll
                for (int nt = 0; nt < 8; nt++)
                    mma_f16(acc[mt][nt], af[mt], bf[nt]);
        }
        __syncthreads();
        s = (s + 1) % 3;
    }

    // Epilogue
    #pragma unroll
    for (int mt = 0; mt < 2; mt++) {
        #pragma unroll
        for (int nt = 0; nt < 8; nt++) {
            int row = m0 + wm + mt*16 + grp;
            int col = n0 + wn + nt*8 + tig*2;
            float2 v01 = make_float2(acc[mt][nt][0], acc[mt][nt][1]);
            float2 v23 = make_float2(acc[mt][nt][2], acc[mt][nt][3]);
            if (BIAS) {
                float2 bv = *(const float2*)(bias + col);
                v01.x += bv.x; v01.y += bv.y;
                v23.x += bv.x; v23.y += bv.y;
            }
            if (GLU) {
                __half* Gh = (__half*)Cv;
                int j = col >> 1;
                float g0 = v01.y, g1 = v23.y;
                float ge0 = 0.5f * g0 * (1.f + erff(g0 * 0.70710678118654752f));
                float ge1 = 0.5f * g1 * (1.f + erff(g1 * 0.70710678118654752f));
                Gh[(size_t)row * DFF_ + j]       = __float2half_rn(v01.x * ge0);
                Gh[(size_t)(row + 8) * DFF_ + j] = __float2half_rn(v23.x * ge1);
            } else {
                if (RESID) {
                    float2 r0 = *(const float2*)(Rs + (size_t)row * N + col);
                    float2 r1 = *(const float2*)(Rs + (size_t)(row + 8) * N + col);
                    v01.x += r0.x; v01.y += r0.y;
                    v23.x += r1.x; v23.y += r1.y;
                }
                if (OUTH) {
                    __half* Ch = (__half*)Cv;
                    *(__half2*)(Ch + (size_t)row * N + col) = __floats2half2_rn(v01.x, v01.y);
                    *(__half2*)(Ch + (size_t)(row + 8) * N + col) = __floats2half2_rn(v23.x, v23.y);
                } else {
                    float* Cf = (float*)Cv;
                    *(float2*)(Cf + (size_t)row * N + col) = v01;
                    *(float2*)(Cf + (size_t)(row + 8) * N + col) = v23;
                }
            }
        }
    }
}

// ---------------------------------------------------------------------------
// fp16 flash attention with explicit Q/K/V row strides.
// ---------------------------------------------------------------------------
#define LDF 72

__global__ void __launch_bounds__(128) flash_h_kernel(
        const __half* __restrict__ Q, int qstr,
        const __half* __restrict__ Kg, int kstr,
        const __half* __restrict__ Vg, int vstr,
        __half* __restrict__ O,
        int Sq, int Sk) {
    __shared__ __half Qs[64*LDF];
    __shared__ __half Ks[2][64*LDF];
    __shared__ __half Vs[2][64*LDF];

    const int tid = threadIdx.x;
    const int wid = tid >> 5, lane = tid & 31;
    const int grp = lane >> 2, tig = lane & 3;
    const int h = blockIdx.y, b = blockIdx.z;
    const int q0 = blockIdx.x * 64;
    const int wq = wid * 16;
    const int vrow = lane & 15;

    const uint32_t qs_u = smem_u32(Qs);
    const uint32_t ks_u = smem_u32(Ks);
    const uint32_t vs_u = smem_u32(Vs);

    const float qscale = 0.125f * 1.4426950408889634f;

    #pragma unroll
    for (int j = 0; j < 4; j++) {
        int i = tid + j * 128;
        int r = i >> 3, c8 = (i & 7) << 3;
        cp16(qs_u + (uint32_t)(r*LDF + c8)*2,
             Q + ((size_t)(b*Sq + q0 + r))*qstr + h*DH_ + c8);
    }
    auto issue_kv = [&](int kt, int s) {
        const int kbase = kt * 64;
        #pragma unroll
        for (int j = 0; j < 4; j++) {
            int i = tid + j * 128;
            int r = i >> 3, c8 = (i & 7) << 3;
            cp16(ks_u + (uint32_t)(s*64*LDF + r*LDF + c8)*2,
                 Kg + ((size_t)(b*Sk + kbase + r))*kstr + h*DH_ + c8);
            cp16(vs_u + (uint32_t)(s*64*LDF + r*LDF + c8)*2,
                 Vg + ((size_t)(b*Sk + kbase + r))*vstr + h*DH_ + c8);
        }
        CP_COMMIT();
    };
    issue_kv(0, 0);

    float o[8][4];
    #pragma unroll
    for (int nf = 0; nf < 8; nf++)
        #pragma unroll
        for (int q = 0; q < 4; q++) o[nf][q] = 0.f;
    float m0 = -1e30f, m1 = -1e30f, l0 = 0.f, l1 = 0.f;

    const int ntiles = Sk >> 6;
    for (int kt = 0; kt < ntiles; kt++) {
        const int s = kt & 1;
        CP_WAIT0();
        __syncthreads();
        if (kt + 1 < ntiles) issue_kv(kt + 1, s ^ 1);

        const __half* ks = Ks[s];
        float sc[8][4];
        #pragma unroll
        for (int nf = 0; nf < 8; nf++)
            #pragma unroll
            for (int q = 0; q < 4; q++) sc[nf][q] = 0.f;

        #pragma unroll
        for (int kk = 0; kk < 64; kk += 16) {
            uint32_t af[4];
            af[0] = *(const uint32_t*)&Qs[(wq + grp    )*LDF + kk + 2*tig    ];
            af[1] = *(const uint32_t*)&Qs[(wq + grp + 8)*LDF + kk + 2*tig    ];
            af[2] = *(const uint32_t*)&Qs[(wq + grp    )*LDF + kk + 2*tig + 8];
            af[3] = *(const uint32_t*)&Qs[(wq + grp + 8)*LDF + kk + 2*tig + 8];
            #pragma unroll
            for (int nf = 0; nf < 8; nf++) {
                uint32_t bf[2];
                bf[0] = *(const uint32_t*)&ks[(nf*8 + grp)*LDF + kk + 2*tig    ];
                bf[1] = *(const uint32_t*)&ks[(nf*8 + grp)*LDF + kk + 2*tig + 8];
                mma_f16(sc[nf], af, bf);
            }
        }

        float r0 = -1e30f, r1 = -1e30f;
        #pragma unroll
        for (int nf = 0; nf < 8; nf++) {
            r0 = fmaxf(r0, fmaxf(sc[nf][0], sc[nf][1]));
            r1 = fmaxf(r1, fmaxf(sc[nf][2], sc[nf][3]));
        }
        r0 = fmaxf(r0, __shfl_xor_sync(0xffffffffu, r0, 1));
        r0 = fmaxf(r0, __shfl_xor_sync(0xffffffffu, r0, 2));
        r1 = fmaxf(r1, __shfl_xor_sync(0xffffffffu, r1, 1));
        r1 = fmaxf(r1, __shfl_xor_sync(0xffffffffu, r1, 2));

        float mn0 = fmaxf(m0, r0 * qscale), mn1 = fmaxf(m1, r1 * qscale);
        float corr0 = ex2f(m0 - mn0), corr1 = ex2f(m1 - mn1);
        m0 = mn0; m1 = mn1;

        float rs0 = 0.f, rs1 = 0.f;
        uint32_t ph[8][2];
        #pragma unroll
        for (int nf = 0; nf < 8; nf++) {
            float p0 = ex2f(fmaf(sc[nf][0], qscale, -mn0));
            float p1 = ex2f(fmaf(sc[nf][1], qscale, -mn0));
            float p2 = ex2f(fmaf(sc[nf][2], qscale, -mn1));
            float p3 = ex2f(fmaf(sc[nf][3], qscale, -mn1));
            rs0 += p0 + p1; rs1 += p2 + p3;
            ph[nf][0] = h2_u32(__floats2half2_rn(p0, p1));
            ph[nf][1] = h2_u32(__floats2half2_rn(p2, p3));
        }
        rs0 += __shfl_xor_sync(0xffffffffu, rs0, 1);
        rs0 += __shfl_xor_sync(0xffffffffu, rs0, 2);
        rs1 += __shfl_xor_sync(0xffffffffu, rs1, 1);
        rs1 += __shfl_xor_sync(0xffffffffu, rs1, 2);
        l0 = l0 * corr0 + rs0;
        l1 = l1 * corr1 + rs1;

        #pragma unroll
        for (int nf = 0; nf < 8; nf++) {
            o[nf][0] *= corr0; o[nf][1] *= corr0;
            o[nf][2] *= corr1; o[nf][3] *= corr1;
        }

        const uint32_t vb = vs_u + (uint32_t)(s*64*LDF)*2;
        #pragma unroll
        for (int kk = 0; kk < 64; kk += 16) {
            const int nf2 = kk >> 3;
            uint32_t af[4] = { ph[nf2][0], ph[nf2][1], ph[nf2+1][0], ph[nf2+1][1] };
            #pragma unroll
            for (int nf = 0; nf < 8; nf++) {
                uint32_t b0, b1;
                ldmx2t(b0, b1, vb + (uint32_t)((kk + vrow)*LDF + nf*8)*2);
                uint32_t bf[2] = { b0, b1 };
                mma_f16(o[nf], af, bf);
            }
        }
    }

    float inv0 = 1.f / l0, inv1 = 1.f / l1;
    const size_t row0 = (size_t)(b*Sq + q0 + wq + grp);
    __half* op0 = O + row0 * INNER_ + h*DH_;
    __half* op1 = O + (row0 + 8) * INNER_ + h*DH_;
    #pragma unroll
    for (int nf = 0; nf < 8; nf++) {
        int col = nf*8 + 2*tig;
        *(__half2*)(op0 + col) = __floats2half2_rn(o[nf][0]*inv0, o[nf][1]*inv0);
        *(__half2*)(op1 + col) = __floats2half2_rn(o[nf][2]*inv1, o[nf][3]*inv1);
    }
}

// ---------------------------------------------------------------------------
// Launch
// ---------------------------------------------------------------------------
template<typename T>
static T* sym_addr_t(const void* s) {
    void* p = nullptr;
    cudaGetSymbolAddress(&p, s);
    return (T*)p;
}

extern "C" void kernel_launch(void* const* d_in, const int* in_sizes, int n_in,
                              void* d_out, int out_size) {
    const float* x_in   = (const float*)d_in[0];
    const float* t_in   = (const float*)d_in[1];
    const float* ctx_in = (const float*)d_in[2];
    const float* a1_wq = (const float*)d_in[3];
    const float* a1_wk = (const float*)d_in[4];
    const float* a1_wv = (const float*)d_in[5];
    const float* a1_wo = (const float*)d_in[6];
    const float* a1_bo = (const float*)d_in[7];
    const float* a2_wq = (const float*)d_in[8];
    const float* a2_wk = (const float*)d_in[9];
    const float* a2_wv = (const float*)d_in[10];
    const float* a2_wo = (const float*)d_in[11];
    const float* a2_bo = (const float*)d_in[12];
    const float* ff_w1 = (const float*)d_in[13];
    const float* ff_b1 = (const float*)d_in[14];
    const float* ff_w2 = (const float*)d_in[15];
    const float* ff_b2 = (const float*)d_in[16];
    const float* n1_w  = (const float*)d_in[17];
    const float* n1_b  = (const float*)d_in[18];
    const float* n2_w  = (const float*)d_in[19];
    const float* n2_b  = (const float*)d_in[20];
    const float* n3_w  = (const float*)d_in[21];
    const float* n3_b  = (const float*)d_in[22];
    float* out = (float*)d_out;

    float*  px    = sym_addr_t<float>(g_x);
    float*  pemb  = sym_addr_t<float>(g_emb);
    float*  pembp = sym_addr_t<float>(g_embp);
    float*  pb1i  = sym_addr_t<float>(g_b1i);
    __half* phh   = sym_addr_t<__half>(g_hh);
    __half* pqh   = sym_addr_t<__half>(g_qh);
    __half* pqkvh = sym_addr_t<__half>(g_qkvh);
    __half* pkvh  = sym_addr_t<__half>(g_kvh);
    __half* path  = sym_addr_t<__half>(g_atth);
    __half* pgluh = sym_addr_t<__half>(g_gluh);
    __half* pctxh = sym_addr_t<__half>(g_ctxh);

    __half* pqkv1T = sym_addr_t<__half>(g_qkv1T);
    __half* pa1woT = sym_addr_t<__half>(g_a1woT);
    __half* pa2wqT = sym_addr_t<__half>(g_a2wqT);
    __half* pkv2T  = sym_addr_t<__half>(g_kv2T);
    __half* pa2woT = sym_addr_t<__half>(g_a2woT);
    __half* pffw1T = sym_addr_t<__half>(g_ffw1T);
    __half* pffw2T = sym_addr_t<__half>(g_ffw2T);

    cudaFuncSetAttribute(gemm_h_kernel<false,false,true,false>,
                         cudaFuncAttributeMaxDynamicSharedMemorySize, GEMM_SMEM);
    cudaFuncSetAttribute(gemm_h_kernel<true,true,false,false>,
                         cudaFuncAttributeMaxDynamicSharedMemorySize, GEMM_SMEM);
    cudaFuncSetAttribute(gemm_h_kernel<true,false,true,true>,
                         cudaFuncAttributeMaxDynamicSharedMemorySize, GEMM_SMEM);

    // side stream + events (created on first, uncaptured, correctness call)
    static cudaStream_t s1 = nullptr;
    static cudaEvent_t evFork = nullptr, evPrep = nullptr, evKv = nullptr;
    if (!s1) {
        cudaStreamCreateWithFlags(&s1, cudaStreamNonBlocking);
        cudaEventCreateWithFlags(&evFork, cudaEventDisableTiming);
        cudaEventCreateWithFlags(&evPrep, cudaEventDisableTiming);
        cudaEventCreateWithFlags(&evKv,   cudaEventDisableTiming);
    }

    const int M  = B_ * S_;      // 4096
    const int Mc = B_ * CTX_;    // 512
    dim3 blk256(256);
    dim3 blk128(128);

    // ---- fork side stream ----
    cudaEventRecord(evFork, 0);
    cudaStreamWaitEvent(s1, evFork, 0);

    // side stream: weight prep + ctx convert + bias interleave + cross K/V GEMM
    PrepParams P;
    int t0 = 0;
    auto addseg = [&](int i, const float* src, __half* dst, int R, int C, int glu) {
        P.seg[i] = {src, dst, R, C, glu, t0};
        t0 += (C >> 5) * (R >> 5);
    };
    addseg(0, a1_wq, pqkv1T,                      D_, INNER_, 0);
    addseg(1, a1_wk, pqkv1T + (size_t)INNER_*D_,  D_, INNER_, 0);
    addseg(2, a1_wv, pqkv1T + (size_t)2*INNER_*D_,D_, INNER_, 0);
    addseg(3, a1_wo, pa1woT, INNER_, D_, 0);
    addseg(4, a2_wq, pa2wqT, D_, INNER_, 0);
    addseg(5, a2_wk, pkv2T,  D_, INNER_, 0);
    addseg(6, a2_wv, pkv2T + (size_t)INNER_*D_, D_, INNER_, 0);
    addseg(7, a2_wo, pa2woT, INNER_, D_, 0);
    addseg(8, ff_w1, pffw1T, D_, 2*DFF_, 1);
    addseg(9, ff_w2, pffw2T, DFF_, D_, 0);
    P.total = t0;
    prep_kernel<<<t0, blk256, 0, s1>>>(P);
    cvt_h_kernel<<<(B_*CTX_*D_)/256, blk256, 0, s1>>>(ctx_in, pctxh);
    bias_ilv_kernel<<<DFF_/256, blk256, 0, s1>>>(ff_b1, pb1i);
    cudaEventRecord(evPrep, s1);
    // cross-attn K/V projection (depends only on prep + cvt)
    dim3 gkv((2*INNER_)/128, Mc/128);
    gemm_h_kernel<false,false,true,false><<<gkv, blk256, GEMM_SMEM, s1>>>(
        pctxh, pkv2T, nullptr, nullptr, pkvh, Mc, 2*INNER_, D_);
    cudaEventRecord(evKv, s1);

    // main stream: embeddings + adaln1 (independent of prep)
    dim3 gemb(EMB_N/256, EMB_KS);
    emb_sk_kernel<<<gemb, blk256>>>(t_in, n1_w, n2_w, n3_w, pembp);
    emb_red_kernel<<<EMB_N/256, blk256>>>(pembp, n1_b, n2_b, n3_b, pemb);

    // ---------------- phase 1: AdaLN + self-attention ----------------
    adaln_kernel<<<M/8, blk256>>>(x_in, pemb, phh);

    cudaStreamWaitEvent(0, evPrep, 0);
    dim3 gqkv((3*INNER_)/128, M/128);
    gemm_h_kernel<false,false,true,false><<<gqkv, blk256, GEMM_SMEM>>>(phh, pqkv1T, nullptr, nullptr, pqkvh, M, 3*INNER_, D_);

    dim3 gf1(S_/64, H_, B_);
    flash_h_kernel<<<gf1, blk128>>>(pqkvh, 3*INNER_, pqkvh + INNER_, 3*INNER_,
                                    pqkvh + 2*INNER_, 3*INNER_, path, S_, S_);

    dim3 g2(D_/128, M/128);
    gemm_h_kernel<true,true,false,false><<<g2, blk256, GEMM_SMEM>>>(path, pa1woT, a1_bo, x_in, px, M, D_, INNER_);

    // ---------------- phase 2: AdaLN + cross-attention ----------------
    adaln_kernel<<<M/8, blk256>>>(px, pemb + B_*2*D_, phh);

    dim3 g1(INNER_/128, M/128);
    gemm_h_kernel<false,false,true,false><<<g1, blk256, GEMM_SMEM>>>(phh, pa2wqT, nullptr, nullptr, pqh, M, INNER_, D_);

    cudaStreamWaitEvent(0, evKv, 0);
    flash_h_kernel<<<gf1, blk128>>>(pqh, INNER_, pkvh, 2*INNER_,
                                    pkvh + INNER_, 2*INNER_, path, S_, CTX_);

    gemm_h_kernel<true,true,false,false><<<g2, blk256, GEMM_SMEM>>>(path, pa2woT, a2_bo, px, px, M, D_, INNER_);

    // ---------------- phase 3: AdaLN + fused GEGLU FFN ----------------
    adaln_kernel<<<M/8, blk256>>>(px, pemb + 2*B_*2*D_, phh);

    dim3 g3((2*DFF_)/128, M/128);
    gemm_h_kernel<true,false,true,true><<<g3, blk256, GEMM_SMEM>>>(phh, pffw1T, pb1i, nullptr, pgluh, M, 2*DFF_, D_);

    dim3 g4(D_/128, M/128);
    gemm_h_kernel<true,true,false,false><<<g4, blk256, GEMM_SMEM>>>(pgluh, pffw2T, ff_b2, px, out, M, D_, DFF_);
}